// round 5
// baseline (speedup 1.0000x reference)
#include <cuda_runtime.h>

#define NN 20000      // nodes
#define NE 160000     // edges
#define TE 320000     // 2E edge-rows
#define HH 128

// ---------------- scratch (static __device__, no allocs) ----------------
__device__ __align__(128) float s_ew2 [(size_t)TE * 128];   // er @ W2
__device__ __align__(128) float s_a0  [(size_t)NN * 128];   // nr @ W0
__device__ __align__(128) float s_a1  [(size_t)NN * 128];   // nr @ W1
__device__ __align__(128) float s_nacc[(size_t)NN * 128];   // node scatter accum
__device__ __align__(128) float s_nin [(size_t)NN * 128];
__device__ __align__(128) float s_np1 [(size_t)NN * 256];   // raw pre-act
__device__ __align__(128) float s_np2 [(size_t)NN * 128];   // raw pre-act
__device__ __align__(128) float s_ein [(size_t)TE * 256];
__device__ __align__(128) float s_ep1 [(size_t)TE * 256];   // raw pre-act
__device__ __align__(128) float s_ep2 [(size_t)TE * 128];   // raw pre-act
__device__ float s_sum[5 * 256];
__device__ float s_sq [5 * 256];
__device__ int   s_u[NE];
__device__ int   s_v[NE];
__device__ int   g_is64;

// ---------------- helpers ----------------
__global__ void k_zero() {
    size_t stride = (size_t)gridDim.x * blockDim.x;
    size_t i0 = (size_t)blockIdx.x * blockDim.x + threadIdx.x;
    size_t n = (size_t)NN * 128;
    for (size_t i = i0; i < n; i += stride) s_nacc[i] = 0.0f;
    if (i0 < 5 * 256) { s_sum[i0] = 0.0f; s_sq[i0] = 0.0f; }
}

__global__ void k_detect(const int* __restrict__ ei32) {
    if (threadIdx.x == 0 && blockIdx.x == 0) {
        int nz = 0;
        for (int i = 0; i < 256; i++) nz |= ei32[2 * i + 1];
        g_is64 = (nz == 0) ? 1 : 0;
    }
}

__global__ void k_decode(const void* __restrict__ ei) {
    int e = blockIdx.x * blockDim.x + threadIdx.x;
    if (e >= NE) return;
    if (g_is64) {
        const long long* p = (const long long*)ei;
        s_u[e] = (int)p[e];
        s_v[e] = (int)p[NE + e];
    } else {
        const int* p = (const int*)ei;
        s_u[e] = p[e];
        s_v[e] = p[NE + e];
    }
}

__device__ __forceinline__ unsigned f2tf(float x) {
    unsigned r;
    asm("cvt.rna.tf32.f32 %0, %1;" : "=r"(r) : "f"(x));
    return r;
}

__device__ __forceinline__ void cpasync16(void* smem_ptr, const void* gptr, int src_bytes) {
    unsigned saddr = (unsigned)__cvta_generic_to_shared(smem_ptr);
    asm volatile("cp.async.cg.shared.global [%0], [%1], 16, %2;"
                 :: "r"(saddr), "l"(gptr), "r"(src_bytes));
}
__device__ __forceinline__ void cpasync_commit() {
    asm volatile("cp.async.commit_group;");
}
template <int N>
__device__ __forceinline__ void cpasync_wait() {
    asm volatile("cp.async.wait_group %0;" :: "n"(N));
}

#define MMA_TF32(d, Af, Bf)                                                     \
    asm volatile(                                                               \
        "mma.sync.aligned.m16n8k8.row.col.f32.tf32.tf32.f32 "                   \
        "{%0,%1,%2,%3},{%4,%5,%6,%7},{%8,%9},{%0,%1,%2,%3};"                    \
        : "+f"(d[0]), "+f"(d[1]), "+f"(d[2]), "+f"(d[3])                        \
        : "r"(Af[0]), "r"(Af[1]), "r"(Af[2]), "r"(Af[3]),                       \
          "r"(Bf[0]), "r"(Bf[1]))

// ---------------- pipelined TF32 GEMM, 128x128 tile, BK=32, cp.async 3-stage ----------------
#define AS_STRIDE 36
#define BS_STRIDE 136
#define AS_TILE (128 * AS_STRIDE)
#define BS_TILE (32 * BS_STRIDE)
#define SMEM_FLOATS (3 * AS_TILE + 3 * BS_TILE + 512)
#define SMEM_BYTES (SMEM_FLOATS * 4)

// SWAP: blockIdx.x indexes N tiles (fast-varying) so both N-tiles of a row block
// run back-to-back -> A rows hit L2 on the second tile.
template <bool FUSE_BN, bool SWAP>
__global__ __launch_bounds__(256, 2) void k_mma_p(
    const float* __restrict__ A, const float* __restrict__ Bm,
    float* __restrict__ C, int M, int K, int NC,
    float* __restrict__ sumO, float* __restrict__ sqO,
    const float* __restrict__ aSum, const float* __restrict__ aSq,
    const float* __restrict__ aG, const float* __restrict__ aBt, float aInv)
{
    extern __shared__ float dsm[];
    float* AsB = dsm;
    float* BsB = dsm + 3 * AS_TILE;
    float* scS = dsm + 3 * AS_TILE + 3 * BS_TILE;
    float* shS = scS + 256;

    const int tid = threadIdx.x;
    const int lane = tid & 31, warp = tid >> 5;
    const int group = lane >> 2, qt = lane & 3;
    const int warpM = warp & 1, warpN = warp >> 1;
    const int mBase = (SWAP ? blockIdx.y : blockIdx.x) * 128;
    const int nBase = (SWAP ? blockIdx.x : blockIdx.y) * 128;
    const int nk = K >> 5;

    if (FUSE_BN) {
        if (tid < K) {
            float mean = aSum[tid] * aInv;
            float var  = aSq[tid] * aInv - mean * mean;
            float s = aG[tid] * rsqrtf(var + 1e-5f);
            scS[tid] = s; shS[tid] = aBt[tid] - mean * s;
        }
    }

    const int arow = tid >> 3, akq = (tid & 7) << 2;     // + it*32 rows
    const int bkr = tid >> 5, bnc = (tid & 31) << 2;     // + it*8 k-rows

    auto issue = [&](int i) {
        const int k0 = i << 5;
        const int b = i % 3;
        float* As = AsB + b * AS_TILE;
        float* Bs = BsB + b * BS_TILE;
#pragma unroll
        for (int it = 0; it < 4; it++) {
            int row = arow + it * 32;
            int gm = mBase + row;
            const float* src = A + (size_t)(gm < M ? gm : 0) * K + k0 + akq;
            cpasync16(As + row * AS_STRIDE + akq, src, gm < M ? 16 : 0);
        }
#pragma unroll
        for (int it = 0; it < 4; it++) {
            int kr = bkr + it * 8;
            const float* src = Bm + (size_t)(k0 + kr) * NC + nBase + bnc;
            cpasync16(Bs + kr * BS_STRIDE + bnc, src, 16);
        }
        cpasync_commit();
    };

    float acc[4][4][4];
#pragma unroll
    for (int mt = 0; mt < 4; mt++)
#pragma unroll
        for (int nt = 0; nt < 4; nt++)
#pragma unroll
            for (int i = 0; i < 4; i++) acc[mt][nt][i] = 0.0f;

    issue(0);
    if (nk > 1) issue(1);

    for (int i = 0; i < nk; i++) {
        // wait until tile i is resident (at most 1 younger group may stay pending)
        if (i + 2 <= nk) cpasync_wait<1>();
        else             cpasync_wait<0>();
        __syncthreads();
        if (i + 2 < nk) issue(i + 2);   // writes buffer (i+2)%3, last read at step i-1

        const float* As = AsB + (i % 3) * AS_TILE;
        const float* Bs = BsB + (i % 3) * BS_TILE;
        const int k0 = i << 5;
#pragma unroll
        for (int ks = 0; ks < 4; ks++) {
            const int kc = ks * 8 + qt;
            float sc0, sh0, sc1, sh1;
            if (FUSE_BN) {
                sc0 = scS[k0 + kc];     sh0 = shS[k0 + kc];
                sc1 = scS[k0 + kc + 4]; sh1 = shS[k0 + kc + 4];
            }
            unsigned af[4][4], bf[4][2];
#pragma unroll
            for (int mt = 0; mt < 4; mt++) {
                int r = warpM * 64 + mt * 16 + group;
                float a0 = As[r * AS_STRIDE + kc];
                float a1 = As[(r + 8) * AS_STRIDE + kc];
                float a2 = As[r * AS_STRIDE + kc + 4];
                float a3 = As[(r + 8) * AS_STRIDE + kc + 4];
                if (FUSE_BN) {
                    a0 = fmaxf(fmaf(a0, sc0, sh0), 0.f);
                    a1 = fmaxf(fmaf(a1, sc0, sh0), 0.f);
                    a2 = fmaxf(fmaf(a2, sc1, sh1), 0.f);
                    a3 = fmaxf(fmaf(a3, sc1, sh1), 0.f);
                }
                af[mt][0] = f2tf(a0); af[mt][1] = f2tf(a1);
                af[mt][2] = f2tf(a2); af[mt][3] = f2tf(a3);
            }
#pragma unroll
            for (int nt = 0; nt < 4; nt++) {
                int cb = warpN * 32 + nt * 8 + group;
                bf[nt][0] = f2tf(Bs[kc * BS_STRIDE + cb]);
                bf[nt][1] = f2tf(Bs[(kc + 4) * BS_STRIDE + cb]);
            }
#pragma unroll
            for (int mt = 0; mt < 4; mt++)
#pragma unroll
                for (int nt = 0; nt < 4; nt++)
                    MMA_TF32(acc[mt][nt], af[mt], bf[nt]);
        }
    }

    // epilogue: store + per-thread column partials (guard OOB rows)
    float cs[4][2], cq[4][2];
#pragma unroll
    for (int nt = 0; nt < 4; nt++) { cs[nt][0] = cs[nt][1] = 0.f; cq[nt][0] = cq[nt][1] = 0.f; }
#pragma unroll
    for (int mt = 0; mt < 4; mt++) {
        int r0 = mBase + warpM * 64 + mt * 16 + group;
        int r1 = r0 + 8;
#pragma unroll
        for (int nt = 0; nt < 4; nt++) {
            float c0 = acc[mt][nt][0], c1 = acc[mt][nt][1];
            float c2 = acc[mt][nt][2], c3 = acc[mt][nt][3];
            int cc = nBase + warpN * 32 + nt * 8 + 2 * qt;
            if (r0 < M) {
                *(float2*)(C + (size_t)r0 * NC + cc) = make_float2(c0, c1);
                cs[nt][0] += c0; cs[nt][1] += c1;
                cq[nt][0] += c0 * c0; cq[nt][1] += c1 * c1;
            }
            if (r1 < M) {
                *(float2*)(C + (size_t)r1 * NC + cc) = make_float2(c2, c3);
                cs[nt][0] += c2; cs[nt][1] += c3;
                cq[nt][0] += c2 * c2; cq[nt][1] += c3 * c3;
            }
        }
    }
    if (sumO) {
#pragma unroll
        for (int off = 4; off < 32; off <<= 1) {
#pragma unroll
            for (int nt = 0; nt < 4; nt++) {
#pragma unroll
                for (int p = 0; p < 2; p++) {
                    cs[nt][p] += __shfl_xor_sync(0xffffffffu, cs[nt][p], off);
                    cq[nt][p] += __shfl_xor_sync(0xffffffffu, cq[nt][p], off);
                }
            }
        }
        if (group == 0) {
#pragma unroll
            for (int nt = 0; nt < 4; nt++) {
                int cc = nBase + warpN * 32 + nt * 8 + 2 * qt;
                atomicAdd(sumO + cc,     cs[nt][0]);
                atomicAdd(sumO + cc + 1, cs[nt][1]);
                atomicAdd(sqO  + cc,     cq[nt][0]);
                atomicAdd(sqO  + cc + 1, cq[nt][1]);
            }
        }
    }
}

// pre1 is recomputed on the fly (never materialized):
// pre1[2e]   = a0[u]+a0[v]+a1[u]+ew2[2e]
// pre1[2e+1] = a0[u]+a0[v]+a1[v]+ew2[2e+1]

// pass 1: BN stats of pre1 (slot 0), no store
__global__ void k_stats1(const float* __restrict__ ew2) {
    int c = threadIdx.x;  // 128
    float ls = 0.f, lq = 0.f;
    for (int e = blockIdx.x; e < NE; e += gridDim.x) {
        int u = s_u[e], v = s_v[e];
        float a0u = s_a0[(size_t)u * 128 + c], a0v = s_a0[(size_t)v * 128 + c];
        float a1u = s_a1[(size_t)u * 128 + c], a1v = s_a1[(size_t)v * 128 + c];
        float base = a0u + a0v;
        size_t r0 = (size_t)(2 * e) * 128, r1 = (size_t)(2 * e + 1) * 128;
        float p0 = base + a1u + ew2[r0 + c];
        float p1 = base + a1v + ew2[r1 + c];
        ls += p0 + p1; lq += p0 * p0 + p1 * p1;
    }
    atomicAdd(&s_sum[c], ls);
    atomicAdd(&s_sq[c],  lq);
}

// pass 2: recompute pre1, BN+ReLU, scatter: nacc[u] += e12*h0 + (h0+h1), sym for v
__global__ void k_scatter(const float* __restrict__ ew2,
                          const float* __restrict__ g, const float* __restrict__ b,
                          const float* __restrict__ eps12p) {
    int c = threadIdx.x;
    float mean = s_sum[c] * (1.0f / TE);
    float var  = s_sq[c]  * (1.0f / TE) - mean * mean;
    float sc = g[c] * rsqrtf(var + 1e-5f);
    float sh = b[c] - mean * sc;
    float e12 = 1.0f + *eps12p;
    for (int e = blockIdx.x; e < NE; e += gridDim.x) {
        int u = s_u[e], v = s_v[e];
        float a0u = s_a0[(size_t)u * 128 + c], a0v = s_a0[(size_t)v * 128 + c];
        float a1u = s_a1[(size_t)u * 128 + c], a1v = s_a1[(size_t)v * 128 + c];
        float base = a0u + a0v;
        size_t r0 = (size_t)(2 * e) * 128, r1 = (size_t)(2 * e + 1) * 128;
        float p0 = base + a1u + ew2[r0 + c];
        float p1 = base + a1v + ew2[r1 + c];
        float h0 = fmaxf(p0 * sc + sh, 0.f);
        float h1 = fmaxf(p1 * sc + sh, 0.f);
        float ds = h0 + h1;
        atomicAdd(&s_nacc[(size_t)u * 128 + c], e12 * h0 + ds);
        atomicAdd(&s_nacc[(size_t)v * 128 + c], e12 * h1 + ds);
    }
}

__global__ void k_nin(const float* __restrict__ nr, const float* __restrict__ eps11p) {
    float e11 = 1.0f + *eps11p;
    size_t stride = (size_t)gridDim.x * blockDim.x;
    size_t n = (size_t)NN * 128;
    for (size_t i = (size_t)blockIdx.x * blockDim.x + threadIdx.x; i < n; i += stride)
        s_nin[i] = e11 * nr[i] + s_nacc[i];
}

// edge_in rows: [fh(e), sh(r)]
__global__ void k_ein(const float* __restrict__ er, const float* __restrict__ nr,
                      const float* __restrict__ eps2p) {
    int c = threadIdx.x;
    float e2 = 1.0f + *eps2p;
    for (int e = blockIdx.x; e < NE; e += gridDim.x) {
        int u = s_u[e], v = s_v[e];
        size_t er0i = (size_t)(2 * e) * 128, er1i = (size_t)(2 * e + 1) * 128;
        float er0 = er[er0i + c], er1 = er[er1i + c];
        float nru = nr[(size_t)u * 128 + c], nrv = nr[(size_t)v * 128 + c];
        float fh = e2 * 0.5f * (er0 + er1) + nru + nrv;
        size_t r0 = (size_t)(2 * e) * 256, r1 = (size_t)(2 * e + 1) * 256;
        s_ein[r0 + c] = fh;
        s_ein[r1 + c] = fh;
        s_ein[r0 + 128 + c] = e2 * er0 + nru;
        s_ein[r1 + 128 + c] = e2 * er1 + nrv;
    }
}

// dst = relu(src*scale + shift), float4 vectorized; cols4 = cols/4 (power of 2)
__global__ void k_bnapply4(const float4* __restrict__ src, float4* __restrict__ dst,
                           int rows, int col4Mask,
                           const float* __restrict__ sum, const float* __restrict__ sq,
                           const float* __restrict__ g, const float* __restrict__ b,
                           float inv) {
    size_t n = (size_t)rows * (col4Mask + 1);
    size_t stride = (size_t)gridDim.x * blockDim.x;
    for (size_t i = (size_t)blockIdx.x * blockDim.x + threadIdx.x; i < n; i += stride) {
        int c = (int)(i & (size_t)col4Mask) << 2;
        float4 v = src[i];
        float4 o;
#pragma unroll
        for (int j = 0; j < 4; j++) {
            float mean = sum[c + j] * inv;
            float var  = sq[c + j] * inv - mean * mean;
            float scv = g[c + j] * rsqrtf(var + 1e-5f);
            float shv = b[c + j] - mean * scv;
            float x = (&v.x)[j] * scv + shv;
            (&o.x)[j] = fmaxf(x, 0.f);
        }
        dst[i] = o;
    }
}

// ---------------- launch ----------------
extern "C" void kernel_launch(void* const* d_in, const int* in_sizes, int n_in,
                              void* d_out, int out_size) {
    const float* nr      = (const float*)d_in[0];
    const float* er      = (const float*)d_in[1];
    const void*  ei      = d_in[2];
    const float* lift_w1 = (const float*)d_in[3];
    const float* lift_g1 = (const float*)d_in[4];
    const float* lift_b1 = (const float*)d_in[5];
    const float* lift_w2 = (const float*)d_in[6];
    const float* lift_g2 = (const float*)d_in[7];
    const float* lift_b2 = (const float*)d_in[8];
    const float* lvl1_w  = (const float*)d_in[9];
    const float* lvl1_g  = (const float*)d_in[10];
    const float* lvl1_b  = (const float*)d_in[11];
    const float* lvl2_w1 = (const float*)d_in[12];
    const float* lvl2_g1 = (const float*)d_in[13];
    const float* lvl2_b1 = (const float*)d_in[14];
    const float* lvl2_w2 = (const float*)d_in[15];
    const float* lvl2_g2 = (const float*)d_in[16];
    const float* lvl2_b2 = (const float*)d_in[17];
    const float* eps11   = (const float*)d_in[18];
    const float* eps12   = (const float*)d_in[19];
    const float* eps2    = (const float*)d_in[20];

    float* out_node = (float*)d_out;
    float* out_edge = out_node + (size_t)NN * HH;

    float *p_ew2, *p_a0, *p_a1, *p_nin, *p_np1, *p_np2, *p_ein, *p_ep1, *p_ep2, *p_sum, *p_sq;
    cudaGetSymbolAddress((void**)&p_ew2, s_ew2);
    cudaGetSymbolAddress((void**)&p_a0,  s_a0);
    cudaGetSymbolAddress((void**)&p_a1,  s_a1);
    cudaGetSymbolAddress((void**)&p_nin, s_nin);
    cudaGetSymbolAddress((void**)&p_np1, s_np1);
    cudaGetSymbolAddress((void**)&p_np2, s_np2);
    cudaGetSymbolAddress((void**)&p_ein, s_ein);
    cudaGetSymbolAddress((void**)&p_ep1, s_ep1);
    cudaGetSymbolAddress((void**)&p_ep2, s_ep2);
    cudaGetSymbolAddress((void**)&p_sum, s_sum);
    cudaGetSymbolAddress((void**)&p_sq,  s_sq);

    static int smem_set = 0;
    if (!smem_set) {
        cudaFuncSetAttribute(k_mma_p<false, false>, cudaFuncAttributeMaxDynamicSharedMemorySize, SMEM_BYTES);
        cudaFuncSetAttribute(k_mma_p<false, true>,  cudaFuncAttributeMaxDynamicSharedMemorySize, SMEM_BYTES);
        cudaFuncSetAttribute(k_mma_p<true,  false>, cudaFuncAttributeMaxDynamicSharedMemorySize, SMEM_BYTES);
        smem_set = 1;
    }

    const int GN  = (NN + 127) / 128;  // 157
    const int GTE = TE / 128;          // 2500

    k_zero<<<2048, 256>>>();
    k_detect<<<1, 32>>>((const int*)ei);
    k_decode<<<(NE + 255) / 256, 256>>>(ei);

    // lvl1 pieces: EW2 = er @ W[256:384], A0 = nr @ W[0:128], A1 = nr @ W[128:256]
    k_mma_p<false, false><<<dim3(GTE, 1), 256, SMEM_BYTES>>>(er, lvl1_w + 256 * 128, p_ew2, TE, 128, 128,
                                 nullptr, nullptr, nullptr, nullptr, nullptr, nullptr, 0.f);
    k_mma_p<false, false><<<dim3(GN, 1), 256, SMEM_BYTES>>>(nr, lvl1_w,             p_a0, NN, 128, 128,
                                 nullptr, nullptr, nullptr, nullptr, nullptr, nullptr, 0.f);
    k_mma_p<false, false><<<dim3(GN, 1), 256, SMEM_BYTES>>>(nr, lvl1_w + 128 * 128, p_a1, NN, 128, 128,
                                 nullptr, nullptr, nullptr, nullptr, nullptr, nullptr, 0.f);

    k_stats1<<<2048, 128>>>(p_ew2);                            // stats slot 0 (no pre1 store)
    k_scatter<<<2048, 128>>>(p_ew2, lvl1_g, lvl1_b, eps12);    // recompute + BN + scatter

    // node path: np1 raw + stats(slot1); np2 applies BN(slot1) on A-load, stats(slot2)
    k_nin<<<4096, 256>>>(nr, eps11);
    k_mma_p<false, true><<<dim3(2, GN), 256, SMEM_BYTES>>>(p_nin, lvl2_w1, p_np1, NN, 128, 256,
                                p_sum + 256, p_sq + 256,
                                nullptr, nullptr, nullptr, nullptr, 0.f);
    k_mma_p<true, false><<<dim3(GN, 1), 256, SMEM_BYTES>>>(p_np1, lvl2_w2, p_np2, NN, 256, 128,
                                p_sum + 512, p_sq + 512,
                                p_sum + 256, p_sq + 256, lvl2_g1, lvl2_b1, 1.0f / NN);
    k_bnapply4<<<2048, 256>>>((const float4*)p_np2, (float4*)out_node, NN, 31,
                              p_sum + 512, p_sq + 512, lvl2_g2, lvl2_b2, 1.0f / NN);

    // edge path: ein materialized (coalesced); ep1 raw + stats(slot3); ep2 BN-fused, stats(slot4)
    k_ein<<<2048, 128>>>(er, nr, eps2);
    k_mma_p<false, true><<<dim3(2, GTE), 256, SMEM_BYTES>>>(p_ein, lift_w1, p_ep1, TE, 256, 256,
                                 p_sum + 768, p_sq + 768,
                                 nullptr, nullptr, nullptr, nullptr, 0.f);
    k_mma_p<true, false><<<dim3(GTE, 1), 256, SMEM_BYTES>>>(p_ep1, lift_w2, p_ep2, TE, 256, 128,
                                 p_sum + 1024, p_sq + 1024,
                                 p_sum + 768, p_sq + 768, lift_g1, lift_b1, 1.0f / TE);
    k_bnapply4<<<4096, 256>>>((const float4*)p_ep2, (float4*)out_edge, TE, 31,
                              p_sum + 1024, p_sq + 1024, lift_g2, lift_b2, 1.0f / TE);
}

// round 6
// speedup vs baseline: 1.0723x; 1.0723x over previous
#include <cuda_runtime.h>
#include <cuda_fp16.h>

#define NN 20000      // nodes
#define NE 160000     // edges
#define TE 320000     // 2E edge-rows
#define HH 128

// ---------------- scratch (static __device__, no allocs) ----------------
__device__ __align__(128) __half s_ew2 [(size_t)TE * 128];   // er @ W2
__device__ __align__(128) __half s_a0  [(size_t)NN * 128];   // nr @ W0
__device__ __align__(128) __half s_a1  [(size_t)NN * 128];   // nr @ W1
__device__ __align__(128) __half s_pre1[(size_t)TE * 128];   // lvl1 pre-act
__device__ __align__(128) float  s_nacc[(size_t)NN * 128];   // node scatter accum (fp32 atomics)
__device__ __align__(128) __half s_nin [(size_t)NN * 128];
__device__ __align__(128) __half s_np1 [(size_t)NN * 256];
__device__ __align__(128) float  s_np2 [(size_t)NN * 128];   // final pre-act: fp32
__device__ __align__(128) __half s_ein [(size_t)TE * 256];
__device__ __align__(128) __half s_ep1 [(size_t)TE * 256];
__device__ __align__(128) float  s_ep2 [(size_t)TE * 128];   // final pre-act: fp32
__device__ float s_sum[5 * 256];
__device__ float s_sq [5 * 256];
__device__ int   s_u[NE];
__device__ int   s_v[NE];
__device__ int   g_is64;

// ---------------- helpers ----------------
__global__ void k_zero() {
    size_t stride = (size_t)gridDim.x * blockDim.x;
    size_t i0 = (size_t)blockIdx.x * blockDim.x + threadIdx.x;
    size_t n = (size_t)NN * 128;
    for (size_t i = i0; i < n; i += stride) s_nacc[i] = 0.0f;
    if (i0 < 5 * 256) { s_sum[i0] = 0.0f; s_sq[i0] = 0.0f; }
}

__global__ void k_detect(const int* __restrict__ ei32) {
    if (threadIdx.x == 0 && blockIdx.x == 0) {
        int nz = 0;
        for (int i = 0; i < 256; i++) nz |= ei32[2 * i + 1];
        g_is64 = (nz == 0) ? 1 : 0;
    }
}

__global__ void k_decode(const void* __restrict__ ei) {
    int e = blockIdx.x * blockDim.x + threadIdx.x;
    if (e >= NE) return;
    if (g_is64) {
        const long long* p = (const long long*)ei;
        s_u[e] = (int)p[e];
        s_v[e] = (int)p[NE + e];
    } else {
        const int* p = (const int*)ei;
        s_u[e] = p[e];
        s_v[e] = p[NE + e];
    }
}

__device__ __forceinline__ unsigned f2tf(float x) {
    unsigned r;
    asm("cvt.rna.tf32.f32 %0, %1;" : "=r"(r) : "f"(x));
    return r;
}

__device__ __forceinline__ void cpasync16(void* smem_ptr, const void* gptr, int src_bytes) {
    unsigned saddr = (unsigned)__cvta_generic_to_shared(smem_ptr);
    asm volatile("cp.async.cg.shared.global [%0], [%1], 16, %2;"
                 :: "r"(saddr), "l"(gptr), "r"(src_bytes));
}
__device__ __forceinline__ void cpasync_commit() {
    asm volatile("cp.async.commit_group;");
}
template <int N>
__device__ __forceinline__ void cpasync_wait() {
    asm volatile("cp.async.wait_group %0;" :: "n"(N));
}

#define MMA_TF32(d, Af, Bf)                                                     \
    asm volatile(                                                               \
        "mma.sync.aligned.m16n8k8.row.col.f32.tf32.tf32.f32 "                   \
        "{%0,%1,%2,%3},{%4,%5,%6,%7},{%8,%9},{%0,%1,%2,%3};"                    \
        : "+f"(d[0]), "+f"(d[1]), "+f"(d[2]), "+f"(d[3])                        \
        : "r"(Af[0]), "r"(Af[1]), "r"(Af[2]), "r"(Af[3]),                       \
          "r"(Bf[0]), "r"(Bf[1]))

// smem load converters + typed stores
__device__ __forceinline__ float ldA(const float* p)  { return *p; }
__device__ __forceinline__ float ldA(const __half* p) { return __half2float(*p); }
__device__ __forceinline__ void st2(float* C, size_t off, float c0, float c1,
                                    float& r0, float& r1) {
    *(float2*)(C + off) = make_float2(c0, c1);
    r0 = c0; r1 = c1;
}
__device__ __forceinline__ void st2(__half* C, size_t off, float c0, float c1,
                                    float& r0, float& r1) {
    __half2 h = __floats2half2_rn(c0, c1);
    *(__half2*)(C + off) = h;
    r0 = __low2float(h); r1 = __high2float(h);   // stats on stored (rounded) values
}

// ---------------- pipelined TF32 GEMM, 128x128 tile, BK=32, cp.async 2-stage ----------------
// A dtype TA (float|half), C dtype TC (float|half). B always fp32.
#define BS_STRIDE 136
#define BS_TILE (32 * BS_STRIDE)

template <typename TA> struct ACfg;
template <> struct ACfg<float>  { static const int STR = 36; };   // 144B/row, conflict-free
template <> struct ACfg<__half> { static const int STR = 40; };   // 80B/row, conflict-free

#define SMEM_BYTES_F (2 * 128 * 36 * 4 + 2 * BS_TILE * 4 + 512 * 4)   // 73728
#define SMEM_BYTES_H (2 * 128 * 40 * 2 + 2 * BS_TILE * 4 + 512 * 4)   // 57344

template <typename TA, typename TC, bool FUSE_BN, bool SWAP>
__global__ __launch_bounds__(256, 2) void k_mma_p(
    const TA* __restrict__ A, const float* __restrict__ Bm,
    TC* __restrict__ C, int M, int K, int NC,
    float* __restrict__ sumO, float* __restrict__ sqO,
    const float* __restrict__ aSum, const float* __restrict__ aSq,
    const float* __restrict__ aG, const float* __restrict__ aBt, float aInv)
{
    const int ASTR = ACfg<TA>::STR;
    const int AS_TILE = 128 * ASTR;
    const int EPC = 16 / sizeof(TA);        // elems per cp.async
    const int TPR = 32 / EPC;               // threads per A row
    const int RPI = 256 / TPR;              // rows per iteration
    const int NIT = 128 / RPI;

    extern __shared__ char dsmRaw[];
    TA* AsB = (TA*)dsmRaw;
    float* BsB = (float*)(dsmRaw + 2 * AS_TILE * sizeof(TA));
    float* scS = BsB + 2 * BS_TILE;
    float* shS = scS + 256;

    const int tid = threadIdx.x;
    const int lane = tid & 31, warp = tid >> 5;
    const int group = lane >> 2, qt = lane & 3;
    const int warpM = warp & 1, warpN = warp >> 1;
    const int mBase = (SWAP ? blockIdx.y : blockIdx.x) * 128;
    const int nBase = (SWAP ? blockIdx.x : blockIdx.y) * 128;
    const int nk = K >> 5;

    if (FUSE_BN) {
        if (tid < K) {
            float mean = aSum[tid] * aInv;
            float var  = aSq[tid] * aInv - mean * mean;
            float s = aG[tid] * rsqrtf(var + 1e-5f);
            scS[tid] = s; shS[tid] = aBt[tid] - mean * s;
        }
    }

    const int arow = tid / TPR, akq = (tid % TPR) * EPC;
    const int bkr = tid >> 5, bnc = (tid & 31) << 2;

    auto issue = [&](int i, int b) {
        const int k0 = i << 5;
        TA* As = AsB + b * AS_TILE;
        float* Bs = BsB + b * BS_TILE;
#pragma unroll
        for (int it = 0; it < NIT; it++) {
            int row = arow + it * RPI;
            int gm = mBase + row;
            const TA* src = A + (size_t)(gm < M ? gm : 0) * K + k0 + akq;
            cpasync16(As + row * ASTR + akq, src, gm < M ? 16 : 0);
        }
#pragma unroll
        for (int it = 0; it < 4; it++) {
            int kr = bkr + it * 8;
            const float* src = Bm + (size_t)(k0 + kr) * NC + nBase + bnc;
            cpasync16(Bs + kr * BS_STRIDE + bnc, src, 16);
        }
        cpasync_commit();
    };

    float acc[4][4][4];
#pragma unroll
    for (int mt = 0; mt < 4; mt++)
#pragma unroll
        for (int nt = 0; nt < 4; nt++)
#pragma unroll
            for (int i = 0; i < 4; i++) acc[mt][nt][i] = 0.0f;

    issue(0, 0);

    for (int i = 0; i < nk; i++) {
        if (i + 1 < nk) { issue(i + 1, (i + 1) & 1); cpasync_wait<1>(); }
        else            { cpasync_wait<0>(); }
        __syncthreads();

        const TA* As = AsB + (i & 1) * AS_TILE;
        const float* Bs = BsB + (i & 1) * BS_TILE;
        const int k0 = i << 5;
#pragma unroll
        for (int ks = 0; ks < 4; ks++) {
            const int kc = ks * 8 + qt;
            float sc0, sh0, sc1, sh1;
            if (FUSE_BN) {
                sc0 = scS[k0 + kc];     sh0 = shS[k0 + kc];
                sc1 = scS[k0 + kc + 4]; sh1 = shS[k0 + kc + 4];
            }
            unsigned af[4][4], bf[4][2];
#pragma unroll
            for (int mt = 0; mt < 4; mt++) {
                int r = warpM * 64 + mt * 16 + group;
                float a0 = ldA(As + r * ASTR + kc);
                float a1 = ldA(As + (r + 8) * ASTR + kc);
                float a2 = ldA(As + r * ASTR + kc + 4);
                float a3 = ldA(As + (r + 8) * ASTR + kc + 4);
                if (FUSE_BN) {
                    a0 = fmaxf(fmaf(a0, sc0, sh0), 0.f);
                    a1 = fmaxf(fmaf(a1, sc0, sh0), 0.f);
                    a2 = fmaxf(fmaf(a2, sc1, sh1), 0.f);
                    a3 = fmaxf(fmaf(a3, sc1, sh1), 0.f);
                }
                af[mt][0] = f2tf(a0); af[mt][1] = f2tf(a1);
                af[mt][2] = f2tf(a2); af[mt][3] = f2tf(a3);
            }
#pragma unroll
            for (int nt = 0; nt < 4; nt++) {
                int cb = warpN * 32 + nt * 8 + group;
                bf[nt][0] = f2tf(Bs[kc * BS_STRIDE + cb]);
                bf[nt][1] = f2tf(Bs[(kc + 4) * BS_STRIDE + cb]);
            }
#pragma unroll
            for (int mt = 0; mt < 4; mt++)
#pragma unroll
                for (int nt = 0; nt < 4; nt++)
                    MMA_TF32(acc[mt][nt], af[mt], bf[nt]);
        }
        __syncthreads();
    }

    // epilogue: store + per-thread column partials (stats on stored/rounded values)
    float cs[4][2], cq[4][2];
#pragma unroll
    for (int nt = 0; nt < 4; nt++) { cs[nt][0] = cs[nt][1] = 0.f; cq[nt][0] = cq[nt][1] = 0.f; }
#pragma unroll
    for (int mt = 0; mt < 4; mt++) {
        int r0 = mBase + warpM * 64 + mt * 16 + group;
        int r1 = r0 + 8;
#pragma unroll
        for (int nt = 0; nt < 4; nt++) {
            int cc = nBase + warpN * 32 + nt * 8 + 2 * qt;
            float x0, x1;
            if (r0 < M) {
                st2(C, (size_t)r0 * NC + cc, acc[mt][nt][0], acc[mt][nt][1], x0, x1);
                cs[nt][0] += x0; cs[nt][1] += x1;
                cq[nt][0] += x0 * x0; cq[nt][1] += x1 * x1;
            }
            if (r1 < M) {
                st2(C, (size_t)r1 * NC + cc, acc[mt][nt][2], acc[mt][nt][3], x0, x1);
                cs[nt][0] += x0; cs[nt][1] += x1;
                cq[nt][0] += x0 * x0; cq[nt][1] += x1 * x1;
            }
        }
    }
    if (sumO) {
#pragma unroll
        for (int off = 4; off < 32; off <<= 1) {
#pragma unroll
            for (int nt = 0; nt < 4; nt++) {
#pragma unroll
                for (int p = 0; p < 2; p++) {
                    cs[nt][p] += __shfl_xor_sync(0xffffffffu, cs[nt][p], off);
                    cq[nt][p] += __shfl_xor_sync(0xffffffffu, cq[nt][p], off);
                }
            }
        }
        if (group == 0) {
#pragma unroll
            for (int nt = 0; nt < 4; nt++) {
                int cc = nBase + warpN * 32 + nt * 8 + 2 * qt;
                atomicAdd(sumO + cc,     cs[nt][0]);
                atomicAdd(sumO + cc + 1, cs[nt][1]);
                atomicAdd(sqO  + cc,     cq[nt][0]);
                atomicAdd(sqO  + cc + 1, cq[nt][1]);
            }
        }
    }
}

// pre1[2e]   = A0[u]+A0[v]+A1[u]+EW2[2e]
// pre1[2e+1] = A0[u]+A0[v]+A1[v]+EW2[2e+1]; store half; stats (slot 0) on stored values
__global__ void k_combine() {
    int c = threadIdx.x;  // 128
    float ls = 0.f, lq = 0.f;
    for (int e = blockIdx.x; e < NE; e += gridDim.x) {
        int u = s_u[e], v = s_v[e];
        float a0u = __half2float(s_a0[(size_t)u * 128 + c]);
        float a0v = __half2float(s_a0[(size_t)v * 128 + c]);
        float a1u = __half2float(s_a1[(size_t)u * 128 + c]);
        float a1v = __half2float(s_a1[(size_t)v * 128 + c]);
        float base = a0u + a0v;
        size_t r0 = (size_t)(2 * e) * 128, r1 = (size_t)(2 * e + 1) * 128;
        float p0 = base + a1u + __half2float(s_ew2[r0 + c]);
        float p1 = base + a1v + __half2float(s_ew2[r1 + c]);
        __half h0 = __float2half_rn(p0), h1 = __float2half_rn(p1);
        s_pre1[r0 + c] = h0;
        s_pre1[r1 + c] = h1;
        float q0 = __half2float(h0), q1 = __half2float(h1);
        ls += q0 + q1; lq += q0 * q0 + q1 * q1;
    }
    atomicAdd(&s_sum[c], ls);
    atomicAdd(&s_sq[c],  lq);
}

// BN+ReLU on pre1(half), then scatter: nacc[u] += (1+eps12)*h0 + (h0+h1), sym for v
__global__ void k_scatter(const float* __restrict__ g, const float* __restrict__ b,
                          const float* __restrict__ eps12p) {
    int c = threadIdx.x;
    float mean = s_sum[c] * (1.0f / TE);
    float var  = s_sq[c]  * (1.0f / TE) - mean * mean;
    float sc = g[c] * rsqrtf(var + 1e-5f);
    float sh = b[c] - mean * sc;
    float e12 = 1.0f + *eps12p;
    for (int e = blockIdx.x; e < NE; e += gridDim.x) {
        int u = s_u[e], v = s_v[e];
        size_t r0 = (size_t)(2 * e) * 128, r1 = (size_t)(2 * e + 1) * 128;
        float h0 = fmaxf(__half2float(s_pre1[r0 + c]) * sc + sh, 0.f);
        float h1 = fmaxf(__half2float(s_pre1[r1 + c]) * sc + sh, 0.f);
        float ds = h0 + h1;
        atomicAdd(&s_nacc[(size_t)u * 128 + c], e12 * h0 + ds);
        atomicAdd(&s_nacc[(size_t)v * 128 + c], e12 * h1 + ds);
    }
}

__global__ void k_nin(const float* __restrict__ nr, const float* __restrict__ eps11p) {
    float e11 = 1.0f + *eps11p;
    size_t stride = (size_t)gridDim.x * blockDim.x;
    size_t n = (size_t)NN * 128;
    for (size_t i = (size_t)blockIdx.x * blockDim.x + threadIdx.x; i < n; i += stride)
        s_nin[i] = __float2half_rn(e11 * nr[i] + s_nacc[i]);
}

// edge_in rows (half): [fh(e), sh(r)]
__global__ void k_ein(const float* __restrict__ er, const float* __restrict__ nr,
                      const float* __restrict__ eps2p) {
    int c = threadIdx.x;
    float e2 = 1.0f + *eps2p;
    for (int e = blockIdx.x; e < NE; e += gridDim.x) {
        int u = s_u[e], v = s_v[e];
        size_t er0i = (size_t)(2 * e) * 128, er1i = (size_t)(2 * e + 1) * 128;
        float er0 = er[er0i + c], er1 = er[er1i + c];
        float nru = nr[(size_t)u * 128 + c], nrv = nr[(size_t)v * 128 + c];
        __half fh = __float2half_rn(e2 * 0.5f * (er0 + er1) + nru + nrv);
        size_t r0 = (size_t)(2 * e) * 256, r1 = (size_t)(2 * e + 1) * 256;
        s_ein[r0 + c] = fh;
        s_ein[r1 + c] = fh;
        s_ein[r0 + 128 + c] = __float2half_rn(e2 * er0 + nru);
        s_ein[r1 + 128 + c] = __float2half_rn(e2 * er1 + nrv);
    }
}

// dst = relu(src*scale + shift), float4 vectorized; cols = 128
__global__ void k_bnapply4(const float4* __restrict__ src, float4* __restrict__ dst,
                           int rows, int col4Mask,
                           const float* __restrict__ sum, const float* __restrict__ sq,
                           const float* __restrict__ g, const float* __restrict__ b,
                           float inv) {
    size_t n = (size_t)rows * (col4Mask + 1);
    size_t stride = (size_t)gridDim.x * blockDim.x;
    for (size_t i = (size_t)blockIdx.x * blockDim.x + threadIdx.x; i < n; i += stride) {
        int c = (int)(i & (size_t)col4Mask) << 2;
        float4 v = src[i];
        float4 o;
#pragma unroll
        for (int j = 0; j < 4; j++) {
            float mean = sum[c + j] * inv;
            float var  = sq[c + j] * inv - mean * mean;
            float scv = g[c + j] * rsqrtf(var + 1e-5f);
            float shv = b[c + j] - mean * scv;
            float x = (&v.x)[j] * scv + shv;
            (&o.x)[j] = fmaxf(x, 0.f);
        }
        dst[i] = o;
    }
}

// ---------------- launch ----------------
extern "C" void kernel_launch(void* const* d_in, const int* in_sizes, int n_in,
                              void* d_out, int out_size) {
    const float* nr      = (const float*)d_in[0];
    const float* er      = (const float*)d_in[1];
    const void*  ei      = d_in[2];
    const float* lift_w1 = (const float*)d_in[3];
    const float* lift_g1 = (const float*)d_in[4];
    const float* lift_b1 = (const float*)d_in[5];
    const float* lift_w2 = (const float*)d_in[6];
    const float* lift_g2 = (const float*)d_in[7];
    const float* lift_b2 = (const float*)d_in[8];
    const float* lvl1_w  = (const float*)d_in[9];
    const float* lvl1_g  = (const float*)d_in[10];
    const float* lvl1_b  = (const float*)d_in[11];
    const float* lvl2_w1 = (const float*)d_in[12];
    const float* lvl2_g1 = (const float*)d_in[13];
    const float* lvl2_b1 = (const float*)d_in[14];
    const float* lvl2_w2 = (const float*)d_in[15];
    const float* lvl2_g2 = (const float*)d_in[16];
    const float* lvl2_b2 = (const float*)d_in[17];
    const float* eps11   = (const float*)d_in[18];
    const float* eps12   = (const float*)d_in[19];
    const float* eps2    = (const float*)d_in[20];

    float* out_node = (float*)d_out;
    float* out_edge = out_node + (size_t)NN * HH;

    __half *p_ew2, *p_a0, *p_a1, *p_nin, *p_np1, *p_ein, *p_ep1;
    float *p_np2, *p_ep2, *p_sum, *p_sq;
    cudaGetSymbolAddress((void**)&p_ew2, s_ew2);
    cudaGetSymbolAddress((void**)&p_a0,  s_a0);
    cudaGetSymbolAddress((void**)&p_a1,  s_a1);
    cudaGetSymbolAddress((void**)&p_nin, s_nin);
    cudaGetSymbolAddress((void**)&p_np1, s_np1);
    cudaGetSymbolAddress((void**)&p_np2, s_np2);
    cudaGetSymbolAddress((void**)&p_ein, s_ein);
    cudaGetSymbolAddress((void**)&p_ep1, s_ep1);
    cudaGetSymbolAddress((void**)&p_ep2, s_ep2);
    cudaGetSymbolAddress((void**)&p_sum, s_sum);
    cudaGetSymbolAddress((void**)&p_sq,  s_sq);

    static int smem_set = 0;
    if (!smem_set) {
        cudaFuncSetAttribute((const void*)k_mma_p<float,  __half, false, false>,
                             cudaFuncAttributeMaxDynamicSharedMemorySize, SMEM_BYTES_F);
        cudaFuncSetAttribute((const void*)k_mma_p<__half, __half, false, true>,
                             cudaFuncAttributeMaxDynamicSharedMemorySize, SMEM_BYTES_H);
        cudaFuncSetAttribute((const void*)k_mma_p<__half, float,  true,  false>,
                             cudaFuncAttributeMaxDynamicSharedMemorySize, SMEM_BYTES_H);
        smem_set = 1;
    }

    const int GN  = (NN + 127) / 128;  // 157
    const int GTE = TE / 128;          // 2500

    k_zero<<<2048, 256>>>();
    k_detect<<<1, 32>>>((const int*)ei);
    k_decode<<<(NE + 255) / 256, 256>>>(ei);

    // lvl1 pieces: EW2 = er @ W[256:384], A0 = nr @ W[0:128], A1 = nr @ W[128:256]  (C=half)
    k_mma_p<float, __half, false, false><<<dim3(GTE, 1), 256, SMEM_BYTES_F>>>(
        er, lvl1_w + 256 * 128, p_ew2, TE, 128, 128,
        nullptr, nullptr, nullptr, nullptr, nullptr, nullptr, 0.f);
    k_mma_p<float, __half, false, false><<<dim3(GN, 1), 256, SMEM_BYTES_F>>>(
        nr, lvl1_w, p_a0, NN, 128, 128,
        nullptr, nullptr, nullptr, nullptr, nullptr, nullptr, 0.f);
    k_mma_p<float, __half, false, false><<<dim3(GN, 1), 256, SMEM_BYTES_F>>>(
        nr, lvl1_w + 128 * 128, p_a1, NN, 128, 128,
        nullptr, nullptr, nullptr, nullptr, nullptr, nullptr, 0.f);

    k_combine<<<2048, 128>>>();                             // stats slot 0, pre1 half
    k_scatter<<<2048, 128>>>(lvl1_g, lvl1_b, eps12);        // BN+ReLU + fused scatter

    // node path: np1(half) + stats(slot1); np2(fp32) BN-fused on A, stats(slot2)
    k_nin<<<4096, 256>>>(nr, eps11);
    k_mma_p<__half, __half, false, true><<<dim3(2, GN), 256, SMEM_BYTES_H>>>(
        p_nin, lvl2_w1, p_np1, NN, 128, 256,
        p_sum + 256, p_sq + 256, nullptr, nullptr, nullptr, nullptr, 0.f);
    k_mma_p<__half, float, true, false><<<dim3(GN, 1), 256, SMEM_BYTES_H>>>(
        p_np1, lvl2_w2, p_np2, NN, 256, 128,
        p_sum + 512, p_sq + 512,
        p_sum + 256, p_sq + 256, lvl2_g1, lvl2_b1, 1.0f / NN);
    k_bnapply4<<<2048, 256>>>((const float4*)p_np2, (float4*)out_node, NN, 31,
                              p_sum + 512, p_sq + 512, lvl2_g2, lvl2_b2, 1.0f / NN);

    // edge path: ein half; ep1(half) + stats(slot3); ep2(fp32) BN-fused, stats(slot4)
    k_ein<<<2048, 128>>>(er, nr, eps2);
    k_mma_p<__half, __half, false, true><<<dim3(2, GTE), 256, SMEM_BYTES_H>>>(
        p_ein, lift_w1, p_ep1, TE, 256, 256,
        p_sum + 768, p_sq + 768, nullptr, nullptr, nullptr, nullptr, 0.f);
    k_mma_p<__half, float, true, false><<<dim3(GTE, 1), 256, SMEM_BYTES_H>>>(
        p_ep1, lift_w2, p_ep2, TE, 256, 128,
        p_sum + 1024, p_sq + 1024,
        p_sum + 768, p_sq + 768, lift_g1, lift_b1, 1.0f / TE);
    k_bnapply4<<<4096, 256>>>((const float4*)p_ep2, (float4*)out_edge, TE, 31,
                              p_sum + 1024, p_sq + 1024, lift_g2, lift_b2, 1.0f / TE);
}

// round 9
// speedup vs baseline: 1.2614x; 1.1763x over previous
#include <cuda_runtime.h>
#include <cuda_fp16.h>
#include <cstring>

#define NN 20000      // nodes
#define NE 160000     // edges
#define TE 320000     // 2E edge-rows
#define HH 128

// ---------------- scratch (static __device__, no allocs) ----------------
__device__ __align__(128) __half s_ew2 [(size_t)TE * 128];   // er @ W2
__device__ __align__(128) __half s_a0  [(size_t)NN * 128];   // nr @ W0
__device__ __align__(128) __half s_a1  [(size_t)NN * 128];   // nr @ W1
__device__ __align__(128) __half s_pre1[(size_t)TE * 128];   // lvl1 pre-act
__device__ __align__(128) float  s_nacc[(size_t)NN * 128];   // node scatter accum
__device__ __align__(128) __half s_nin [(size_t)NN * 128];
__device__ __align__(128) __half s_np1 [(size_t)NN * 256];
__device__ __align__(128) float  s_np2 [(size_t)NN * 128];   // final pre-act: fp32
__device__ __align__(128) __half s_ein [(size_t)TE * 256];
__device__ __align__(128) __half s_ep1 [(size_t)TE * 256];
__device__ __align__(128) float  s_ep2 [(size_t)TE * 128];   // final pre-act: fp32
// fp16 weights, pre-transposed to n-major [N][K]
__device__ __align__(128) __half w_np1h[256 * 128];
__device__ __align__(128) __half w_np2h[128 * 256];
__device__ __align__(128) __half w_ep1h[256 * 256];
__device__ __align__(128) __half w_ep2h[128 * 256];
__device__ float s_sum[5 * 256];
__device__ float s_sq [5 * 256];
__device__ int   s_u[NE];
__device__ int   s_v[NE];
__device__ int   g_is64;

// ---------------- helpers ----------------
__device__ __forceinline__ unsigned h2u(__half2 h) {
    unsigned u;
    memcpy(&u, &h, 4);
    return u;
}

__global__ void k_zero() {
    size_t stride = (size_t)gridDim.x * blockDim.x;
    size_t i0 = (size_t)blockIdx.x * blockDim.x + threadIdx.x;
    size_t n = (size_t)NN * 128;
    for (size_t i = i0; i < n; i += stride) s_nacc[i] = 0.0f;
    if (i0 < 5 * 256) { s_sum[i0] = 0.0f; s_sq[i0] = 0.0f; }
}

__global__ void k_detect(const int* __restrict__ ei32) {
    if (threadIdx.x == 0 && blockIdx.x == 0) {
        int nz = 0;
        for (int i = 0; i < 256; i++) nz |= ei32[2 * i + 1];
        g_is64 = (nz == 0) ? 1 : 0;
    }
}

__global__ void k_decode(const void* __restrict__ ei) {
    int e = blockIdx.x * blockDim.x + threadIdx.x;
    if (e >= NE) return;
    if (g_is64) {
        const long long* p = (const long long*)ei;
        s_u[e] = (int)p[e];
        s_v[e] = (int)p[NE + e];
    } else {
        const int* p = (const int*)ei;
        s_u[e] = p[e];
        s_v[e] = p[NE + e];
    }
}

// convert + transpose weights to fp16 n-major
__global__ void k_wprep(const float* __restrict__ w_np1, const float* __restrict__ w_np2,
                        const float* __restrict__ w_ep1, const float* __restrict__ w_ep2) {
    int i = blockIdx.x * blockDim.x + threadIdx.x;   // 65536 threads
    if (i < 256 * 128) {            // np1: [128][256] -> [256][128]
        int n = i >> 7, k = i & 127;
        w_np1h[i] = __float2half_rn(w_np1[k * 256 + n]);
    }
    if (i < 128 * 256) {            // np2: [256][128] -> [128][256]
        int n = i >> 8, k = i & 255;
        w_np2h[i] = __float2half_rn(w_np2[k * 128 + n]);
    }
    if (i < 256 * 256) {            // ep1: [256][256] -> transposed
        int n = i >> 8, k = i & 255;
        w_ep1h[i] = __float2half_rn(w_ep1[k * 256 + n]);
    }
    if (i < 128 * 256) {            // ep2: [256][128] -> [128][256]
        int n = i >> 8, k = i & 255;
        w_ep2h[i] = __float2half_rn(w_ep2[k * 128 + n]);
    }
}

__device__ __forceinline__ unsigned f2tf(float x) {
    unsigned r;
    asm("cvt.rna.tf32.f32 %0, %1;" : "=r"(r) : "f"(x));
    return r;
}

__device__ __forceinline__ void cpasync16(void* smem_ptr, const void* gptr, int src_bytes) {
    unsigned saddr = (unsigned)__cvta_generic_to_shared(smem_ptr);
    asm volatile("cp.async.cg.shared.global [%0], [%1], 16, %2;"
                 :: "r"(saddr), "l"(gptr), "r"(src_bytes));
}
__device__ __forceinline__ void cpasync_commit() {
    asm volatile("cp.async.commit_group;");
}
template <int N>
__device__ __forceinline__ void cpasync_wait() {
    asm volatile("cp.async.wait_group %0;" :: "n"(N));
}

#define MMA_TF32(d, Af, Bf)                                                     \
    asm volatile(                                                               \
        "mma.sync.aligned.m16n8k8.row.col.f32.tf32.tf32.f32 "                   \
        "{%0,%1,%2,%3},{%4,%5,%6,%7},{%8,%9},{%0,%1,%2,%3};"                    \
        : "+f"(d[0]), "+f"(d[1]), "+f"(d[2]), "+f"(d[3])                        \
        : "r"(Af[0]), "r"(Af[1]), "r"(Af[2]), "r"(Af[3]),                       \
          "r"(Bf[0]), "r"(Bf[1]))

#define MMA_F16(d, Af, Bf)                                                      \
    asm volatile(                                                               \
        "mma.sync.aligned.m16n8k16.row.col.f32.f16.f16.f32 "                    \
        "{%0,%1,%2,%3},{%4,%5,%6,%7},{%8,%9},{%0,%1,%2,%3};"                    \
        : "+f"(d[0]), "+f"(d[1]), "+f"(d[2]), "+f"(d[3])                        \
        : "r"(Af[0]), "r"(Af[1]), "r"(Af[2]), "r"(Af[3]),                       \
          "r"(Bf[0]), "r"(Bf[1]))

// typed stores (stats on stored/rounded values)
__device__ __forceinline__ void st2(float* C, size_t off, float c0, float c1,
                                    float& r0, float& r1) {
    *(float2*)(C + off) = make_float2(c0, c1);
    r0 = c0; r1 = c1;
}
__device__ __forceinline__ void st2(__half* C, size_t off, float c0, float c1,
                                    float& r0, float& r1) {
    __half2 h = __floats2half2_rn(c0, c1);
    *(__half2*)(C + off) = h;
    r0 = __low2float(h); r1 = __high2float(h);
}

// ================= TF32 GEMM (float A, fp32 k-major B, half C) ==================
#define BS_STRIDE 136
#define BS_TILE (32 * BS_STRIDE)
#define AF_STRIDE 36
#define SMEM_BYTES_F (2 * 128 * AF_STRIDE * 4 + 2 * BS_TILE * 4 + 2048)   // 73728

__global__ __launch_bounds__(256, 2) void k_mma_f(
    const float* __restrict__ A, const float* __restrict__ Bm,
    __half* __restrict__ C, int M, int K, int NC)
{
    extern __shared__ float dsm[];
    float* AsB = dsm;
    float* BsB = dsm + 2 * 128 * AF_STRIDE;

    const int tid = threadIdx.x;
    const int lane = tid & 31, warp = tid >> 5;
    const int group = lane >> 2, qt = lane & 3;
    const int warpM = warp & 1, warpN = warp >> 1;
    const int mBase = blockIdx.x * 128, nBase = blockIdx.y * 128;
    const int nk = K >> 5;

    const int arow = tid >> 3, akq = (tid & 7) << 2;
    const int bkr = tid >> 5, bnc = (tid & 31) << 2;

    auto issue = [&](int i, int b) {
        const int k0 = i << 5;
        float* As = AsB + b * 128 * AF_STRIDE;
        float* Bs = BsB + b * BS_TILE;
#pragma unroll
        for (int it = 0; it < 4; it++) {
            int row = arow + it * 32;
            int gm = mBase + row;
            const float* src = A + (size_t)(gm < M ? gm : 0) * K + k0 + akq;
            cpasync16(As + row * AF_STRIDE + akq, src, gm < M ? 16 : 0);
        }
#pragma unroll
        for (int it = 0; it < 4; it++) {
            int kr = bkr + it * 8;
            const float* src = Bm + (size_t)(k0 + kr) * NC + nBase + bnc;
            cpasync16(Bs + kr * BS_STRIDE + bnc, src, 16);
        }
        cpasync_commit();
    };

    float acc[4][4][4];
#pragma unroll
    for (int mt = 0; mt < 4; mt++)
#pragma unroll
        for (int nt = 0; nt < 4; nt++)
#pragma unroll
            for (int i = 0; i < 4; i++) acc[mt][nt][i] = 0.0f;

    issue(0, 0);
    for (int i = 0; i < nk; i++) {
        if (i + 1 < nk) { issue(i + 1, (i + 1) & 1); cpasync_wait<1>(); }
        else            { cpasync_wait<0>(); }
        __syncthreads();
        const float* As = AsB + (i & 1) * 128 * AF_STRIDE;
        const float* Bs = BsB + (i & 1) * BS_TILE;
#pragma unroll
        for (int ks = 0; ks < 4; ks++) {
            const int kc = ks * 8 + qt;
            unsigned af[4][4], bf[4][2];
#pragma unroll
            for (int mt = 0; mt < 4; mt++) {
                int r = warpM * 64 + mt * 16 + group;
                af[mt][0] = f2tf(As[r * AF_STRIDE + kc]);
                af[mt][1] = f2tf(As[(r + 8) * AF_STRIDE + kc]);
                af[mt][2] = f2tf(As[r * AF_STRIDE + kc + 4]);
                af[mt][3] = f2tf(As[(r + 8) * AF_STRIDE + kc + 4]);
            }
#pragma unroll
            for (int nt = 0; nt < 4; nt++) {
                int cb = warpN * 32 + nt * 8 + group;
                bf[nt][0] = f2tf(Bs[kc * BS_STRIDE + cb]);
                bf[nt][1] = f2tf(Bs[(kc + 4) * BS_STRIDE + cb]);
            }
#pragma unroll
            for (int mt = 0; mt < 4; mt++)
#pragma unroll
                for (int nt = 0; nt < 4; nt++)
                    MMA_TF32(acc[mt][nt], af[mt], bf[nt]);
        }
        __syncthreads();
    }

#pragma unroll
    for (int mt = 0; mt < 4; mt++) {
        int r0 = mBase + warpM * 64 + mt * 16 + group;
        int r1 = r0 + 8;
#pragma unroll
        for (int nt = 0; nt < 4; nt++) {
            int cc = nBase + warpN * 32 + nt * 8 + 2 * qt;
            float x0, x1;
            if (r0 < M) st2(C, (size_t)r0 * NC + cc, acc[mt][nt][0], acc[mt][nt][1], x0, x1);
            if (r1 < M) st2(C, (size_t)r1 * NC + cc, acc[mt][nt][2], acc[mt][nt][3], x0, x1);
        }
    }
}

// ================= FP16 HMMA GEMM (half A [M][K], half B n-major [NC][K]) ==========
#define HSTR 40
#define HA_TILE (128 * HSTR)  // halfs per buffer (A or B)
#define SMEM_BYTES_H (4 * HA_TILE * 2 + 2048)   // 2 A-bufs + 2 B-bufs + BN = 43008

template <typename TC, bool FUSE_BN, bool SWAP>
__global__ __launch_bounds__(256, 2) void k_mma_h(
    const __half* __restrict__ A, const __half* __restrict__ Bt,
    TC* __restrict__ C, int M, int K, int NC,
    float* __restrict__ sumO, float* __restrict__ sqO,
    const float* __restrict__ aSum, const float* __restrict__ aSq,
    const float* __restrict__ aG, const float* __restrict__ aBt, float aInv)
{
    extern __shared__ char dsmRaw[];
    __half* AsB = (__half*)dsmRaw;
    __half* BsB = (__half*)(dsmRaw + 2 * HA_TILE * 2);
    float* scS = (float*)(dsmRaw + 4 * HA_TILE * 2);
    float* shS = scS + 256;

    const int tid = threadIdx.x;
    const int lane = tid & 31, warp = tid >> 5;
    const int group = lane >> 2, qt = lane & 3;
    const int warpM = warp & 1, warpN = warp >> 1;
    const int mBase = (SWAP ? blockIdx.y : blockIdx.x) * 128;
    const int nBase = (SWAP ? blockIdx.x : blockIdx.y) * 128;
    const int nk = K >> 5;

    if (FUSE_BN) {
        if (tid < K) {
            float mean = aSum[tid] * aInv;
            float var  = aSq[tid] * aInv - mean * mean;
            float s = aG[tid] * rsqrtf(var + 1e-5f);
            scS[tid] = s; shS[tid] = aBt[tid] - mean * s;
        }
        __syncthreads();
    }

    const int arow = tid >> 2, akq = (tid & 3) << 3;  // halfs: TPR=4, RPI=64

    auto issue = [&](int i, int b) {
        const int k0 = i << 5;
        __half* As = AsB + b * HA_TILE;
        __half* Bs = BsB + b * HA_TILE;
#pragma unroll
        for (int it = 0; it < 2; it++) {
            int row = arow + it * 64;
            int gm = mBase + row;
            const __half* src = A + (size_t)(gm < M ? gm : 0) * K + k0 + akq;
            cpasync16(As + row * HSTR + akq, src, gm < M ? 16 : 0);
        }
#pragma unroll
        for (int it = 0; it < 2; it++) {
            int row = arow + it * 64;
            const __half* src = Bt + (size_t)(nBase + row) * K + k0 + akq;
            cpasync16(Bs + row * HSTR + akq, src, 16);
        }
        cpasync_commit();
    };

    float acc[4][4][4];
#pragma unroll
    for (int mt = 0; mt < 4; mt++)
#pragma unroll
        for (int nt = 0; nt < 4; nt++)
#pragma unroll
            for (int i = 0; i < 4; i++) acc[mt][nt][i] = 0.0f;

    issue(0, 0);
    for (int i = 0; i < nk; i++) {
        if (i + 1 < nk) { issue(i + 1, (i + 1) & 1); cpasync_wait<1>(); }
        else            { cpasync_wait<0>(); }
        __syncthreads();
        const __half* As = AsB + (i & 1) * HA_TILE;
        const __half* Bs = BsB + (i & 1) * HA_TILE;
        const int k0 = i << 5;
#pragma unroll
        for (int ks = 0; ks < 2; ks++) {
            const int kk = ks * 16;
            const int kb = kk + 2 * qt;
            unsigned af[4][4], bf[4][2];
            float sc0, sh0, sc1, sh1, sc8, sh8, sc9, sh9;
            if (FUSE_BN) {
                int g = k0 + kb;
                sc0 = scS[g];     sh0 = shS[g];
                sc1 = scS[g + 1]; sh1 = shS[g + 1];
                sc8 = scS[g + 8]; sh8 = shS[g + 8];
                sc9 = scS[g + 9]; sh9 = shS[g + 9];
            }
#pragma unroll
            for (int mt = 0; mt < 4; mt++) {
                int r = warpM * 64 + mt * 16 + group;
                const __half* p0 = As + r * HSTR + kb;
                const __half* p1 = As + (r + 8) * HSTR + kb;
                if (FUSE_BN) {
                    float2 v0 = __half22float2(*(const __half2*)p0);
                    float2 v1 = __half22float2(*(const __half2*)p1);
                    float2 v2 = __half22float2(*(const __half2*)(p0 + 8));
                    float2 v3 = __half22float2(*(const __half2*)(p1 + 8));
                    af[mt][0] = h2u(__floats2half2_rn(
                        fmaxf(fmaf(v0.x, sc0, sh0), 0.f), fmaxf(fmaf(v0.y, sc1, sh1), 0.f)));
                    af[mt][1] = h2u(__floats2half2_rn(
                        fmaxf(fmaf(v1.x, sc0, sh0), 0.f), fmaxf(fmaf(v1.y, sc1, sh1), 0.f)));
                    af[mt][2] = h2u(__floats2half2_rn(
                        fmaxf(fmaf(v2.x, sc8, sh8), 0.f), fmaxf(fmaf(v2.y, sc9, sh9), 0.f)));
                    af[mt][3] = h2u(__floats2half2_rn(
                        fmaxf(fmaf(v3.x, sc8, sh8), 0.f), fmaxf(fmaf(v3.y, sc9, sh9), 0.f)));
                } else {
                    af[mt][0] = *(const unsigned*)p0;
                    af[mt][1] = *(const unsigned*)p1;
                    af[mt][2] = *(const unsigned*)(p0 + 8);
                    af[mt][3] = *(const unsigned*)(p1 + 8);
                }
            }
#pragma unroll
            for (int nt = 0; nt < 4; nt++) {
                int cb = warpN * 32 + nt * 8 + group;
                const __half* q = Bs + cb * HSTR + kb;
                bf[nt][0] = *(const unsigned*)q;
                bf[nt][1] = *(const unsigned*)(q + 8);
            }
#pragma unroll
            for (int mt = 0; mt < 4; mt++)
#pragma unroll
                for (int nt = 0; nt < 4; nt++)
                    MMA_F16(acc[mt][nt], af[mt], bf[nt]);
        }
        __syncthreads();
    }

    // epilogue: store + BN stats (on stored values)
    float cs[4][2], cq[4][2];
#pragma unroll
    for (int nt = 0; nt < 4; nt++) { cs[nt][0] = cs[nt][1] = 0.f; cq[nt][0] = cq[nt][1] = 0.f; }
#pragma unroll
    for (int mt = 0; mt < 4; mt++) {
        int r0 = mBase + warpM * 64 + mt * 16 + group;
        int r1 = r0 + 8;
#pragma unroll
        for (int nt = 0; nt < 4; nt++) {
            int cc = nBase + warpN * 32 + nt * 8 + 2 * qt;
            float x0, x1;
            if (r0 < M) {
                st2(C, (size_t)r0 * NC + cc, acc[mt][nt][0], acc[mt][nt][1], x0, x1);
                cs[nt][0] += x0; cs[nt][1] += x1;
                cq[nt][0] += x0 * x0; cq[nt][1] += x1 * x1;
            }
            if (r1 < M) {
                st2(C, (size_t)r1 * NC + cc, acc[mt][nt][2], acc[mt][nt][3], x0, x1);
                cs[nt][0] += x0; cs[nt][1] += x1;
                cq[nt][0] += x0 * x0; cq[nt][1] += x1 * x1;
            }
        }
    }
    if (sumO) {
#pragma unroll
        for (int off = 4; off < 32; off <<= 1) {
#pragma unroll
            for (int nt = 0; nt < 4; nt++) {
#pragma unroll
                for (int p = 0; p < 2; p++) {
                    cs[nt][p] += __shfl_xor_sync(0xffffffffu, cs[nt][p], off);
                    cq[nt][p] += __shfl_xor_sync(0xffffffffu, cq[nt][p], off);
                }
            }
        }
        if (group == 0) {
#pragma unroll
            for (int nt = 0; nt < 4; nt++) {
                int cc = nBase + warpN * 32 + nt * 8 + 2 * qt;
                atomicAdd(sumO + cc,     cs[nt][0]);
                atomicAdd(sumO + cc + 1, cs[nt][1]);
                atomicAdd(sqO  + cc,     cq[nt][0]);
                atomicAdd(sqO  + cc + 1, cq[nt][1]);
            }
        }
    }
}

// ---------------- combine / scatter / ein / nin (half2 vectorized) ----------------
__global__ void k_combine() {
    int c = threadIdx.x & 63;
    int eo = threadIdx.x >> 6;
    float ls0 = 0.f, ls1 = 0.f, lq0 = 0.f, lq1 = 0.f;
    const __half2* a0 = (const __half2*)s_a0;
    const __half2* a1 = (const __half2*)s_a1;
    const __half2* ew = (const __half2*)s_ew2;
    __half2* pre = (__half2*)s_pre1;
    for (int e = blockIdx.x * 2 + eo; e < NE; e += gridDim.x * 2) {
        int u = s_u[e], v = s_v[e];
        float2 a0u = __half22float2(a0[(size_t)u * 64 + c]);
        float2 a0v = __half22float2(a0[(size_t)v * 64 + c]);
        float2 a1u = __half22float2(a1[(size_t)u * 64 + c]);
        float2 a1v = __half22float2(a1[(size_t)v * 64 + c]);
        float bx = a0u.x + a0v.x, by = a0u.y + a0v.y;
        size_t r0 = (size_t)(2 * e) * 64 + c, r1 = (size_t)(2 * e + 1) * 64 + c;
        float2 e0 = __half22float2(ew[r0]);
        float2 e1 = __half22float2(ew[r1]);
        __half2 h0 = __floats2half2_rn(bx + a1u.x + e0.x, by + a1u.y + e0.y);
        __half2 h1 = __floats2half2_rn(bx + a1v.x + e1.x, by + a1v.y + e1.y);
        pre[r0] = h0; pre[r1] = h1;
        float2 q0 = __half22float2(h0), q1 = __half22float2(h1);
        ls0 += q0.x + q1.x; ls1 += q0.y + q1.y;
        lq0 += q0.x * q0.x + q1.x * q1.x; lq1 += q0.y * q0.y + q1.y * q1.y;
    }
    atomicAdd(&s_sum[2 * c],     ls0);
    atomicAdd(&s_sum[2 * c + 1], ls1);
    atomicAdd(&s_sq[2 * c],      lq0);
    atomicAdd(&s_sq[2 * c + 1],  lq1);
}

__global__ void k_scatter(const float* __restrict__ g, const float* __restrict__ b,
                          const float* __restrict__ eps12p) {
    int c = threadIdx.x & 63;
    int eo = threadIdx.x >> 6;
    float m0 = s_sum[2 * c] * (1.0f / TE), m1 = s_sum[2 * c + 1] * (1.0f / TE);
    float v0 = s_sq[2 * c] * (1.0f / TE) - m0 * m0;
    float v1 = s_sq[2 * c + 1] * (1.0f / TE) - m1 * m1;
    float sc0 = g[2 * c] * rsqrtf(v0 + 1e-5f), sc1 = g[2 * c + 1] * rsqrtf(v1 + 1e-5f);
    float sh0 = b[2 * c] - m0 * sc0, sh1 = b[2 * c + 1] - m1 * sc1;
    float e12 = 1.0f + *eps12p;
    const __half2* pre = (const __half2*)s_pre1;
    for (int e = blockIdx.x * 2 + eo; e < NE; e += gridDim.x * 2) {
        int u = s_u[e], v = s_v[e];
        size_t r0 = (size_t)(2 * e) * 64 + c, r1 = (size_t)(2 * e + 1) * 64 + c;
        float2 p0 = __half22float2(pre[r0]);
        float2 p1 = __half22float2(pre[r1]);
        float h0x = fmaxf(p0.x * sc0 + sh0, 0.f), h0y = fmaxf(p0.y * sc1 + sh1, 0.f);
        float h1x = fmaxf(p1.x * sc0 + sh0, 0.f), h1y = fmaxf(p1.y * sc1 + sh1, 0.f);
        float dsx = h0x + h1x, dsy = h0y + h1y;
        float* nu = s_nacc + (size_t)u * 128 + 2 * c;
        float* nv = s_nacc + (size_t)v * 128 + 2 * c;
        atomicAdd(nu,     e12 * h0x + dsx);
        atomicAdd(nu + 1, e12 * h0y + dsy);
        atomicAdd(nv,     e12 * h1x + dsx);
        atomicAdd(nv + 1, e12 * h1y + dsy);
    }
}

__global__ void k_nin(const float* __restrict__ nr, const float* __restrict__ eps11p) {
    float e11 = 1.0f + *eps11p;
    size_t stride = (size_t)gridDim.x * blockDim.x;
    size_t n = (size_t)NN * 64;
    const float2* nr2 = (const float2*)nr;
    const float2* ac2 = (const float2*)s_nacc;
    __half2* out = (__half2*)s_nin;
    for (size_t i = (size_t)blockIdx.x * blockDim.x + threadIdx.x; i < n; i += stride) {
        float2 a = nr2[i], b = ac2[i];
        out[i] = __floats2half2_rn(e11 * a.x + b.x, e11 * a.y + b.y);
    }
}

__global__ void k_ein(const float* __restrict__ er, const float* __restrict__ nr,
                      const float* __restrict__ eps2p) {
    int c = threadIdx.x & 63;
    int eo = threadIdx.x >> 6;
    float e2 = 1.0f + *eps2p;
    float e2h = 0.5f * e2;
    const float2* er2 = (const float2*)er;
    const float2* nr2 = (const float2*)nr;
    __half2* ein = (__half2*)s_ein;
    for (int e = blockIdx.x * 2 + eo; e < NE; e += gridDim.x * 2) {
        int u = s_u[e], v = s_v[e];
        float2 a = er2[(size_t)(2 * e) * 64 + c];
        float2 bq = er2[(size_t)(2 * e + 1) * 64 + c];
        float2 p = nr2[(size_t)u * 64 + c];
        float2 q = nr2[(size_t)v * 64 + c];
        __half2 fh = __floats2half2_rn(e2h * (a.x + bq.x) + p.x + q.x,
                                       e2h * (a.y + bq.y) + p.y + q.y);
        size_t r0 = (size_t)(2 * e) * 128 + c, r1 = (size_t)(2 * e + 1) * 128 + c;
        ein[r0] = fh;
        ein[r1] = fh;
        ein[r0 + 64] = __floats2half2_rn(e2 * a.x + p.x,  e2 * a.y + p.y);
        ein[r1 + 64] = __floats2half2_rn(e2 * bq.x + q.x, e2 * bq.y + q.y);
    }
}

// dst = relu(src*scale + shift), float4 vectorized
__global__ void k_bnapply4(const float4* __restrict__ src, float4* __restrict__ dst,
                           int rows, int col4Mask,
                           const float* __restrict__ sum, const float* __restrict__ sq,
                           const float* __restrict__ g, const float* __restrict__ b,
                           float inv) {
    size_t n = (size_t)rows * (col4Mask + 1);
    size_t stride = (size_t)gridDim.x * blockDim.x;
    for (size_t i = (size_t)blockIdx.x * blockDim.x + threadIdx.x; i < n; i += stride) {
        int c = (int)(i & (size_t)col4Mask) << 2;
        float4 v = src[i];
        float4 o;
#pragma unroll
        for (int j = 0; j < 4; j++) {
            float mean = sum[c + j] * inv;
            float var  = sq[c + j] * inv - mean * mean;
            float scv = g[c + j] * rsqrtf(var + 1e-5f);
            float shv = b[c + j] - mean * scv;
            float x = (&v.x)[j] * scv + shv;
            (&o.x)[j] = fmaxf(x, 0.f);
        }
        dst[i] = o;
    }
}

// ---------------- launch ----------------
extern "C" void kernel_launch(void* const* d_in, const int* in_sizes, int n_in,
                              void* d_out, int out_size) {
    const float* nr      = (const float*)d_in[0];
    const float* er      = (const float*)d_in[1];
    const void*  ei      = d_in[2];
    const float* lift_w1 = (const float*)d_in[3];
    const float* lift_g1 = (const float*)d_in[4];
    const float* lift_b1 = (const float*)d_in[5];
    const float* lift_w2 = (const float*)d_in[6];
    const float* lift_g2 = (const float*)d_in[7];
    const float* lift_b2 = (const float*)d_in[8];
    const float* lvl1_w  = (const float*)d_in[9];
    const float* lvl1_g  = (const float*)d_in[10];
    const float* lvl1_b  = (const float*)d_in[11];
    const float* lvl2_w1 = (const float*)d_in[12];
    const float* lvl2_g1 = (const float*)d_in[13];
    const float* lvl2_b1 = (const float*)d_in[14];
    const float* lvl2_w2 = (const float*)d_in[15];
    const float* lvl2_g2 = (const float*)d_in[16];
    const float* lvl2_b2 = (const float*)d_in[17];
    const float* eps11   = (const float*)d_in[18];
    const float* eps12   = (const float*)d_in[19];
    const float* eps2    = (const float*)d_in[20];

    float* out_node = (float*)d_out;
    float* out_edge = out_node + (size_t)NN * HH;

    __half *p_ew2, *p_a0, *p_a1, *p_nin, *p_np1, *p_ein, *p_ep1;
    __half *p_wnp1, *p_wnp2, *p_wep1, *p_wep2;
    float *p_np2, *p_ep2, *p_sum, *p_sq;
    cudaGetSymbolAddress((void**)&p_ew2, s_ew2);
    cudaGetSymbolAddress((void**)&p_a0,  s_a0);
    cudaGetSymbolAddress((void**)&p_a1,  s_a1);
    cudaGetSymbolAddress((void**)&p_nin, s_nin);
    cudaGetSymbolAddress((void**)&p_np1, s_np1);
    cudaGetSymbolAddress((void**)&p_np2, s_np2);
    cudaGetSymbolAddress((void**)&p_ein, s_ein);
    cudaGetSymbolAddress((void**)&p_ep1, s_ep1);
    cudaGetSymbolAddress((void**)&p_ep2, s_ep2);
    cudaGetSymbolAddress((void**)&p_sum, s_sum);
    cudaGetSymbolAddress((void**)&p_sq,  s_sq);
    cudaGetSymbolAddress((void**)&p_wnp1, w_np1h);
    cudaGetSymbolAddress((void**)&p_wnp2, w_np2h);
    cudaGetSymbolAddress((void**)&p_wep1, w_ep1h);
    cudaGetSymbolAddress((void**)&p_wep2, w_ep2h);

    static int smem_set = 0;
    if (!smem_set) {
        cudaFuncSetAttribute((const void*)k_mma_f,
                             cudaFuncAttributeMaxDynamicSharedMemorySize, SMEM_BYTES_F);
        cudaFuncSetAttribute((const void*)k_mma_h<__half, false, true>,
                             cudaFuncAttributeMaxDynamicSharedMemorySize, SMEM_BYTES_H);
        cudaFuncSetAttribute((const void*)k_mma_h<float, true, false>,
                             cudaFuncAttributeMaxDynamicSharedMemorySize, SMEM_BYTES_H);
        smem_set = 1;
    }

    const int GN  = (NN + 127) / 128;  // 157
    const int GTE = TE / 128;          // 2500

    k_zero<<<2048, 256>>>();
    k_detect<<<1, 32>>>((const int*)ei);
    k_decode<<<(NE + 255) / 256, 256>>>(ei);
    k_wprep<<<256, 256>>>(lvl2_w1, lvl2_w2, lift_w1, lift_w2);

    // lvl1 pieces (tf32, float A): EW2, A0, A1 (C=half)
    k_mma_f<<<dim3(GTE, 1), 256, SMEM_BYTES_F>>>(er, lvl1_w + 256 * 128, p_ew2, TE, 128, 128);
    k_mma_f<<<dim3(GN, 1),  256, SMEM_BYTES_F>>>(nr, lvl1_w,             p_a0,  NN, 128, 128);
    k_mma_f<<<dim3(GN, 1),  256, SMEM_BYTES_F>>>(nr, lvl1_w + 128 * 128, p_a1,  NN, 128, 128);

    k_combine<<<2048, 128>>>();                             // stats slot 0, pre1 half
    k_scatter<<<2048, 128>>>(lvl1_g, lvl1_b, eps12);        // BN+ReLU + fused scatter

    // node path (fp16 HMMA): np1(half)+stats(slot1); np2(fp32) BN-fused, stats(slot2)
    k_nin<<<2048, 256>>>(nr, eps11);
    k_mma_h<__half, false, true><<<dim3(2, GN), 256, SMEM_BYTES_H>>>(
        p_nin, p_wnp1, p_np1, NN, 128, 256,
        p_sum + 256, p_sq + 256, nullptr, nullptr, nullptr, nullptr, 0.f);
    k_mma_h<float, true, false><<<dim3(GN, 1), 256, SMEM_BYTES_H>>>(
        p_np1, p_wnp2, p_np2, NN, 256, 128,
        p_sum + 512, p_sq + 512,
        p_sum + 256, p_sq + 256, lvl2_g1, lvl2_b1, 1.0f / NN);
    k_bnapply4<<<2048, 256>>>((const float4*)p_np2, (float4*)out_node, NN, 31,
                              p_sum + 512, p_sq + 512, lvl2_g2, lvl2_b2, 1.0f / NN);

    // edge path (fp16 HMMA): ein half; ep1(half)+stats(slot3); ep2(fp32) BN-fused, stats(slot4)
    k_ein<<<2048, 128>>>(er, nr, eps2);
    k_mma_h<__half, false, true><<<dim3(2, GTE), 256, SMEM_BYTES_H>>>(
        p_ein, p_wep1, p_ep1, TE, 256, 256,
        p_sum + 768, p_sq + 768, nullptr, nullptr, nullptr, nullptr, 0.f);
    k_mma_h<float, true, false><<<dim3(GTE, 1), 256, SMEM_BYTES_H>>>(
        p_ep1, p_wep2, p_ep2, TE, 256, 128,
        p_sum + 1024, p_sq + 1024,
        p_sum + 768, p_sq + 768, lift_g1, lift_b1, 1.0f / TE);
    k_bnapply4<<<4096, 256>>>((const float4*)p_ep2, (float4*)out_edge, TE, 31,
                              p_sum + 1024, p_sq + 1024, lift_g2, lift_b2, 1.0f / TE);
}

// round 10
// speedup vs baseline: 1.3398x; 1.0621x over previous
#include <cuda_runtime.h>
#include <cuda_fp16.h>
#include <cstring>

#define NN 20000      // nodes
#define NE 160000     // edges
#define TE 320000     // 2E edge-rows
#define HH 128

// ---------------- scratch (static __device__, no allocs) ----------------
__device__ __align__(128) __half s_ew2 [(size_t)TE * 128];   // er @ W2
__device__ __align__(128) __half s_a0  [(size_t)NN * 128];   // nr @ W0
__device__ __align__(128) __half s_a1  [(size_t)NN * 128];   // nr @ W1
__device__ __align__(128) __half s_pre1[(size_t)TE * 128];   // lvl1 pre-act
__device__ __align__(128) float  s_nacc[(size_t)NN * 128];   // node scatter accum
__device__ __align__(128) __half s_nin [(size_t)NN * 128];
__device__ __align__(128) __half s_np1 [(size_t)NN * 256];
__device__ __align__(128) float  s_np2 [(size_t)NN * 128];   // final pre-act: fp32
__device__ __align__(128) __half s_ein [(size_t)TE * 256];
__device__ __align__(128) __half s_ep1 [(size_t)TE * 256];
__device__ __align__(128) float  s_ep2 [(size_t)TE * 128];   // final pre-act: fp32
// fp16 weights, pre-transposed to n-major [N][K]
__device__ __align__(128) __half w_np1h[256 * 128];
__device__ __align__(128) __half w_np2h[128 * 256];
__device__ __align__(128) __half w_ep1h[256 * 256];
__device__ __align__(128) __half w_ep2h[128 * 256];
__device__ float s_sum[5 * 256];
__device__ float s_sq [5 * 256];
__device__ int   s_u[NE];
__device__ int   s_v[NE];
__device__ int   g_is64;

// ---------------- helpers ----------------
__device__ __forceinline__ unsigned h2u(__half2 h) {
    unsigned u;
    memcpy(&u, &h, 4);
    return u;
}

__global__ void k_zero() {
    size_t stride = (size_t)gridDim.x * blockDim.x;
    size_t i0 = (size_t)blockIdx.x * blockDim.x + threadIdx.x;
    size_t n = (size_t)NN * 128;
    for (size_t i = i0; i < n; i += stride) s_nacc[i] = 0.0f;
    if (i0 < 5 * 256) { s_sum[i0] = 0.0f; s_sq[i0] = 0.0f; }
}

__global__ void k_detect(const int* __restrict__ ei32) {
    if (threadIdx.x == 0 && blockIdx.x == 0) {
        int nz = 0;
        for (int i = 0; i < 256; i++) nz |= ei32[2 * i + 1];
        g_is64 = (nz == 0) ? 1 : 0;
    }
}

__global__ void k_decode(const void* __restrict__ ei) {
    int e = blockIdx.x * blockDim.x + threadIdx.x;
    if (e >= NE) return;
    if (g_is64) {
        const long long* p = (const long long*)ei;
        s_u[e] = (int)p[e];
        s_v[e] = (int)p[NE + e];
    } else {
        const int* p = (const int*)ei;
        s_u[e] = p[e];
        s_v[e] = p[NE + e];
    }
}

// convert + transpose weights to fp16 n-major
__global__ void k_wprep(const float* __restrict__ w_np1, const float* __restrict__ w_np2,
                        const float* __restrict__ w_ep1, const float* __restrict__ w_ep2) {
    int i = blockIdx.x * blockDim.x + threadIdx.x;   // 65536 threads
    if (i < 256 * 128) {            // np1: [128][256] -> [256][128]
        int n = i >> 7, k = i & 127;
        w_np1h[i] = __float2half_rn(w_np1[k * 256 + n]);
    }
    if (i < 128 * 256) {            // np2: [256][128] -> [128][256]
        int n = i >> 8, k = i & 255;
        w_np2h[i] = __float2half_rn(w_np2[k * 128 + n]);
    }
    if (i < 256 * 256) {            // ep1: [256][256] -> transposed
        int n = i >> 8, k = i & 255;
        w_ep1h[i] = __float2half_rn(w_ep1[k * 256 + n]);
    }
    if (i < 128 * 256) {            // ep2: [256][128] -> [128][256]
        int n = i >> 8, k = i & 255;
        w_ep2h[i] = __float2half_rn(w_ep2[k * 128 + n]);
    }
}

__device__ __forceinline__ unsigned f2tf(float x) {
    unsigned r;
    asm("cvt.rna.tf32.f32 %0, %1;" : "=r"(r) : "f"(x));
    return r;
}

__device__ __forceinline__ void cpasync16(void* smem_ptr, const void* gptr, int src_bytes) {
    unsigned saddr = (unsigned)__cvta_generic_to_shared(smem_ptr);
    asm volatile("cp.async.cg.shared.global [%0], [%1], 16, %2;"
                 :: "r"(saddr), "l"(gptr), "r"(src_bytes));
}
__device__ __forceinline__ void cpasync_commit() {
    asm volatile("cp.async.commit_group;");
}
template <int N>
__device__ __forceinline__ void cpasync_wait() {
    asm volatile("cp.async.wait_group %0;" :: "n"(N));
}

#define MMA_TF32(d, Af, Bf)                                                     \
    asm volatile(                                                               \
        "mma.sync.aligned.m16n8k8.row.col.f32.tf32.tf32.f32 "                   \
        "{%0,%1,%2,%3},{%4,%5,%6,%7},{%8,%9},{%0,%1,%2,%3};"                    \
        : "+f"(d[0]), "+f"(d[1]), "+f"(d[2]), "+f"(d[3])                        \
        : "r"(Af[0]), "r"(Af[1]), "r"(Af[2]), "r"(Af[3]),                       \
          "r"(Bf[0]), "r"(Bf[1]))

#define MMA_F16(d, Af, Bf)                                                      \
    asm volatile(                                                               \
        "mma.sync.aligned.m16n8k16.row.col.f32.f16.f16.f32 "                    \
        "{%0,%1,%2,%3},{%4,%5,%6,%7},{%8,%9},{%0,%1,%2,%3};"                    \
        : "+f"(d[0]), "+f"(d[1]), "+f"(d[2]), "+f"(d[3])                        \
        : "r"(Af[0]), "r"(Af[1]), "r"(Af[2]), "r"(Af[3]),                       \
          "r"(Bf[0]), "r"(Bf[1]))

// typed stores (stats on stored/rounded values)
__device__ __forceinline__ void st2(float* C, size_t off, float c0, float c1,
                                    float& r0, float& r1) {
    *(float2*)(C + off) = make_float2(c0, c1);
    r0 = c0; r1 = c1;
}
__device__ __forceinline__ void st2(__half* C, size_t off, float c0, float c1,
                                    float& r0, float& r1) {
    __half2 h = __floats2half2_rn(c0, c1);
    *(__half2*)(C + off) = h;
    r0 = __low2float(h); r1 = __high2float(h);
}

// ================= TF32 GEMM (float A, fp32 k-major B, half C) ==================
#define BS_STRIDE 136
#define BS_TILE (32 * BS_STRIDE)
#define AF_STRIDE 36
#define SMEM_BYTES_F (2 * 128 * AF_STRIDE * 4 + 2 * BS_TILE * 4 + 2048)   // 73728

__global__ __launch_bounds__(256, 2) void k_mma_f(
    const float* __restrict__ A, const float* __restrict__ Bm,
    __half* __restrict__ C, int M, int K, int NC)
{
    extern __shared__ float dsm[];
    float* AsB = dsm;
    float* BsB = dsm + 2 * 128 * AF_STRIDE;

    const int tid = threadIdx.x;
    const int lane = tid & 31, warp = tid >> 5;
    const int group = lane >> 2, qt = lane & 3;
    const int warpM = warp & 1, warpN = warp >> 1;
    const int mBase = blockIdx.x * 128, nBase = blockIdx.y * 128;
    const int nk = K >> 5;

    const int arow = tid >> 3, akq = (tid & 7) << 2;
    const int bkr = tid >> 5, bnc = (tid & 31) << 2;

    auto issue = [&](int i, int b) {
        const int k0 = i << 5;
        float* As = AsB + b * 128 * AF_STRIDE;
        float* Bs = BsB + b * BS_TILE;
#pragma unroll
        for (int it = 0; it < 4; it++) {
            int row = arow + it * 32;
            int gm = mBase + row;
            const float* src = A + (size_t)(gm < M ? gm : 0) * K + k0 + akq;
            cpasync16(As + row * AF_STRIDE + akq, src, gm < M ? 16 : 0);
        }
#pragma unroll
        for (int it = 0; it < 4; it++) {
            int kr = bkr + it * 8;
            const float* src = Bm + (size_t)(k0 + kr) * NC + nBase + bnc;
            cpasync16(Bs + kr * BS_STRIDE + bnc, src, 16);
        }
        cpasync_commit();
    };

    float acc[4][4][4];
#pragma unroll
    for (int mt = 0; mt < 4; mt++)
#pragma unroll
        for (int nt = 0; nt < 4; nt++)
#pragma unroll
            for (int i = 0; i < 4; i++) acc[mt][nt][i] = 0.0f;

    issue(0, 0);
    for (int i = 0; i < nk; i++) {
        if (i + 1 < nk) { issue(i + 1, (i + 1) & 1); cpasync_wait<1>(); }
        else            { cpasync_wait<0>(); }
        __syncthreads();
        const float* As = AsB + (i & 1) * 128 * AF_STRIDE;
        const float* Bs = BsB + (i & 1) * BS_TILE;
#pragma unroll
        for (int ks = 0; ks < 4; ks++) {
            const int kc = ks * 8 + qt;
            unsigned af[4][4], bf[4][2];
#pragma unroll
            for (int mt = 0; mt < 4; mt++) {
                int r = warpM * 64 + mt * 16 + group;
                af[mt][0] = f2tf(As[r * AF_STRIDE + kc]);
                af[mt][1] = f2tf(As[(r + 8) * AF_STRIDE + kc]);
                af[mt][2] = f2tf(As[r * AF_STRIDE + kc + 4]);
                af[mt][3] = f2tf(As[(r + 8) * AF_STRIDE + kc + 4]);
            }
#pragma unroll
            for (int nt = 0; nt < 4; nt++) {
                int cb = warpN * 32 + nt * 8 + group;
                bf[nt][0] = f2tf(Bs[kc * BS_STRIDE + cb]);
                bf[nt][1] = f2tf(Bs[(kc + 4) * BS_STRIDE + cb]);
            }
#pragma unroll
            for (int mt = 0; mt < 4; mt++)
#pragma unroll
                for (int nt = 0; nt < 4; nt++)
                    MMA_TF32(acc[mt][nt], af[mt], bf[nt]);
        }
        __syncthreads();
    }

#pragma unroll
    for (int mt = 0; mt < 4; mt++) {
        int r0 = mBase + warpM * 64 + mt * 16 + group;
        int r1 = r0 + 8;
#pragma unroll
        for (int nt = 0; nt < 4; nt++) {
            int cc = nBase + warpN * 32 + nt * 8 + 2 * qt;
            float x0, x1;
            if (r0 < M) st2(C, (size_t)r0 * NC + cc, acc[mt][nt][0], acc[mt][nt][1], x0, x1);
            if (r1 < M) st2(C, (size_t)r1 * NC + cc, acc[mt][nt][2], acc[mt][nt][3], x0, x1);
        }
    }
}

// ================= FP16 HMMA GEMM (half A [M][K], half B n-major [NC][K]) ==========
#define HSTR 40
#define HA_TILE (128 * HSTR)  // halfs per buffer (A or B)
#define SMEM_BYTES_H (4 * HA_TILE * 2 + 2048)   // 2 A-bufs + 2 B-bufs + BN = 43008

template <typename TC, bool FUSE_BN, bool SWAP>
__global__ __launch_bounds__(256, 2) void k_mma_h(
    const __half* __restrict__ A, const __half* __restrict__ Bt,
    TC* __restrict__ C, int M, int K, int NC,
    float* __restrict__ sumO, float* __restrict__ sqO,
    const float* __restrict__ aSum, const float* __restrict__ aSq,
    const float* __restrict__ aG, const float* __restrict__ aBt, float aInv)
{
    extern __shared__ char dsmRaw[];
    __half* AsB = (__half*)dsmRaw;
    __half* BsB = (__half*)(dsmRaw + 2 * HA_TILE * 2);
    float* scS = (float*)(dsmRaw + 4 * HA_TILE * 2);
    float* shS = scS + 256;

    const int tid = threadIdx.x;
    const int lane = tid & 31, warp = tid >> 5;
    const int group = lane >> 2, qt = lane & 3;
    const int warpM = warp & 1, warpN = warp >> 1;
    const int mBase = (SWAP ? blockIdx.y : blockIdx.x) * 128;
    const int nBase = (SWAP ? blockIdx.x : blockIdx.y) * 128;
    const int nk = K >> 5;

    if (FUSE_BN) {
        if (tid < K) {
            float mean = aSum[tid] * aInv;
            float var  = aSq[tid] * aInv - mean * mean;
            float s = aG[tid] * rsqrtf(var + 1e-5f);
            scS[tid] = s; shS[tid] = aBt[tid] - mean * s;
        }
        __syncthreads();
    }

    const int arow = tid >> 2, akq = (tid & 3) << 3;  // halfs: TPR=4, RPI=64

    auto issue = [&](int i, int b) {
        const int k0 = i << 5;
        __half* As = AsB + b * HA_TILE;
        __half* Bs = BsB + b * HA_TILE;
#pragma unroll
        for (int it = 0; it < 2; it++) {
            int row = arow + it * 64;
            int gm = mBase + row;
            const __half* src = A + (size_t)(gm < M ? gm : 0) * K + k0 + akq;
            cpasync16(As + row * HSTR + akq, src, gm < M ? 16 : 0);
        }
#pragma unroll
        for (int it = 0; it < 2; it++) {
            int row = arow + it * 64;
            const __half* src = Bt + (size_t)(nBase + row) * K + k0 + akq;
            cpasync16(Bs + row * HSTR + akq, src, 16);
        }
        cpasync_commit();
    };

    float acc[4][4][4];
#pragma unroll
    for (int mt = 0; mt < 4; mt++)
#pragma unroll
        for (int nt = 0; nt < 4; nt++)
#pragma unroll
            for (int i = 0; i < 4; i++) acc[mt][nt][i] = 0.0f;

    issue(0, 0);
    for (int i = 0; i < nk; i++) {
        if (i + 1 < nk) { issue(i + 1, (i + 1) & 1); cpasync_wait<1>(); }
        else            { cpasync_wait<0>(); }
        __syncthreads();
        const __half* As = AsB + (i & 1) * HA_TILE;
        const __half* Bs = BsB + (i & 1) * HA_TILE;
        const int k0 = i << 5;
#pragma unroll
        for (int ks = 0; ks < 2; ks++) {
            const int kk = ks * 16;
            const int kb = kk + 2 * qt;
            unsigned af[4][4], bf[4][2];
            float sc0, sh0, sc1, sh1, sc8, sh8, sc9, sh9;
            if (FUSE_BN) {
                int g = k0 + kb;
                sc0 = scS[g];     sh0 = shS[g];
                sc1 = scS[g + 1]; sh1 = shS[g + 1];
                sc8 = scS[g + 8]; sh8 = shS[g + 8];
                sc9 = scS[g + 9]; sh9 = shS[g + 9];
            }
#pragma unroll
            for (int mt = 0; mt < 4; mt++) {
                int r = warpM * 64 + mt * 16 + group;
                const __half* p0 = As + r * HSTR + kb;
                const __half* p1 = As + (r + 8) * HSTR + kb;
                if (FUSE_BN) {
                    float2 v0 = __half22float2(*(const __half2*)p0);
                    float2 v1 = __half22float2(*(const __half2*)p1);
                    float2 v2 = __half22float2(*(const __half2*)(p0 + 8));
                    float2 v3 = __half22float2(*(const __half2*)(p1 + 8));
                    af[mt][0] = h2u(__floats2half2_rn(
                        fmaxf(fmaf(v0.x, sc0, sh0), 0.f), fmaxf(fmaf(v0.y, sc1, sh1), 0.f)));
                    af[mt][1] = h2u(__floats2half2_rn(
                        fmaxf(fmaf(v1.x, sc0, sh0), 0.f), fmaxf(fmaf(v1.y, sc1, sh1), 0.f)));
                    af[mt][2] = h2u(__floats2half2_rn(
                        fmaxf(fmaf(v2.x, sc8, sh8), 0.f), fmaxf(fmaf(v2.y, sc9, sh9), 0.f)));
                    af[mt][3] = h2u(__floats2half2_rn(
                        fmaxf(fmaf(v3.x, sc8, sh8), 0.f), fmaxf(fmaf(v3.y, sc9, sh9), 0.f)));
                } else {
                    af[mt][0] = *(const unsigned*)p0;
                    af[mt][1] = *(const unsigned*)p1;
                    af[mt][2] = *(const unsigned*)(p0 + 8);
                    af[mt][3] = *(const unsigned*)(p1 + 8);
                }
            }
#pragma unroll
            for (int nt = 0; nt < 4; nt++) {
                int cb = warpN * 32 + nt * 8 + group;
                const __half* q = Bs + cb * HSTR + kb;
                bf[nt][0] = *(const unsigned*)q;
                bf[nt][1] = *(const unsigned*)(q + 8);
            }
#pragma unroll
            for (int mt = 0; mt < 4; mt++)
#pragma unroll
                for (int nt = 0; nt < 4; nt++)
                    MMA_F16(acc[mt][nt], af[mt], bf[nt]);
        }
        __syncthreads();
    }

    // epilogue: store + BN stats (on stored values)
    float cs[4][2], cq[4][2];
#pragma unroll
    for (int nt = 0; nt < 4; nt++) { cs[nt][0] = cs[nt][1] = 0.f; cq[nt][0] = cq[nt][1] = 0.f; }
#pragma unroll
    for (int mt = 0; mt < 4; mt++) {
        int r0 = mBase + warpM * 64 + mt * 16 + group;
        int r1 = r0 + 8;
#pragma unroll
        for (int nt = 0; nt < 4; nt++) {
            int cc = nBase + warpN * 32 + nt * 8 + 2 * qt;
            float x0, x1;
            if (r0 < M) {
                st2(C, (size_t)r0 * NC + cc, acc[mt][nt][0], acc[mt][nt][1], x0, x1);
                cs[nt][0] += x0; cs[nt][1] += x1;
                cq[nt][0] += x0 * x0; cq[nt][1] += x1 * x1;
            }
            if (r1 < M) {
                st2(C, (size_t)r1 * NC + cc, acc[mt][nt][2], acc[mt][nt][3], x0, x1);
                cs[nt][0] += x0; cs[nt][1] += x1;
                cq[nt][0] += x0 * x0; cq[nt][1] += x1 * x1;
            }
        }
    }
    if (sumO) {
#pragma unroll
        for (int off = 4; off < 32; off <<= 1) {
#pragma unroll
            for (int nt = 0; nt < 4; nt++) {
#pragma unroll
                for (int p = 0; p < 2; p++) {
                    cs[nt][p] += __shfl_xor_sync(0xffffffffu, cs[nt][p], off);
                    cq[nt][p] += __shfl_xor_sync(0xffffffffu, cq[nt][p], off);
                }
            }
        }
        if (group == 0) {
#pragma unroll
            for (int nt = 0; nt < 4; nt++) {
                int cc = nBase + warpN * 32 + nt * 8 + 2 * qt;
                atomicAdd(sumO + cc,     cs[nt][0]);
                atomicAdd(sumO + cc + 1, cs[nt][1]);
                atomicAdd(sqO  + cc,     cq[nt][0]);
                atomicAdd(sqO  + cc + 1, cq[nt][1]);
            }
        }
    }
}

// ---------------- combine / scatter / ein / nin (half2 vectorized) ----------------
__global__ void k_combine() {
    int c = threadIdx.x & 63;
    int eo = threadIdx.x >> 6;
    float ls0 = 0.f, ls1 = 0.f, lq0 = 0.f, lq1 = 0.f;
    const __half2* a0 = (const __half2*)s_a0;
    const __half2* a1 = (const __half2*)s_a1;
    const __half2* ew = (const __half2*)s_ew2;
    __half2* pre = (__half2*)s_pre1;
    for (int e = blockIdx.x * 2 + eo; e < NE; e += gridDim.x * 2) {
        int u = s_u[e], v = s_v[e];
        float2 a0u = __half22float2(a0[(size_t)u * 64 + c]);
        float2 a0v = __half22float2(a0[(size_t)v * 64 + c]);
        float2 a1u = __half22float2(a1[(size_t)u * 64 + c]);
        float2 a1v = __half22float2(a1[(size_t)v * 64 + c]);
        float bx = a0u.x + a0v.x, by = a0u.y + a0v.y;
        size_t r0 = (size_t)(2 * e) * 64 + c, r1 = (size_t)(2 * e + 1) * 64 + c;
        float2 e0 = __half22float2(ew[r0]);
        float2 e1 = __half22float2(ew[r1]);
        __half2 h0 = __floats2half2_rn(bx + a1u.x + e0.x, by + a1u.y + e0.y);
        __half2 h1 = __floats2half2_rn(bx + a1v.x + e1.x, by + a1v.y + e1.y);
        pre[r0] = h0; pre[r1] = h1;
        float2 q0 = __half22float2(h0), q1 = __half22float2(h1);
        ls0 += q0.x + q1.x; ls1 += q0.y + q1.y;
        lq0 += q0.x * q0.x + q1.x * q1.x; lq1 += q0.y * q0.y + q1.y * q1.y;
    }
    atomicAdd(&s_sum[2 * c],     ls0);
    atomicAdd(&s_sum[2 * c + 1], ls1);
    atomicAdd(&s_sq[2 * c],      lq0);
    atomicAdd(&s_sq[2 * c + 1],  lq1);
}

__global__ void k_scatter(const float* __restrict__ g, const float* __restrict__ b,
                          const float* __restrict__ eps12p) {
    int c = threadIdx.x & 63;
    int eo = threadIdx.x >> 6;
    float m0 = s_sum[2 * c] * (1.0f / TE), m1 = s_sum[2 * c + 1] * (1.0f / TE);
    float v0 = s_sq[2 * c] * (1.0f / TE) - m0 * m0;
    float v1 = s_sq[2 * c + 1] * (1.0f / TE) - m1 * m1;
    float sc0 = g[2 * c] * rsqrtf(v0 + 1e-5f), sc1 = g[2 * c + 1] * rsqrtf(v1 + 1e-5f);
    float sh0 = b[2 * c] - m0 * sc0, sh1 = b[2 * c + 1] - m1 * sc1;
    float e12 = 1.0f + *eps12p;
    const __half2* pre = (const __half2*)s_pre1;
    for (int e = blockIdx.x * 2 + eo; e < NE; e += gridDim.x * 2) {
        int u = s_u[e], v = s_v[e];
        size_t r0 = (size_t)(2 * e) * 64 + c, r1 = (size_t)(2 * e + 1) * 64 + c;
        float2 p0 = __half22float2(pre[r0]);
        float2 p1 = __half22float2(pre[r1]);
        float h0x = fmaxf(p0.x * sc0 + sh0, 0.f), h0y = fmaxf(p0.y * sc1 + sh1, 0.f);
        float h1x = fmaxf(p1.x * sc0 + sh0, 0.f), h1y = fmaxf(p1.y * sc1 + sh1, 0.f);
        float dsx = h0x + h1x, dsy = h0y + h1y;
        float* nu = s_nacc + (size_t)u * 128 + 2 * c;
        float* nv = s_nacc + (size_t)v * 128 + 2 * c;
        atomicAdd(nu,     e12 * h0x + dsx);
        atomicAdd(nu + 1, e12 * h0y + dsy);
        atomicAdd(nv,     e12 * h1x + dsx);
        atomicAdd(nv + 1, e12 * h1y + dsy);
    }
}

__global__ void k_nin(const float* __restrict__ nr, const float* __restrict__ eps11p) {
    float e11 = 1.0f + *eps11p;
    size_t stride = (size_t)gridDim.x * blockDim.x;
    size_t n = (size_t)NN * 64;
    const float2* nr2 = (const float2*)nr;
    const float2* ac2 = (const float2*)s_nacc;
    __half2* out = (__half2*)s_nin;
    for (size_t i = (size_t)blockIdx.x * blockDim.x + threadIdx.x; i < n; i += stride) {
        float2 a = nr2[i], b = ac2[i];
        out[i] = __floats2half2_rn(e11 * a.x + b.x, e11 * a.y + b.y);
    }
}

__global__ void k_ein(const float* __restrict__ er, const float* __restrict__ nr,
                      const float* __restrict__ eps2p) {
    int c = threadIdx.x & 63;
    int eo = threadIdx.x >> 6;
    float e2 = 1.0f + *eps2p;
    float e2h = 0.5f * e2;
    const float2* er2 = (const float2*)er;
    const float2* nr2 = (const float2*)nr;
    __half2* ein = (__half2*)s_ein;
    for (int e = blockIdx.x * 2 + eo; e < NE; e += gridDim.x * 2) {
        int u = s_u[e], v = s_v[e];
        float2 a = er2[(size_t)(2 * e) * 64 + c];
        float2 bq = er2[(size_t)(2 * e + 1) * 64 + c];
        float2 p = nr2[(size_t)u * 64 + c];
        float2 q = nr2[(size_t)v * 64 + c];
        __half2 fh = __floats2half2_rn(e2h * (a.x + bq.x) + p.x + q.x,
                                       e2h * (a.y + bq.y) + p.y + q.y);
        size_t r0 = (size_t)(2 * e) * 128 + c, r1 = (size_t)(2 * e + 1) * 128 + c;
        ein[r0] = fh;
        ein[r1] = fh;
        ein[r0 + 64] = __floats2half2_rn(e2 * a.x + p.x,  e2 * a.y + p.y);
        ein[r1 + 64] = __floats2half2_rn(e2 * bq.x + q.x, e2 * bq.y + q.y);
    }
}

// dst = relu(src*scale + shift), float4 vectorized
__global__ void k_bnapply4(const float4* __restrict__ src, float4* __restrict__ dst,
                           int rows, int col4Mask,
                           const float* __restrict__ sum, const float* __restrict__ sq,
                           const float* __restrict__ g, const float* __restrict__ b,
                           float inv) {
    size_t n = (size_t)rows * (col4Mask + 1);
    size_t stride = (size_t)gridDim.x * blockDim.x;
    for (size_t i = (size_t)blockIdx.x * blockDim.x + threadIdx.x; i < n; i += stride) {
        int c = (int)(i & (size_t)col4Mask) << 2;
        float4 v = src[i];
        float4 o;
#pragma unroll
        for (int j = 0; j < 4; j++) {
            float mean = sum[c + j] * inv;
            float var  = sq[c + j] * inv - mean * mean;
            float scv = g[c + j] * rsqrtf(var + 1e-5f);
            float shv = b[c + j] - mean * scv;
            float x = (&v.x)[j] * scv + shv;
            (&o.x)[j] = fmaxf(x, 0.f);
        }
        dst[i] = o;
    }
}

// ---------------- launch ----------------
extern "C" void kernel_launch(void* const* d_in, const int* in_sizes, int n_in,
                              void* d_out, int out_size) {
    const float* nr      = (const float*)d_in[0];
    const float* er      = (const float*)d_in[1];
    const void*  ei      = d_in[2];
    const float* lift_w1 = (const float*)d_in[3];
    const float* lift_g1 = (const float*)d_in[4];
    const float* lift_b1 = (const float*)d_in[5];
    const float* lift_w2 = (const float*)d_in[6];
    const float* lift_g2 = (const float*)d_in[7];
    const float* lift_b2 = (const float*)d_in[8];
    const float* lvl1_w  = (const float*)d_in[9];
    const float* lvl1_g  = (const float*)d_in[10];
    const float* lvl1_b  = (const float*)d_in[11];
    const float* lvl2_w1 = (const float*)d_in[12];
    const float* lvl2_g1 = (const float*)d_in[13];
    const float* lvl2_b1 = (const float*)d_in[14];
    const float* lvl2_w2 = (const float*)d_in[15];
    const float* lvl2_g2 = (const float*)d_in[16];
    const float* lvl2_b2 = (const float*)d_in[17];
    const float* eps11   = (const float*)d_in[18];
    const float* eps12   = (const float*)d_in[19];
    const float* eps2    = (const float*)d_in[20];

    float* out_node = (float*)d_out;
    float* out_edge = out_node + (size_t)NN * HH;

    __half *p_ew2, *p_a0, *p_a1, *p_nin, *p_np1, *p_ein, *p_ep1;
    __half *p_wnp1, *p_wnp2, *p_wep1, *p_wep2;
    float *p_np2, *p_ep2, *p_sum, *p_sq;
    cudaGetSymbolAddress((void**)&p_ew2, s_ew2);
    cudaGetSymbolAddress((void**)&p_a0,  s_a0);
    cudaGetSymbolAddress((void**)&p_a1,  s_a1);
    cudaGetSymbolAddress((void**)&p_nin, s_nin);
    cudaGetSymbolAddress((void**)&p_np1, s_np1);
    cudaGetSymbolAddress((void**)&p_np2, s_np2);
    cudaGetSymbolAddress((void**)&p_ein, s_ein);
    cudaGetSymbolAddress((void**)&p_ep1, s_ep1);
    cudaGetSymbolAddress((void**)&p_ep2, s_ep2);
    cudaGetSymbolAddress((void**)&p_sum, s_sum);
    cudaGetSymbolAddress((void**)&p_sq,  s_sq);
    cudaGetSymbolAddress((void**)&p_wnp1, w_np1h);
    cudaGetSymbolAddress((void**)&p_wnp2, w_np2h);
    cudaGetSymbolAddress((void**)&p_wep1, w_ep1h);
    cudaGetSymbolAddress((void**)&p_wep2, w_ep2h);

    static cudaStream_t s_edge = nullptr;
    static cudaEvent_t ev_fork = nullptr, ev_edge = nullptr;
    static int smem_set = 0;
    if (!smem_set) {
        cudaFuncSetAttribute((const void*)k_mma_f,
                             cudaFuncAttributeMaxDynamicSharedMemorySize, SMEM_BYTES_F);
        cudaFuncSetAttribute((const void*)k_mma_h<__half, false, true>,
                             cudaFuncAttributeMaxDynamicSharedMemorySize, SMEM_BYTES_H);
        cudaFuncSetAttribute((const void*)k_mma_h<float, true, false>,
                             cudaFuncAttributeMaxDynamicSharedMemorySize, SMEM_BYTES_H);
        cudaStreamCreateWithFlags(&s_edge, cudaStreamNonBlocking);
        cudaEventCreateWithFlags(&ev_fork, cudaEventDisableTiming);
        cudaEventCreateWithFlags(&ev_edge, cudaEventDisableTiming);
        smem_set = 1;
    }

    const int GN  = (NN + 127) / 128;  // 157
    const int GTE = TE / 128;          // 2500

    // -------- pre-fork (stream 0): shared prerequisites --------
    k_zero<<<2048, 256>>>();
    k_detect<<<1, 32>>>((const int*)ei);
    k_decode<<<(NE + 255) / 256, 256>>>(ei);
    k_wprep<<<256, 256>>>(lvl2_w1, lvl2_w2, lift_w1, lift_w2);
    cudaEventRecord(ev_fork, 0);

    // -------- edge chain (s_edge): independent of the lvl1/node path --------
    cudaStreamWaitEvent(s_edge, ev_fork, 0);
    k_ein<<<2048, 128, 0, s_edge>>>(er, nr, eps2);
    k_mma_h<__half, false, true><<<dim3(2, GTE), 256, SMEM_BYTES_H, s_edge>>>(
        p_ein, p_wep1, p_ep1, TE, 256, 256,
        p_sum + 768, p_sq + 768, nullptr, nullptr, nullptr, nullptr, 0.f);
    k_mma_h<float, true, false><<<dim3(GTE, 1), 256, SMEM_BYTES_H, s_edge>>>(
        p_ep1, p_wep2, p_ep2, TE, 256, 128,
        p_sum + 1024, p_sq + 1024,
        p_sum + 768, p_sq + 768, lift_g1, lift_b1, 1.0f / TE);
    k_bnapply4<<<4096, 256, 0, s_edge>>>((const float4*)p_ep2, (float4*)out_edge, TE, 31,
                              p_sum + 1024, p_sq + 1024, lift_g2, lift_b2, 1.0f / TE);
    cudaEventRecord(ev_edge, s_edge);

    // -------- node chain (stream 0) --------
    k_mma_f<<<dim3(GTE, 1), 256, SMEM_BYTES_F>>>(er, lvl1_w + 256 * 128, p_ew2, TE, 128, 128);
    k_mma_f<<<dim3(GN, 1),  256, SMEM_BYTES_F>>>(nr, lvl1_w,             p_a0,  NN, 128, 128);
    k_mma_f<<<dim3(GN, 1),  256, SMEM_BYTES_F>>>(nr, lvl1_w + 128 * 128, p_a1,  NN, 128, 128);

    k_combine<<<2048, 128>>>();                             // stats slot 0, pre1 half
    k_scatter<<<2048, 128>>>(lvl1_g, lvl1_b, eps12);        // BN+ReLU + fused scatter

    k_nin<<<2048, 256>>>(nr, eps11);
    k_mma_h<__half, false, true><<<dim3(2, GN), 256, SMEM_BYTES_H>>>(
        p_nin, p_wnp1, p_np1, NN, 128, 256,
        p_sum + 256, p_sq + 256, nullptr, nullptr, nullptr, nullptr, 0.f);
    k_mma_h<float, true, false><<<dim3(GN, 1), 256, SMEM_BYTES_H>>>(
        p_np1, p_wnp2, p_np2, NN, 256, 128,
        p_sum + 512, p_sq + 512,
        p_sum + 256, p_sq + 256, lvl2_g1, lvl2_b1, 1.0f / NN);
    k_bnapply4<<<2048, 256>>>((const float4*)p_np2, (float4*)out_node, NN, 31,
                              p_sum + 512, p_sq + 512, lvl2_g2, lvl2_b2, 1.0f / NN);

    // -------- join: graph end depends on both chains --------
    cudaStreamWaitEvent(0, ev_edge, 0);
}

// round 11
// speedup vs baseline: 1.3692x; 1.0220x over previous
#include <cuda_runtime.h>
#include <cuda_fp16.h>
#include <cstring>

#define NN 20000      // nodes
#define NE 160000     // edges
#define TE 320000     // 2E edge-rows
#define HH 128

// ---------------- scratch (static __device__, no allocs) ----------------
__device__ __align__(128) __half s_ew2 [(size_t)TE * 128];   // er @ W2
__device__ __align__(128) __half s_a0  [(size_t)NN * 128];   // nr @ W0
__device__ __align__(128) __half s_a1  [(size_t)NN * 128];   // nr @ W1
__device__ __align__(128) __half s_pre1[(size_t)TE * 128];   // lvl1 pre-act
__device__ __align__(128) __half s_nin [(size_t)NN * 128];
__device__ __align__(128) __half s_np1 [(size_t)NN * 256];
__device__ __align__(128) float  s_np2 [(size_t)NN * 128];   // final pre-act: fp32
__device__ __align__(128) __half s_ein [(size_t)TE * 256];
__device__ __align__(128) __half s_ep1 [(size_t)TE * 256];
__device__ __align__(128) float  s_ep2 [(size_t)TE * 128];   // final pre-act: fp32
// fp16 weights, pre-transposed to n-major [N][K]
__device__ __align__(128) __half w_np1h[256 * 128];
__device__ __align__(128) __half w_np2h[128 * 256];
__device__ __align__(128) __half w_ep1h[256 * 256];
__device__ __align__(128) __half w_ep2h[128 * 256];
// CSR: node -> incident edge-rows
__device__ int s_deg[NN];
__device__ int s_rowptr[NN + 1];
__device__ int s_cursor[NN];
__device__ int s_csr[TE];
__device__ float s_sum[5 * 256];
__device__ float s_sq [5 * 256];
__device__ int   s_u[NE];
__device__ int   s_v[NE];
__device__ int   g_is64;

// ---------------- helpers ----------------
__device__ __forceinline__ unsigned h2u(__half2 h) {
    unsigned u;
    memcpy(&u, &h, 4);
    return u;
}

__global__ void k_zero() {
    int i0 = blockIdx.x * blockDim.x + threadIdx.x;
    if (i0 < NN) s_deg[i0] = 0;
    if (i0 < 5 * 256) { s_sum[i0] = 0.0f; s_sq[i0] = 0.0f; }
}

__global__ void k_detect(const int* __restrict__ ei32) {
    if (threadIdx.x == 0 && blockIdx.x == 0) {
        int nz = 0;
        for (int i = 0; i < 256; i++) nz |= ei32[2 * i + 1];
        g_is64 = (nz == 0) ? 1 : 0;
    }
}

__global__ void k_decode(const void* __restrict__ ei) {
    int e = blockIdx.x * blockDim.x + threadIdx.x;
    if (e >= NE) return;
    if (g_is64) {
        const long long* p = (const long long*)ei;
        s_u[e] = (int)p[e];
        s_v[e] = (int)p[NE + e];
    } else {
        const int* p = (const int*)ei;
        s_u[e] = p[e];
        s_v[e] = p[NE + e];
    }
}

// ---- CSR build ----
__global__ void k_hist() {
    int e = blockIdx.x * blockDim.x + threadIdx.x;
    if (e >= NE) return;
    atomicAdd(&s_deg[s_u[e]], 1);
    atomicAdd(&s_deg[s_v[e]], 1);
}

__global__ void k_scan() {   // single block, 1024 threads; 20 nodes/thread
    __shared__ int ts[1024];
    int t = threadIdx.x;
    int base = t * 20;
    int lv[20];
    int loc = 0;
#pragma unroll
    for (int i = 0; i < 20; i++) {
        int n = base + i;
        lv[i] = (n < NN) ? s_deg[n] : 0;
        loc += lv[i];
    }
    ts[t] = loc;
    __syncthreads();
    for (int off = 1; off < 1024; off <<= 1) {
        int v = (t >= off) ? ts[t - off] : 0;
        __syncthreads();
        ts[t] += v;
        __syncthreads();
    }
    int run = ts[t] - loc;   // exclusive prefix
#pragma unroll
    for (int i = 0; i < 20; i++) {
        int n = base + i;
        if (n < NN) {
            s_rowptr[n] = run;
            s_cursor[n] = run;
            run += lv[i];
        }
    }
    if (t == 1023) s_rowptr[NN] = ts[1023];
}

__global__ void k_place() {
    int e = blockIdx.x * blockDim.x + threadIdx.x;
    if (e >= NE) return;
    int p0 = atomicAdd(&s_cursor[s_u[e]], 1);
    s_csr[p0] = 2 * e;
    int p1 = atomicAdd(&s_cursor[s_v[e]], 1);
    s_csr[p1] = 2 * e + 1;
}

// convert + transpose weights to fp16 n-major
__global__ void k_wprep(const float* __restrict__ w_np1, const float* __restrict__ w_np2,
                        const float* __restrict__ w_ep1, const float* __restrict__ w_ep2) {
    int i = blockIdx.x * blockDim.x + threadIdx.x;   // 65536 threads
    if (i < 256 * 128) {            // np1: [128][256] -> [256][128]
        int n = i >> 7, k = i & 127;
        w_np1h[i] = __float2half_rn(w_np1[k * 256 + n]);
    }
    if (i < 128 * 256) {            // np2: [256][128] -> [128][256]
        int n = i >> 8, k = i & 255;
        w_np2h[i] = __float2half_rn(w_np2[k * 128 + n]);
    }
    if (i < 256 * 256) {            // ep1: [256][256] -> transposed
        int n = i >> 8, k = i & 255;
        w_ep1h[i] = __float2half_rn(w_ep1[k * 256 + n]);
    }
    if (i < 128 * 256) {            // ep2: [256][128] -> [128][256]
        int n = i >> 8, k = i & 255;
        w_ep2h[i] = __float2half_rn(w_ep2[k * 128 + n]);
    }
}

__device__ __forceinline__ unsigned f2tf(float x) {
    unsigned r;
    asm("cvt.rna.tf32.f32 %0, %1;" : "=r"(r) : "f"(x));
    return r;
}

__device__ __forceinline__ void cpasync16(void* smem_ptr, const void* gptr, int src_bytes) {
    unsigned saddr = (unsigned)__cvta_generic_to_shared(smem_ptr);
    asm volatile("cp.async.cg.shared.global [%0], [%1], 16, %2;"
                 :: "r"(saddr), "l"(gptr), "r"(src_bytes));
}
__device__ __forceinline__ void cpasync_commit() {
    asm volatile("cp.async.commit_group;");
}
template <int N>
__device__ __forceinline__ void cpasync_wait() {
    asm volatile("cp.async.wait_group %0;" :: "n"(N));
}

#define MMA_TF32(d, Af, Bf)                                                     \
    asm volatile(                                                               \
        "mma.sync.aligned.m16n8k8.row.col.f32.tf32.tf32.f32 "                   \
        "{%0,%1,%2,%3},{%4,%5,%6,%7},{%8,%9},{%0,%1,%2,%3};"                    \
        : "+f"(d[0]), "+f"(d[1]), "+f"(d[2]), "+f"(d[3])                        \
        : "r"(Af[0]), "r"(Af[1]), "r"(Af[2]), "r"(Af[3]),                       \
          "r"(Bf[0]), "r"(Bf[1]))

#define MMA_F16(d, Af, Bf)                                                      \
    asm volatile(                                                               \
        "mma.sync.aligned.m16n8k16.row.col.f32.f16.f16.f32 "                    \
        "{%0,%1,%2,%3},{%4,%5,%6,%7},{%8,%9},{%0,%1,%2,%3};"                    \
        : "+f"(d[0]), "+f"(d[1]), "+f"(d[2]), "+f"(d[3])                        \
        : "r"(Af[0]), "r"(Af[1]), "r"(Af[2]), "r"(Af[3]),                       \
          "r"(Bf[0]), "r"(Bf[1]))

// typed stores (stats on stored/rounded values)
__device__ __forceinline__ void st2(float* C, size_t off, float c0, float c1,
                                    float& r0, float& r1) {
    *(float2*)(C + off) = make_float2(c0, c1);
    r0 = c0; r1 = c1;
}
__device__ __forceinline__ void st2(__half* C, size_t off, float c0, float c1,
                                    float& r0, float& r1) {
    __half2 h = __floats2half2_rn(c0, c1);
    *(__half2*)(C + off) = h;
    r0 = __low2float(h); r1 = __high2float(h);
}

// ================= TF32 GEMM (float A, fp32 k-major B, half C) ==================
#define BS_STRIDE 136
#define BS_TILE (32 * BS_STRIDE)
#define AF_STRIDE 36
#define SMEM_BYTES_F (2 * 128 * AF_STRIDE * 4 + 2 * BS_TILE * 4 + 2048)   // 73728

__global__ __launch_bounds__(256, 2) void k_mma_f(
    const float* __restrict__ A, const float* __restrict__ Bm,
    __half* __restrict__ C, int M, int K, int NC)
{
    extern __shared__ float dsm[];
    float* AsB = dsm;
    float* BsB = dsm + 2 * 128 * AF_STRIDE;

    const int tid = threadIdx.x;
    const int lane = tid & 31, warp = tid >> 5;
    const int group = lane >> 2, qt = lane & 3;
    const int warpM = warp & 1, warpN = warp >> 1;
    const int mBase = blockIdx.x * 128, nBase = blockIdx.y * 128;
    const int nk = K >> 5;

    const int arow = tid >> 3, akq = (tid & 7) << 2;
    const int bkr = tid >> 5, bnc = (tid & 31) << 2;

    auto issue = [&](int i, int b) {
        const int k0 = i << 5;
        float* As = AsB + b * 128 * AF_STRIDE;
        float* Bs = BsB + b * BS_TILE;
#pragma unroll
        for (int it = 0; it < 4; it++) {
            int row = arow + it * 32;
            int gm = mBase + row;
            const float* src = A + (size_t)(gm < M ? gm : 0) * K + k0 + akq;
            cpasync16(As + row * AF_STRIDE + akq, src, gm < M ? 16 : 0);
        }
#pragma unroll
        for (int it = 0; it < 4; it++) {
            int kr = bkr + it * 8;
            const float* src = Bm + (size_t)(k0 + kr) * NC + nBase + bnc;
            cpasync16(Bs + kr * BS_STRIDE + bnc, src, 16);
        }
        cpasync_commit();
    };

    float acc[4][4][4];
#pragma unroll
    for (int mt = 0; mt < 4; mt++)
#pragma unroll
        for (int nt = 0; nt < 4; nt++)
#pragma unroll
            for (int i = 0; i < 4; i++) acc[mt][nt][i] = 0.0f;

    issue(0, 0);
    for (int i = 0; i < nk; i++) {
        if (i + 1 < nk) { issue(i + 1, (i + 1) & 1); cpasync_wait<1>(); }
        else            { cpasync_wait<0>(); }
        __syncthreads();
        const float* As = AsB + (i & 1) * 128 * AF_STRIDE;
        const float* Bs = BsB + (i & 1) * BS_TILE;
#pragma unroll
        for (int ks = 0; ks < 4; ks++) {
            const int kc = ks * 8 + qt;
            unsigned af[4][4], bf[4][2];
#pragma unroll
            for (int mt = 0; mt < 4; mt++) {
                int r = warpM * 64 + mt * 16 + group;
                af[mt][0] = f2tf(As[r * AF_STRIDE + kc]);
                af[mt][1] = f2tf(As[(r + 8) * AF_STRIDE + kc]);
                af[mt][2] = f2tf(As[r * AF_STRIDE + kc + 4]);
                af[mt][3] = f2tf(As[(r + 8) * AF_STRIDE + kc + 4]);
            }
#pragma unroll
            for (int nt = 0; nt < 4; nt++) {
                int cb = warpN * 32 + nt * 8 + group;
                bf[nt][0] = f2tf(Bs[kc * BS_STRIDE + cb]);
                bf[nt][1] = f2tf(Bs[(kc + 4) * BS_STRIDE + cb]);
            }
#pragma unroll
            for (int mt = 0; mt < 4; mt++)
#pragma unroll
                for (int nt = 0; nt < 4; nt++)
                    MMA_TF32(acc[mt][nt], af[mt], bf[nt]);
        }
        __syncthreads();
    }

#pragma unroll
    for (int mt = 0; mt < 4; mt++) {
        int r0 = mBase + warpM * 64 + mt * 16 + group;
        int r1 = r0 + 8;
#pragma unroll
        for (int nt = 0; nt < 4; nt++) {
            int cc = nBase + warpN * 32 + nt * 8 + 2 * qt;
            float x0, x1;
            if (r0 < M) st2(C, (size_t)r0 * NC + cc, acc[mt][nt][0], acc[mt][nt][1], x0, x1);
            if (r1 < M) st2(C, (size_t)r1 * NC + cc, acc[mt][nt][2], acc[mt][nt][3], x0, x1);
        }
    }
}

// ================= FP16 HMMA GEMM (half A [M][K], half B n-major [NC][K]) ==========
#define HSTR 40
#define HA_TILE (128 * HSTR)  // halfs per buffer (A or B)
#define SMEM_BYTES_H (4 * HA_TILE * 2 + 2048)   // 2 A-bufs + 2 B-bufs + BN = 43008

template <typename TC, bool FUSE_BN, bool SWAP>
__global__ __launch_bounds__(256, 2) void k_mma_h(
    const __half* __restrict__ A, const __half* __restrict__ Bt,
    TC* __restrict__ C, int M, int K, int NC,
    float* __restrict__ sumO, float* __restrict__ sqO,
    const float* __restrict__ aSum, const float* __restrict__ aSq,
    const float* __restrict__ aG, const float* __restrict__ aBt, float aInv)
{
    extern __shared__ char dsmRaw[];
    __half* AsB = (__half*)dsmRaw;
    __half* BsB = (__half*)(dsmRaw + 2 * HA_TILE * 2);
    float* scS = (float*)(dsmRaw + 4 * HA_TILE * 2);
    float* shS = scS + 256;

    const int tid = threadIdx.x;
    const int lane = tid & 31, warp = tid >> 5;
    const int group = lane >> 2, qt = lane & 3;
    const int warpM = warp & 1, warpN = warp >> 1;
    const int mBase = (SWAP ? blockIdx.y : blockIdx.x) * 128;
    const int nBase = (SWAP ? blockIdx.x : blockIdx.y) * 128;
    const int nk = K >> 5;

    if (FUSE_BN) {
        if (tid < K) {
            float mean = aSum[tid] * aInv;
            float var  = aSq[tid] * aInv - mean * mean;
            float s = aG[tid] * rsqrtf(var + 1e-5f);
            scS[tid] = s; shS[tid] = aBt[tid] - mean * s;
        }
        __syncthreads();
    }

    const int arow = tid >> 2, akq = (tid & 3) << 3;  // halfs: TPR=4, RPI=64

    auto issue = [&](int i, int b) {
        const int k0 = i << 5;
        __half* As = AsB + b * HA_TILE;
        __half* Bs = BsB + b * HA_TILE;
#pragma unroll
        for (int it = 0; it < 2; it++) {
            int row = arow + it * 64;
            int gm = mBase + row;
            const __half* src = A + (size_t)(gm < M ? gm : 0) * K + k0 + akq;
            cpasync16(As + row * HSTR + akq, src, gm < M ? 16 : 0);
        }
#pragma unroll
        for (int it = 0; it < 2; it++) {
            int row = arow + it * 64;
            const __half* src = Bt + (size_t)(nBase + row) * K + k0 + akq;
            cpasync16(Bs + row * HSTR + akq, src, 16);
        }
        cpasync_commit();
    };

    float acc[4][4][4];
#pragma unroll
    for (int mt = 0; mt < 4; mt++)
#pragma unroll
        for (int nt = 0; nt < 4; nt++)
#pragma unroll
            for (int i = 0; i < 4; i++) acc[mt][nt][i] = 0.0f;

    issue(0, 0);
    for (int i = 0; i < nk; i++) {
        if (i + 1 < nk) { issue(i + 1, (i + 1) & 1); cpasync_wait<1>(); }
        else            { cpasync_wait<0>(); }
        __syncthreads();
        const __half* As = AsB + (i & 1) * HA_TILE;
        const __half* Bs = BsB + (i & 1) * HA_TILE;
        const int k0 = i << 5;
#pragma unroll
        for (int ks = 0; ks < 2; ks++) {
            const int kk = ks * 16;
            const int kb = kk + 2 * qt;
            unsigned af[4][4], bf[4][2];
            float sc0, sh0, sc1, sh1, sc8, sh8, sc9, sh9;
            if (FUSE_BN) {
                int g = k0 + kb;
                sc0 = scS[g];     sh0 = shS[g];
                sc1 = scS[g + 1]; sh1 = shS[g + 1];
                sc8 = scS[g + 8]; sh8 = shS[g + 8];
                sc9 = scS[g + 9]; sh9 = shS[g + 9];
            }
#pragma unroll
            for (int mt = 0; mt < 4; mt++) {
                int r = warpM * 64 + mt * 16 + group;
                const __half* p0 = As + r * HSTR + kb;
                const __half* p1 = As + (r + 8) * HSTR + kb;
                if (FUSE_BN) {
                    float2 v0 = __half22float2(*(const __half2*)p0);
                    float2 v1 = __half22float2(*(const __half2*)p1);
                    float2 v2 = __half22float2(*(const __half2*)(p0 + 8));
                    float2 v3 = __half22float2(*(const __half2*)(p1 + 8));
                    af[mt][0] = h2u(__floats2half2_rn(
                        fmaxf(fmaf(v0.x, sc0, sh0), 0.f), fmaxf(fmaf(v0.y, sc1, sh1), 0.f)));
                    af[mt][1] = h2u(__floats2half2_rn(
                        fmaxf(fmaf(v1.x, sc0, sh0), 0.f), fmaxf(fmaf(v1.y, sc1, sh1), 0.f)));
                    af[mt][2] = h2u(__floats2half2_rn(
                        fmaxf(fmaf(v2.x, sc8, sh8), 0.f), fmaxf(fmaf(v2.y, sc9, sh9), 0.f)));
                    af[mt][3] = h2u(__floats2half2_rn(
                        fmaxf(fmaf(v3.x, sc8, sh8), 0.f), fmaxf(fmaf(v3.y, sc9, sh9), 0.f)));
                } else {
                    af[mt][0] = *(const unsigned*)p0;
                    af[mt][1] = *(const unsigned*)p1;
                    af[mt][2] = *(const unsigned*)(p0 + 8);
                    af[mt][3] = *(const unsigned*)(p1 + 8);
                }
            }
#pragma unroll
            for (int nt = 0; nt < 4; nt++) {
                int cb = warpN * 32 + nt * 8 + group;
                const __half* q = Bs + cb * HSTR + kb;
                bf[nt][0] = *(const unsigned*)q;
                bf[nt][1] = *(const unsigned*)(q + 8);
            }
#pragma unroll
            for (int mt = 0; mt < 4; mt++)
#pragma unroll
                for (int nt = 0; nt < 4; nt++)
                    MMA_F16(acc[mt][nt], af[mt], bf[nt]);
        }
        __syncthreads();
    }

    // epilogue: store + BN stats (on stored values)
    float cs[4][2], cq[4][2];
#pragma unroll
    for (int nt = 0; nt < 4; nt++) { cs[nt][0] = cs[nt][1] = 0.f; cq[nt][0] = cq[nt][1] = 0.f; }
#pragma unroll
    for (int mt = 0; mt < 4; mt++) {
        int r0 = mBase + warpM * 64 + mt * 16 + group;
        int r1 = r0 + 8;
#pragma unroll
        for (int nt = 0; nt < 4; nt++) {
            int cc = nBase + warpN * 32 + nt * 8 + 2 * qt;
            float x0, x1;
            if (r0 < M) {
                st2(C, (size_t)r0 * NC + cc, acc[mt][nt][0], acc[mt][nt][1], x0, x1);
                cs[nt][0] += x0; cs[nt][1] += x1;
                cq[nt][0] += x0 * x0; cq[nt][1] += x1 * x1;
            }
            if (r1 < M) {
                st2(C, (size_t)r1 * NC + cc, acc[mt][nt][2], acc[mt][nt][3], x0, x1);
                cs[nt][0] += x0; cs[nt][1] += x1;
                cq[nt][0] += x0 * x0; cq[nt][1] += x1 * x1;
            }
        }
    }
    if (sumO) {
#pragma unroll
        for (int off = 4; off < 32; off <<= 1) {
#pragma unroll
            for (int nt = 0; nt < 4; nt++) {
#pragma unroll
                for (int p = 0; p < 2; p++) {
                    cs[nt][p] += __shfl_xor_sync(0xffffffffu, cs[nt][p], off);
                    cq[nt][p] += __shfl_xor_sync(0xffffffffu, cq[nt][p], off);
                }
            }
        }
        if (group == 0) {
#pragma unroll
            for (int nt = 0; nt < 4; nt++) {
                int cc = nBase + warpN * 32 + nt * 8 + 2 * qt;
                atomicAdd(sumO + cc,     cs[nt][0]);
                atomicAdd(sumO + cc + 1, cs[nt][1]);
                atomicAdd(sqO  + cc,     cq[nt][0]);
                atomicAdd(sqO  + cc + 1, cq[nt][1]);
            }
        }
    }
}

// ---------------- combine (half2 vectorized) ----------------
__global__ void k_combine() {
    int c = threadIdx.x & 63;
    int eo = threadIdx.x >> 6;
    float ls0 = 0.f, ls1 = 0.f, lq0 = 0.f, lq1 = 0.f;
    const __half2* a0 = (const __half2*)s_a0;
    const __half2* a1 = (const __half2*)s_a1;
    const __half2* ew = (const __half2*)s_ew2;
    __half2* pre = (__half2*)s_pre1;
    for (int e = blockIdx.x * 2 + eo; e < NE; e += gridDim.x * 2) {
        int u = s_u[e], v = s_v[e];
        float2 a0u = __half22float2(a0[(size_t)u * 64 + c]);
        float2 a0v = __half22float2(a0[(size_t)v * 64 + c]);
        float2 a1u = __half22float2(a1[(size_t)u * 64 + c]);
        float2 a1v = __half22float2(a1[(size_t)v * 64 + c]);
        float bx = a0u.x + a0v.x, by = a0u.y + a0v.y;
        size_t r0 = (size_t)(2 * e) * 64 + c, r1 = (size_t)(2 * e + 1) * 64 + c;
        float2 e0 = __half22float2(ew[r0]);
        float2 e1 = __half22float2(ew[r1]);
        __half2 h0 = __floats2half2_rn(bx + a1u.x + e0.x, by + a1u.y + e0.y);
        __half2 h1 = __floats2half2_rn(bx + a1v.x + e1.x, by + a1v.y + e1.y);
        pre[r0] = h0; pre[r1] = h1;
        float2 q0 = __half22float2(h0), q1 = __half22float2(h1);
        ls0 += q0.x + q1.x; ls1 += q0.y + q1.y;
        lq0 += q0.x * q0.x + q1.x * q1.x; lq1 += q0.y * q0.y + q1.y * q1.y;
    }
    atomicAdd(&s_sum[2 * c],     ls0);
    atomicAdd(&s_sum[2 * c + 1], ls1);
    atomicAdd(&s_sq[2 * c],      lq0);
    atomicAdd(&s_sq[2 * c + 1],  lq1);
}

// CSR gather: nin[n] = e11*nr[n] + sum_entries[(2+eps12)*h_r + h_sib]
// block = one node, 128 threads = fp32 columns
__global__ void k_gather_nin(const float* __restrict__ nr,
                             const float* __restrict__ g, const float* __restrict__ b,
                             const float* __restrict__ eps12p,
                             const float* __restrict__ eps11p) {
    int n = blockIdx.x;
    int c = threadIdx.x;
    float mean = s_sum[c] * (1.0f / TE);
    float var  = s_sq[c]  * (1.0f / TE) - mean * mean;
    float sc = g[c] * rsqrtf(var + 1e-5f);
    float sh = b[c] - mean * sc;
    float cf = 2.0f + *eps12p;     // (1+eps12) + 1
    float e11 = 1.0f + *eps11p;
    int beg = s_rowptr[n], end = s_rowptr[n + 1];
    float acc = 0.f;
    for (int j = beg; j < end; j++) {
        int r = s_csr[j];
        int sIb = r ^ 1;
        float hr = fmaxf(__half2float(s_pre1[(size_t)r  * 128 + c]) * sc + sh, 0.f);
        float hs = fmaxf(__half2float(s_pre1[(size_t)sIb * 128 + c]) * sc + sh, 0.f);
        acc += cf * hr + hs;
    }
    s_nin[(size_t)n * 128 + c] = __float2half_rn(e11 * nr[(size_t)n * 128 + c] + acc);
}

__global__ void k_ein(const float* __restrict__ er, const float* __restrict__ nr,
                      const float* __restrict__ eps2p) {
    int c = threadIdx.x & 63;
    int eo = threadIdx.x >> 6;
    float e2 = 1.0f + *eps2p;
    float e2h = 0.5f * e2;
    const float2* er2 = (const float2*)er;
    const float2* nr2 = (const float2*)nr;
    __half2* ein = (__half2*)s_ein;
    for (int e = blockIdx.x * 2 + eo; e < NE; e += gridDim.x * 2) {
        int u = s_u[e], v = s_v[e];
        float2 a = er2[(size_t)(2 * e) * 64 + c];
        float2 bq = er2[(size_t)(2 * e + 1) * 64 + c];
        float2 p = nr2[(size_t)u * 64 + c];
        float2 q = nr2[(size_t)v * 64 + c];
        __half2 fh = __floats2half2_rn(e2h * (a.x + bq.x) + p.x + q.x,
                                       e2h * (a.y + bq.y) + p.y + q.y);
        size_t r0 = (size_t)(2 * e) * 128 + c, r1 = (size_t)(2 * e + 1) * 128 + c;
        ein[r0] = fh;
        ein[r1] = fh;
        ein[r0 + 64] = __floats2half2_rn(e2 * a.x + p.x,  e2 * a.y + p.y);
        ein[r1 + 64] = __floats2half2_rn(e2 * bq.x + q.x, e2 * bq.y + q.y);
    }
}

// dst = relu(src*scale + shift), float4 vectorized
__global__ void k_bnapply4(const float4* __restrict__ src, float4* __restrict__ dst,
                           int rows, int col4Mask,
                           const float* __restrict__ sum, const float* __restrict__ sq,
                           const float* __restrict__ g, const float* __restrict__ b,
                           float inv) {
    size_t n = (size_t)rows * (col4Mask + 1);
    size_t stride = (size_t)gridDim.x * blockDim.x;
    for (size_t i = (size_t)blockIdx.x * blockDim.x + threadIdx.x; i < n; i += stride) {
        int c = (int)(i & (size_t)col4Mask) << 2;
        float4 v = src[i];
        float4 o;
#pragma unroll
        for (int j = 0; j < 4; j++) {
            float mean = sum[c + j] * inv;
            float var  = sq[c + j] * inv - mean * mean;
            float scv = g[c + j] * rsqrtf(var + 1e-5f);
            float shv = b[c + j] - mean * scv;
            float x = (&v.x)[j] * scv + shv;
            (&o.x)[j] = fmaxf(x, 0.f);
        }
        dst[i] = o;
    }
}

// ---------------- launch ----------------
extern "C" void kernel_launch(void* const* d_in, const int* in_sizes, int n_in,
                              void* d_out, int out_size) {
    const float* nr      = (const float*)d_in[0];
    const float* er      = (const float*)d_in[1];
    const void*  ei      = d_in[2];
    const float* lift_w1 = (const float*)d_in[3];
    const float* lift_g1 = (const float*)d_in[4];
    const float* lift_b1 = (const float*)d_in[5];
    const float* lift_w2 = (const float*)d_in[6];
    const float* lift_g2 = (const float*)d_in[7];
    const float* lift_b2 = (const float*)d_in[8];
    const float* lvl1_w  = (const float*)d_in[9];
    const float* lvl1_g  = (const float*)d_in[10];
    const float* lvl1_b  = (const float*)d_in[11];
    const float* lvl2_w1 = (const float*)d_in[12];
    const float* lvl2_g1 = (const float*)d_in[13];
    const float* lvl2_b1 = (const float*)d_in[14];
    const float* lvl2_w2 = (const float*)d_in[15];
    const float* lvl2_g2 = (const float*)d_in[16];
    const float* lvl2_b2 = (const float*)d_in[17];
    const float* eps11   = (const float*)d_in[18];
    const float* eps12   = (const float*)d_in[19];
    const float* eps2    = (const float*)d_in[20];

    float* out_node = (float*)d_out;
    float* out_edge = out_node + (size_t)NN * HH;

    __half *p_ew2, *p_a0, *p_a1, *p_nin, *p_np1, *p_ein, *p_ep1;
    __half *p_wnp1, *p_wnp2, *p_wep1, *p_wep2;
    float *p_np2, *p_ep2, *p_sum, *p_sq;
    cudaGetSymbolAddress((void**)&p_ew2, s_ew2);
    cudaGetSymbolAddress((void**)&p_a0,  s_a0);
    cudaGetSymbolAddress((void**)&p_a1,  s_a1);
    cudaGetSymbolAddress((void**)&p_nin, s_nin);
    cudaGetSymbolAddress((void**)&p_np1, s_np1);
    cudaGetSymbolAddress((void**)&p_np2, s_np2);
    cudaGetSymbolAddress((void**)&p_ein, s_ein);
    cudaGetSymbolAddress((void**)&p_ep1, s_ep1);
    cudaGetSymbolAddress((void**)&p_ep2, s_ep2);
    cudaGetSymbolAddress((void**)&p_sum, s_sum);
    cudaGetSymbolAddress((void**)&p_sq,  s_sq);
    cudaGetSymbolAddress((void**)&p_wnp1, w_np1h);
    cudaGetSymbolAddress((void**)&p_wnp2, w_np2h);
    cudaGetSymbolAddress((void**)&p_wep1, w_ep1h);
    cudaGetSymbolAddress((void**)&p_wep2, w_ep2h);

    static cudaStream_t s_edge = nullptr, s_csrS = nullptr;
    static cudaEvent_t ev_fork = nullptr, ev_edge = nullptr, ev_csr = nullptr;
    static int smem_set = 0;
    if (!smem_set) {
        cudaFuncSetAttribute((const void*)k_mma_f,
                             cudaFuncAttributeMaxDynamicSharedMemorySize, SMEM_BYTES_F);
        cudaFuncSetAttribute((const void*)k_mma_h<__half, false, true>,
                             cudaFuncAttributeMaxDynamicSharedMemorySize, SMEM_BYTES_H);
        cudaFuncSetAttribute((const void*)k_mma_h<float, true, false>,
                             cudaFuncAttributeMaxDynamicSharedMemorySize, SMEM_BYTES_H);
        cudaStreamCreateWithFlags(&s_edge, cudaStreamNonBlocking);
        cudaStreamCreateWithFlags(&s_csrS, cudaStreamNonBlocking);
        cudaEventCreateWithFlags(&ev_fork, cudaEventDisableTiming);
        cudaEventCreateWithFlags(&ev_edge, cudaEventDisableTiming);
        cudaEventCreateWithFlags(&ev_csr,  cudaEventDisableTiming);
        smem_set = 1;
    }

    const int GN  = (NN + 127) / 128;  // 157
    const int GTE = TE / 128;          // 2500

    // -------- pre-fork (stream 0): shared prerequisites --------
    k_zero<<<(NN + 255) / 256, 256>>>();
    k_detect<<<1, 32>>>((const int*)ei);
    k_decode<<<(NE + 255) / 256, 256>>>(ei);
    k_wprep<<<256, 256>>>(lvl2_w1, lvl2_w2, lift_w1, lift_w2);
    cudaEventRecord(ev_fork, 0);

    // -------- CSR build (s_csrS): overlapped with GEMM chains --------
    cudaStreamWaitEvent(s_csrS, ev_fork, 0);
    k_hist<<<(NE + 255) / 256, 256, 0, s_csrS>>>();
    k_scan<<<1, 1024, 0, s_csrS>>>();
    k_place<<<(NE + 255) / 256, 256, 0, s_csrS>>>();
    cudaEventRecord(ev_csr, s_csrS);

    // -------- edge chain (s_edge): independent of the lvl1/node path --------
    cudaStreamWaitEvent(s_edge, ev_fork, 0);
    k_ein<<<2048, 128, 0, s_edge>>>(er, nr, eps2);
    k_mma_h<__half, false, true><<<dim3(2, GTE), 256, SMEM_BYTES_H, s_edge>>>(
        p_ein, p_wep1, p_ep1, TE, 256, 256,
        p_sum + 768, p_sq + 768, nullptr, nullptr, nullptr, nullptr, 0.f);
    k_mma_h<float, true, false><<<dim3(GTE, 1), 256, SMEM_BYTES_H, s_edge>>>(
        p_ep1, p_wep2, p_ep2, TE, 256, 128,
        p_sum + 1024, p_sq + 1024,
        p_sum + 768, p_sq + 768, lift_g1, lift_b1, 1.0f / TE);
    k_bnapply4<<<4096, 256, 0, s_edge>>>((const float4*)p_ep2, (float4*)out_edge, TE, 31,
                              p_sum + 1024, p_sq + 1024, lift_g2, lift_b2, 1.0f / TE);
    cudaEventRecord(ev_edge, s_edge);

    // -------- node chain (stream 0) --------
    k_mma_f<<<dim3(GTE, 1), 256, SMEM_BYTES_F>>>(er, lvl1_w + 256 * 128, p_ew2, TE, 128, 128);
    k_mma_f<<<dim3(GN, 1),  256, SMEM_BYTES_F>>>(nr, lvl1_w,             p_a0,  NN, 128, 128);
    k_mma_f<<<dim3(GN, 1),  256, SMEM_BYTES_F>>>(nr, lvl1_w + 128 * 128, p_a1,  NN, 128, 128);

    k_combine<<<2048, 128>>>();                             // stats slot 0, pre1 half

    cudaStreamWaitEvent(0, ev_csr, 0);
    k_gather_nin<<<NN, 128>>>(nr, lvl1_g, lvl1_b, eps12, eps11);  // BN+aggregate+nin fused

    k_mma_h<__half, false, true><<<dim3(2, GN), 256, SMEM_BYTES_H>>>(
        p_nin, p_wnp1, p_np1, NN, 128, 256,
        p_sum + 256, p_sq + 256, nullptr, nullptr, nullptr, nullptr, 0.f);
    k_mma_h<float, true, false><<<dim3(GN, 1), 256, SMEM_BYTES_H>>>(
        p_np1, p_wnp2, p_np2, NN, 256, 128,
        p_sum + 512, p_sq + 512,
        p_sum + 256, p_sq + 256, lvl2_g1, lvl2_b1, 1.0f / NN);
    k_bnapply4<<<2048, 256>>>((const float4*)p_np2, (float4*)out_node, NN, 31,
                              p_sum + 512, p_sq + 512, lvl2_g2, lvl2_b2, 1.0f / NN);

    // -------- join: graph end depends on both chains --------
    cudaStreamWaitEvent(0, ev_edge, 0);
}

// round 12
// speedup vs baseline: 1.3833x; 1.0103x over previous
#include <cuda_runtime.h>
#include <cuda_fp16.h>
#include <cstring>

#define NN 20000      // nodes
#define NE 160000     // edges
#define TE 320000     // 2E edge-rows
#define HH 128

// ---------------- scratch (static __device__, no allocs) ----------------
__device__ __align__(128) __half s_ew2 [(size_t)TE * 128];   // er @ W2
__device__ __align__(128) __half s_a0  [(size_t)NN * 128];   // nr @ W0
__device__ __align__(128) __half s_a1  [(size_t)NN * 128];   // nr @ W1
__device__ __align__(128) __half s_pre1[(size_t)TE * 128];   // lvl1 pre-act
__device__ __align__(128) __half s_nin [(size_t)NN * 128];
__device__ __align__(128) __half s_np1 [(size_t)NN * 256];
__device__ __align__(128) float  s_np2 [(size_t)NN * 128];   // final pre-act: fp32
__device__ __align__(128) __half s_ein [(size_t)TE * 256];
__device__ __align__(128) __half s_ep1 [(size_t)TE * 256];
__device__ __align__(128) float  s_ep2 [(size_t)TE * 128];   // final pre-act: fp32
// fp16 weights, pre-transposed to n-major [N][K]
__device__ __align__(128) __half w_np1h[256 * 128];
__device__ __align__(128) __half w_np2h[128 * 256];
__device__ __align__(128) __half w_ep1h[256 * 256];
__device__ __align__(128) __half w_ep2h[128 * 256];
__device__ __align__(128) __half w_l1h [3 * 128 * 128];   // lvl1 W blocks 0,1,2 n-major
// CSR: node -> incident edge-rows
__device__ int s_deg[NN];
__device__ int s_rowptr[NN + 1];
__device__ int s_cursor[NN];
__device__ int s_csr[TE];
__device__ float s_sum[5 * 256];
__device__ float s_sq [5 * 256];
__device__ int   s_u[NE];
__device__ int   s_v[NE];
__device__ int   g_is64;

// ---------------- helpers ----------------
__device__ __forceinline__ unsigned h2u(__half2 h) {
    unsigned u;
    memcpy(&u, &h, 4);
    return u;
}

__global__ void k_zero() {
    int i0 = blockIdx.x * blockDim.x + threadIdx.x;
    if (i0 < NN) s_deg[i0] = 0;
    if (i0 < 5 * 256) { s_sum[i0] = 0.0f; s_sq[i0] = 0.0f; }
}

__global__ void k_detect(const int* __restrict__ ei32) {
    if (threadIdx.x == 0 && blockIdx.x == 0) {
        int nz = 0;
        for (int i = 0; i < 256; i++) nz |= ei32[2 * i + 1];
        g_is64 = (nz == 0) ? 1 : 0;
    }
}

__global__ void k_decode(const void* __restrict__ ei) {
    int e = blockIdx.x * blockDim.x + threadIdx.x;
    if (e >= NE) return;
    if (g_is64) {
        const long long* p = (const long long*)ei;
        s_u[e] = (int)p[e];
        s_v[e] = (int)p[NE + e];
    } else {
        const int* p = (const int*)ei;
        s_u[e] = p[e];
        s_v[e] = p[NE + e];
    }
}

// ---- CSR build ----
__global__ void k_hist() {
    int e = blockIdx.x * blockDim.x + threadIdx.x;
    if (e >= NE) return;
    atomicAdd(&s_deg[s_u[e]], 1);
    atomicAdd(&s_deg[s_v[e]], 1);
}

__global__ void k_scan() {   // single block, 1024 threads; 20 nodes/thread
    __shared__ int ts[1024];
    int t = threadIdx.x;
    int base = t * 20;
    int lv[20];
    int loc = 0;
#pragma unroll
    for (int i = 0; i < 20; i++) {
        int n = base + i;
        lv[i] = (n < NN) ? s_deg[n] : 0;
        loc += lv[i];
    }
    ts[t] = loc;
    __syncthreads();
    for (int off = 1; off < 1024; off <<= 1) {
        int v = (t >= off) ? ts[t - off] : 0;
        __syncthreads();
        ts[t] += v;
        __syncthreads();
    }
    int run = ts[t] - loc;   // exclusive prefix
#pragma unroll
    for (int i = 0; i < 20; i++) {
        int n = base + i;
        if (n < NN) {
            s_rowptr[n] = run;
            s_cursor[n] = run;
            run += lv[i];
        }
    }
    if (t == 1023) s_rowptr[NN] = ts[1023];
}

__global__ void k_place() {
    int e = blockIdx.x * blockDim.x + threadIdx.x;
    if (e >= NE) return;
    int p0 = atomicAdd(&s_cursor[s_u[e]], 1);
    s_csr[p0] = 2 * e;
    int p1 = atomicAdd(&s_cursor[s_v[e]], 1);
    s_csr[p1] = 2 * e + 1;
}

// convert + transpose weights to fp16 n-major
__global__ void k_wprep(const float* __restrict__ w_np1, const float* __restrict__ w_np2,
                        const float* __restrict__ w_ep1, const float* __restrict__ w_ep2,
                        const float* __restrict__ w_l1) {
    int i = blockIdx.x * blockDim.x + threadIdx.x;   // 65536 threads
    if (i < 256 * 128) {            // np1: [128][256] -> [256][128]
        int n = i >> 7, k = i & 127;
        w_np1h[i] = __float2half_rn(w_np1[k * 256 + n]);
    }
    if (i < 128 * 256) {            // np2: [256][128] -> [128][256]
        int n = i >> 8, k = i & 255;
        w_np2h[i] = __float2half_rn(w_np2[k * 128 + n]);
    }
    if (i < 256 * 256) {            // ep1: [256][256] -> transposed
        int n = i >> 8, k = i & 255;
        w_ep1h[i] = __float2half_rn(w_ep1[k * 256 + n]);
    }
    if (i < 128 * 256) {            // ep2: [256][128] -> [128][256]
        int n = i >> 8, k = i & 255;
        w_ep2h[i] = __float2half_rn(w_ep2[k * 128 + n]);
    }
    if (i < 3 * 128 * 128) {        // lvl1 blocks: [384][128] -> 3x [128][128] n-major
        int blk = i >> 14, rem = i & 16383;
        int n = rem >> 7, k = rem & 127;
        w_l1h[i] = __float2half_rn(w_l1[(blk * 128 + k) * 128 + n]);
    }
}

__device__ __forceinline__ void cpasync16(void* smem_ptr, const void* gptr, int src_bytes) {
    unsigned saddr = (unsigned)__cvta_generic_to_shared(smem_ptr);
    asm volatile("cp.async.cg.shared.global [%0], [%1], 16, %2;"
                 :: "r"(saddr), "l"(gptr), "r"(src_bytes));
}
__device__ __forceinline__ void cpasync_commit() {
    asm volatile("cp.async.commit_group;");
}
template <int N>
__device__ __forceinline__ void cpasync_wait() {
    asm volatile("cp.async.wait_group %0;" :: "n"(N));
}

#define MMA_F16(d, Af, Bf)                                                      \
    asm volatile(                                                               \
        "mma.sync.aligned.m16n8k16.row.col.f32.f16.f16.f32 "                    \
        "{%0,%1,%2,%3},{%4,%5,%6,%7},{%8,%9},{%0,%1,%2,%3};"                    \
        : "+f"(d[0]), "+f"(d[1]), "+f"(d[2]), "+f"(d[3])                        \
        : "r"(Af[0]), "r"(Af[1]), "r"(Af[2]), "r"(Af[3]),                       \
          "r"(Bf[0]), "r"(Bf[1]))

// typed stores (stats on stored/rounded values)
__device__ __forceinline__ void st2(float* C, size_t off, float c0, float c1,
                                    float& r0, float& r1) {
    *(float2*)(C + off) = make_float2(c0, c1);
    r0 = c0; r1 = c1;
}
__device__ __forceinline__ void st2(__half* C, size_t off, float c0, float c1,
                                    float& r0, float& r1) {
    __half2 h = __floats2half2_rn(c0, c1);
    *(__half2*)(C + off) = h;
    r0 = __low2float(h); r1 = __high2float(h);
}

#define HSTR 40
#define HA_TILE (128 * HSTR)

// ======== HMMA GEMM, fp32 A (cvt at smem->reg), fp16 n-major B, half C ========
// For ew2/a0/a1: K=128, NC=128, no stats, no BN, no SWAP.
#define AF_STRIDE 36
#define SMEM_BYTES_FH (2 * 128 * AF_STRIDE * 4 + 2 * HA_TILE * 2 + 1024)  // 58368

__global__ __launch_bounds__(256, 2) void k_mma_fh(
    const float* __restrict__ A, const __half* __restrict__ Bt,
    __half* __restrict__ C, int M, int K, int NC)
{
    extern __shared__ char dsmRaw[];
    float* AsB = (float*)dsmRaw;
    __half* BsB = (__half*)(dsmRaw + 2 * 128 * AF_STRIDE * 4);

    const int tid = threadIdx.x;
    const int lane = tid & 31, warp = tid >> 5;
    const int group = lane >> 2, qt = lane & 3;
    const int warpM = warp & 1, warpN = warp >> 1;
    const int mBase = blockIdx.x * 128, nBase = blockIdx.y * 128;
    const int nk = K >> 5;

    const int arow = tid >> 3, akq = (tid & 7) << 2;     // fp32: 8 thr/row
    const int brow = tid >> 2, bkq = (tid & 3) << 3;     // fp16: 4 thr/row

    auto issue = [&](int i, int b) {
        const int k0 = i << 5;
        float* As = AsB + b * 128 * AF_STRIDE;
        __half* Bs = BsB + b * HA_TILE;
#pragma unroll
        for (int it = 0; it < 4; it++) {
            int row = arow + it * 32;
            int gm = mBase + row;
            const float* src = A + (size_t)(gm < M ? gm : 0) * K + k0 + akq;
            cpasync16(As + row * AF_STRIDE + akq, src, gm < M ? 16 : 0);
        }
#pragma unroll
        for (int it = 0; it < 2; it++) {
            int row = brow + it * 64;
            const __half* src = Bt + (size_t)(nBase + row) * K + k0 + bkq;
            cpasync16(Bs + row * HSTR + bkq, src, 16);
        }
        cpasync_commit();
    };

    float acc[4][4][4];
#pragma unroll
    for (int mt = 0; mt < 4; mt++)
#pragma unroll
        for (int nt = 0; nt < 4; nt++)
#pragma unroll
            for (int i = 0; i < 4; i++) acc[mt][nt][i] = 0.0f;

    issue(0, 0);
    for (int i = 0; i < nk; i++) {
        if (i + 1 < nk) { issue(i + 1, (i + 1) & 1); cpasync_wait<1>(); }
        else            { cpasync_wait<0>(); }
        __syncthreads();
        const float* As = AsB + (i & 1) * 128 * AF_STRIDE;
        const __half* Bs = BsB + (i & 1) * HA_TILE;
#pragma unroll
        for (int ks = 0; ks < 2; ks++) {
            const int kb = ks * 16 + 2 * qt;
            unsigned af[4][4], bf[4][2];
#pragma unroll
            for (int mt = 0; mt < 4; mt++) {
                int r = warpM * 64 + mt * 16 + group;
                float2 v0 = *(const float2*)(As + r * AF_STRIDE + kb);
                float2 v1 = *(const float2*)(As + (r + 8) * AF_STRIDE + kb);
                float2 v2 = *(const float2*)(As + r * AF_STRIDE + kb + 8);
                float2 v3 = *(const float2*)(As + (r + 8) * AF_STRIDE + kb + 8);
                af[mt][0] = h2u(__floats2half2_rn(v0.x, v0.y));
                af[mt][1] = h2u(__floats2half2_rn(v1.x, v1.y));
                af[mt][2] = h2u(__floats2half2_rn(v2.x, v2.y));
                af[mt][3] = h2u(__floats2half2_rn(v3.x, v3.y));
            }
#pragma unroll
            for (int nt = 0; nt < 4; nt++) {
                int cb = warpN * 32 + nt * 8 + group;
                const __half* q = Bs + cb * HSTR + kb;
                bf[nt][0] = *(const unsigned*)q;
                bf[nt][1] = *(const unsigned*)(q + 8);
            }
#pragma unroll
            for (int mt = 0; mt < 4; mt++)
#pragma unroll
                for (int nt = 0; nt < 4; nt++)
                    MMA_F16(acc[mt][nt], af[mt], bf[nt]);
        }
        __syncthreads();
    }

#pragma unroll
    for (int mt = 0; mt < 4; mt++) {
        int r0 = mBase + warpM * 64 + mt * 16 + group;
        int r1 = r0 + 8;
#pragma unroll
        for (int nt = 0; nt < 4; nt++) {
            int cc = nBase + warpN * 32 + nt * 8 + 2 * qt;
            float x0, x1;
            if (r0 < M) st2(C, (size_t)r0 * NC + cc, acc[mt][nt][0], acc[mt][nt][1], x0, x1);
            if (r1 < M) st2(C, (size_t)r1 * NC + cc, acc[mt][nt][2], acc[mt][nt][3], x0, x1);
        }
    }
}

// ================= FP16 HMMA GEMM (half A [M][K], half B n-major [NC][K]) ==========
#define SMEM_BYTES_H (4 * HA_TILE * 2 + 2048)   // 2 A-bufs + 2 B-bufs + BN = 43008

template <typename TC, bool FUSE_BN, bool SWAP>
__global__ __launch_bounds__(256, 2) void k_mma_h(
    const __half* __restrict__ A, const __half* __restrict__ Bt,
    TC* __restrict__ C, int M, int K, int NC,
    float* __restrict__ sumO, float* __restrict__ sqO,
    const float* __restrict__ aSum, const float* __restrict__ aSq,
    const float* __restrict__ aG, const float* __restrict__ aBt, float aInv)
{
    extern __shared__ char dsmRaw[];
    __half* AsB = (__half*)dsmRaw;
    __half* BsB = (__half*)(dsmRaw + 2 * HA_TILE * 2);
    float* scS = (float*)(dsmRaw + 4 * HA_TILE * 2);
    float* shS = scS + 256;

    const int tid = threadIdx.x;
    const int lane = tid & 31, warp = tid >> 5;
    const int group = lane >> 2, qt = lane & 3;
    const int warpM = warp & 1, warpN = warp >> 1;
    const int mBase = (SWAP ? blockIdx.y : blockIdx.x) * 128;
    const int nBase = (SWAP ? blockIdx.x : blockIdx.y) * 128;
    const int nk = K >> 5;

    if (FUSE_BN) {
        if (tid < K) {
            float mean = aSum[tid] * aInv;
            float var  = aSq[tid] * aInv - mean * mean;
            float s = aG[tid] * rsqrtf(var + 1e-5f);
            scS[tid] = s; shS[tid] = aBt[tid] - mean * s;
        }
        __syncthreads();
    }

    const int arow = tid >> 2, akq = (tid & 3) << 3;  // halfs: TPR=4, RPI=64

    auto issue = [&](int i, int b) {
        const int k0 = i << 5;
        __half* As = AsB + b * HA_TILE;
        __half* Bs = BsB + b * HA_TILE;
#pragma unroll
        for (int it = 0; it < 2; it++) {
            int row = arow + it * 64;
            int gm = mBase + row;
            const __half* src = A + (size_t)(gm < M ? gm : 0) * K + k0 + akq;
            cpasync16(As + row * HSTR + akq, src, gm < M ? 16 : 0);
        }
#pragma unroll
        for (int it = 0; it < 2; it++) {
            int row = arow + it * 64;
            const __half* src = Bt + (size_t)(nBase + row) * K + k0 + akq;
            cpasync16(Bs + row * HSTR + akq, src, 16);
        }
        cpasync_commit();
    };

    float acc[4][4][4];
#pragma unroll
    for (int mt = 0; mt < 4; mt++)
#pragma unroll
        for (int nt = 0; nt < 4; nt++)
#pragma unroll
            for (int i = 0; i < 4; i++) acc[mt][nt][i] = 0.0f;

    issue(0, 0);
    for (int i = 0; i < nk; i++) {
        if (i + 1 < nk) { issue(i + 1, (i + 1) & 1); cpasync_wait<1>(); }
        else            { cpasync_wait<0>(); }
        __syncthreads();
        const __half* As = AsB + (i & 1) * HA_TILE;
        const __half* Bs = BsB + (i & 1) * HA_TILE;
        const int k0 = i << 5;
#pragma unroll
        for (int ks = 0; ks < 2; ks++) {
            const int kb = ks * 16 + 2 * qt;
            unsigned af[4][4], bf[4][2];
            float sc0, sh0, sc1, sh1, sc8, sh8, sc9, sh9;
            if (FUSE_BN) {
                int g = k0 + kb;
                sc0 = scS[g];     sh0 = shS[g];
                sc1 = scS[g + 1]; sh1 = shS[g + 1];
                sc8 = scS[g + 8]; sh8 = shS[g + 8];
                sc9 = scS[g + 9]; sh9 = shS[g + 9];
            }
#pragma unroll
            for (int mt = 0; mt < 4; mt++) {
                int r = warpM * 64 + mt * 16 + group;
                const __half* p0 = As + r * HSTR + kb;
                const __half* p1 = As + (r + 8) * HSTR + kb;
                if (FUSE_BN) {
                    float2 v0 = __half22float2(*(const __half2*)p0);
                    float2 v1 = __half22float2(*(const __half2*)p1);
                    float2 v2 = __half22float2(*(const __half2*)(p0 + 8));
                    float2 v3 = __half22float2(*(const __half2*)(p1 + 8));
                    af[mt][0] = h2u(__floats2half2_rn(
                        fmaxf(fmaf(v0.x, sc0, sh0), 0.f), fmaxf(fmaf(v0.y, sc1, sh1), 0.f)));
                    af[mt][1] = h2u(__floats2half2_rn(
                        fmaxf(fmaf(v1.x, sc0, sh0), 0.f), fmaxf(fmaf(v1.y, sc1, sh1), 0.f)));
                    af[mt][2] = h2u(__floats2half2_rn(
                        fmaxf(fmaf(v2.x, sc8, sh8), 0.f), fmaxf(fmaf(v2.y, sc9, sh9), 0.f)));
                    af[mt][3] = h2u(__floats2half2_rn(
                        fmaxf(fmaf(v3.x, sc8, sh8), 0.f), fmaxf(fmaf(v3.y, sc9, sh9), 0.f)));
                } else {
                    af[mt][0] = *(const unsigned*)p0;
                    af[mt][1] = *(const unsigned*)p1;
                    af[mt][2] = *(const unsigned*)(p0 + 8);
                    af[mt][3] = *(const unsigned*)(p1 + 8);
                }
            }
#pragma unroll
            for (int nt = 0; nt < 4; nt++) {
                int cb = warpN * 32 + nt * 8 + group;
                const __half* q = Bs + cb * HSTR + kb;
                bf[nt][0] = *(const unsigned*)q;
                bf[nt][1] = *(const unsigned*)(q + 8);
            }
#pragma unroll
            for (int mt = 0; mt < 4; mt++)
#pragma unroll
                for (int nt = 0; nt < 4; nt++)
                    MMA_F16(acc[mt][nt], af[mt], bf[nt]);
        }
        __syncthreads();
    }

    // epilogue: store + BN stats (on stored values)
    float cs[4][2], cq[4][2];
#pragma unroll
    for (int nt = 0; nt < 4; nt++) { cs[nt][0] = cs[nt][1] = 0.f; cq[nt][0] = cq[nt][1] = 0.f; }
#pragma unroll
    for (int mt = 0; mt < 4; mt++) {
        int r0 = mBase + warpM * 64 + mt * 16 + group;
        int r1 = r0 + 8;
#pragma unroll
        for (int nt = 0; nt < 4; nt++) {
            int cc = nBase + warpN * 32 + nt * 8 + 2 * qt;
            float x0, x1;
            if (r0 < M) {
                st2(C, (size_t)r0 * NC + cc, acc[mt][nt][0], acc[mt][nt][1], x0, x1);
                cs[nt][0] += x0; cs[nt][1] += x1;
                cq[nt][0] += x0 * x0; cq[nt][1] += x1 * x1;
            }
            if (r1 < M) {
                st2(C, (size_t)r1 * NC + cc, acc[mt][nt][2], acc[mt][nt][3], x0, x1);
                cs[nt][0] += x0; cs[nt][1] += x1;
                cq[nt][0] += x0 * x0; cq[nt][1] += x1 * x1;
            }
        }
    }
    if (sumO) {
#pragma unroll
        for (int off = 4; off < 32; off <<= 1) {
#pragma unroll
            for (int nt = 0; nt < 4; nt++) {
#pragma unroll
                for (int p = 0; p < 2; p++) {
                    cs[nt][p] += __shfl_xor_sync(0xffffffffu, cs[nt][p], off);
                    cq[nt][p] += __shfl_xor_sync(0xffffffffu, cq[nt][p], off);
                }
            }
        }
        if (group == 0) {
#pragma unroll
            for (int nt = 0; nt < 4; nt++) {
                int cc = nBase + warpN * 32 + nt * 8 + 2 * qt;
                atomicAdd(sumO + cc,     cs[nt][0]);
                atomicAdd(sumO + cc + 1, cs[nt][1]);
                atomicAdd(sqO  + cc,     cq[nt][0]);
                atomicAdd(sqO  + cc + 1, cq[nt][1]);
            }
        }
    }
}

// ---------------- combine (half2 vectorized) ----------------
__global__ void k_combine() {
    int c = threadIdx.x & 63;
    int eo = threadIdx.x >> 6;
    float ls0 = 0.f, ls1 = 0.f, lq0 = 0.f, lq1 = 0.f;
    const __half2* a0 = (const __half2*)s_a0;
    const __half2* a1 = (const __half2*)s_a1;
    const __half2* ew = (const __half2*)s_ew2;
    __half2* pre = (__half2*)s_pre1;
    for (int e = blockIdx.x * 2 + eo; e < NE; e += gridDim.x * 2) {
        int u = s_u[e], v = s_v[e];
        float2 a0u = __half22float2(a0[(size_t)u * 64 + c]);
        float2 a0v = __half22float2(a0[(size_t)v * 64 + c]);
        float2 a1u = __half22float2(a1[(size_t)u * 64 + c]);
        float2 a1v = __half22float2(a1[(size_t)v * 64 + c]);
        float bx = a0u.x + a0v.x, by = a0u.y + a0v.y;
        size_t r0 = (size_t)(2 * e) * 64 + c, r1 = (size_t)(2 * e + 1) * 64 + c;
        float2 e0 = __half22float2(ew[r0]);
        float2 e1 = __half22float2(ew[r1]);
        __half2 h0 = __floats2half2_rn(bx + a1u.x + e0.x, by + a1u.y + e0.y);
        __half2 h1 = __floats2half2_rn(bx + a1v.x + e1.x, by + a1v.y + e1.y);
        pre[r0] = h0; pre[r1] = h1;
        float2 q0 = __half22float2(h0), q1 = __half22float2(h1);
        ls0 += q0.x + q1.x; ls1 += q0.y + q1.y;
        lq0 += q0.x * q0.x + q1.x * q1.x; lq1 += q0.y * q0.y + q1.y * q1.y;
    }
    atomicAdd(&s_sum[2 * c],     ls0);
    atomicAdd(&s_sum[2 * c + 1], ls1);
    atomicAdd(&s_sq[2 * c],      lq0);
    atomicAdd(&s_sq[2 * c + 1],  lq1);
}

// CSR gather: nin[n] = e11*nr[n] + sum_entries[(2+eps12)*h_r + h_sib]
__global__ void k_gather_nin(const float* __restrict__ nr,
                             const float* __restrict__ g, const float* __restrict__ b,
                             const float* __restrict__ eps12p,
                             const float* __restrict__ eps11p) {
    int n = blockIdx.x;
    int c = threadIdx.x;
    float mean = s_sum[c] * (1.0f / TE);
    float var  = s_sq[c]  * (1.0f / TE) - mean * mean;
    float sc = g[c] * rsqrtf(var + 1e-5f);
    float sh = b[c] - mean * sc;
    float cf = 2.0f + *eps12p;
    float e11 = 1.0f + *eps11p;
    int beg = s_rowptr[n], end = s_rowptr[n + 1];
    float acc = 0.f;
    for (int j = beg; j < end; j++) {
        int r = s_csr[j];
        int sIb = r ^ 1;
        float hr = fmaxf(__half2float(s_pre1[(size_t)r  * 128 + c]) * sc + sh, 0.f);
        float hs = fmaxf(__half2float(s_pre1[(size_t)sIb * 128 + c]) * sc + sh, 0.f);
        acc += cf * hr + hs;
    }
    s_nin[(size_t)n * 128 + c] = __float2half_rn(e11 * nr[(size_t)n * 128 + c] + acc);
}

__global__ void k_ein(const float* __restrict__ er, const float* __restrict__ nr,
                      const float* __restrict__ eps2p) {
    int c = threadIdx.x & 63;
    int eo = threadIdx.x >> 6;
    float e2 = 1.0f + *eps2p;
    float e2h = 0.5f * e2;
    const float2* er2 = (const float2*)er;
    const float2* nr2 = (const float2*)nr;
    __half2* ein = (__half2*)s_ein;
    for (int e = blockIdx.x * 2 + eo; e < NE; e += gridDim.x * 2) {
        int u = s_u[e], v = s_v[e];
        float2 a = er2[(size_t)(2 * e) * 64 + c];
        float2 bq = er2[(size_t)(2 * e + 1) * 64 + c];
        float2 p = nr2[(size_t)u * 64 + c];
        float2 q = nr2[(size_t)v * 64 + c];
        __half2 fh = __floats2half2_rn(e2h * (a.x + bq.x) + p.x + q.x,
                                       e2h * (a.y + bq.y) + p.y + q.y);
        size_t r0 = (size_t)(2 * e) * 128 + c, r1 = (size_t)(2 * e + 1) * 128 + c;
        ein[r0] = fh;
        ein[r1] = fh;
        ein[r0 + 64] = __floats2half2_rn(e2 * a.x + p.x,  e2 * a.y + p.y);
        ein[r1 + 64] = __floats2half2_rn(e2 * bq.x + q.x, e2 * bq.y + q.y);
    }
}

// dst = relu(src*scale + shift), float4 vectorized
__global__ void k_bnapply4(const float4* __restrict__ src, float4* __restrict__ dst,
                           int rows, int col4Mask,
                           const float* __restrict__ sum, const float* __restrict__ sq,
                           const float* __restrict__ g, const float* __restrict__ b,
                           float inv) {
    size_t n = (size_t)rows * (col4Mask + 1);
    size_t stride = (size_t)gridDim.x * blockDim.x;
    for (size_t i = (size_t)blockIdx.x * blockDim.x + threadIdx.x; i < n; i += stride) {
        int c = (int)(i & (size_t)col4Mask) << 2;
        float4 v = src[i];
        float4 o;
#pragma unroll
        for (int j = 0; j < 4; j++) {
            float mean = sum[c + j] * inv;
            float var  = sq[c + j] * inv - mean * mean;
            float scv = g[c + j] * rsqrtf(var + 1e-5f);
            float shv = b[c + j] - mean * scv;
            float x = (&v.x)[j] * scv + shv;
            (&o.x)[j] = fmaxf(x, 0.f);
        }
        dst[i] = o;
    }
}

// ---------------- launch ----------------
extern "C" void kernel_launch(void* const* d_in, const int* in_sizes, int n_in,
                              void* d_out, int out_size) {
    const float* nr      = (const float*)d_in[0];
    const float* er      = (const float*)d_in[1];
    const void*  ei      = d_in[2];
    const float* lift_w1 = (const float*)d_in[3];
    const float* lift_g1 = (const float*)d_in[4];
    const float* lift_b1 = (const float*)d_in[5];
    const float* lift_w2 = (const float*)d_in[6];
    const float* lift_g2 = (const float*)d_in[7];
    const float* lift_b2 = (const float*)d_in[8];
    const float* lvl1_w  = (const float*)d_in[9];
    const float* lvl1_g  = (const float*)d_in[10];
    const float* lvl1_b  = (const float*)d_in[11];
    const float* lvl2_w1 = (const float*)d_in[12];
    const float* lvl2_g1 = (const float*)d_in[13];
    const float* lvl2_b1 = (const float*)d_in[14];
    const float* lvl2_w2 = (const float*)d_in[15];
    const float* lvl2_g2 = (const float*)d_in[16];
    const float* lvl2_b2 = (const float*)d_in[17];
    const float* eps11   = (const float*)d_in[18];
    const float* eps12   = (const float*)d_in[19];
    const float* eps2    = (const float*)d_in[20];

    float* out_node = (float*)d_out;
    float* out_edge = out_node + (size_t)NN * HH;

    __half *p_ew2, *p_a0, *p_a1, *p_nin, *p_np1, *p_ein, *p_ep1;
    __half *p_wnp1, *p_wnp2, *p_wep1, *p_wep2, *p_wl1;
    float *p_np2, *p_ep2, *p_sum, *p_sq;
    cudaGetSymbolAddress((void**)&p_ew2, s_ew2);
    cudaGetSymbolAddress((void**)&p_a0,  s_a0);
    cudaGetSymbolAddress((void**)&p_a1,  s_a1);
    cudaGetSymbolAddress((void**)&p_nin, s_nin);
    cudaGetSymbolAddress((void**)&p_np1, s_np1);
    cudaGetSymbolAddress((void**)&p_np2, s_np2);
    cudaGetSymbolAddress((void**)&p_ein, s_ein);
    cudaGetSymbolAddress((void**)&p_ep1, s_ep1);
    cudaGetSymbolAddress((void**)&p_ep2, s_ep2);
    cudaGetSymbolAddress((void**)&p_sum, s_sum);
    cudaGetSymbolAddress((void**)&p_sq,  s_sq);
    cudaGetSymbolAddress((void**)&p_wnp1, w_np1h);
    cudaGetSymbolAddress((void**)&p_wnp2, w_np2h);
    cudaGetSymbolAddress((void**)&p_wep1, w_ep1h);
    cudaGetSymbolAddress((void**)&p_wep2, w_ep2h);
    cudaGetSymbolAddress((void**)&p_wl1,  w_l1h);

    static cudaStream_t s_edge = nullptr, s_csrS = nullptr;
    static cudaEvent_t ev_fork = nullptr, ev_edge = nullptr, ev_csr = nullptr;
    static int smem_set = 0;
    if (!smem_set) {
        cudaFuncSetAttribute((const void*)k_mma_fh,
                             cudaFuncAttributeMaxDynamicSharedMemorySize, SMEM_BYTES_FH);
        cudaFuncSetAttribute((const void*)k_mma_h<__half, false, true>,
                             cudaFuncAttributeMaxDynamicSharedMemorySize, SMEM_BYTES_H);
        cudaFuncSetAttribute((const void*)k_mma_h<float, true, false>,
                             cudaFuncAttributeMaxDynamicSharedMemorySize, SMEM_BYTES_H);
        cudaStreamCreateWithFlags(&s_edge, cudaStreamNonBlocking);
        cudaStreamCreateWithFlags(&s_csrS, cudaStreamNonBlocking);
        cudaEventCreateWithFlags(&ev_fork, cudaEventDisableTiming);
        cudaEventCreateWithFlags(&ev_edge, cudaEventDisableTiming);
        cudaEventCreateWithFlags(&ev_csr,  cudaEventDisableTiming);
        smem_set = 1;
    }

    const int GN  = (NN + 127) / 128;  // 157
    const int GTE = TE / 128;          // 2500

    // -------- pre-fork (stream 0): shared prerequisites --------
    k_zero<<<(NN + 255) / 256, 256>>>();
    k_detect<<<1, 32>>>((const int*)ei);
    k_decode<<<(NE + 255) / 256, 256>>>(ei);
    k_wprep<<<256, 256>>>(lvl2_w1, lvl2_w2, lift_w1, lift_w2, lvl1_w);
    cudaEventRecord(ev_fork, 0);

    // -------- CSR build (s_csrS): overlapped with GEMM chains --------
    cudaStreamWaitEvent(s_csrS, ev_fork, 0);
    k_hist<<<(NE + 255) / 256, 256, 0, s_csrS>>>();
    k_scan<<<1, 1024, 0, s_csrS>>>();
    k_place<<<(NE + 255) / 256, 256, 0, s_csrS>>>();
    cudaEventRecord(ev_csr, s_csrS);

    // -------- edge chain (s_edge): independent of the lvl1/node path --------
    cudaStreamWaitEvent(s_edge, ev_fork, 0);
    k_ein<<<2048, 128, 0, s_edge>>>(er, nr, eps2);
    k_mma_h<__half, false, true><<<dim3(2, GTE), 256, SMEM_BYTES_H, s_edge>>>(
        p_ein, p_wep1, p_ep1, TE, 256, 256,
        p_sum + 768, p_sq + 768, nullptr, nullptr, nullptr, nullptr, 0.f);
    k_mma_h<float, true, false><<<dim3(GTE, 1), 256, SMEM_BYTES_H, s_edge>>>(
        p_ep1, p_wep2, p_ep2, TE, 256, 128,
        p_sum + 1024, p_sq + 1024,
        p_sum + 768, p_sq + 768, lift_g1, lift_b1, 1.0f / TE);
    k_bnapply4<<<4096, 256, 0, s_edge>>>((const float4*)p_ep2, (float4*)out_edge, TE, 31,
                              p_sum + 1024, p_sq + 1024, lift_g2, lift_b2, 1.0f / TE);
    cudaEventRecord(ev_edge, s_edge);

    // -------- node chain (stream 0): lvl1 GEMMs now HMMA (fp32 A, fp16 W) --------
    k_mma_fh<<<dim3(GTE, 1), 256, SMEM_BYTES_FH>>>(er, p_wl1 + 2 * 16384, p_ew2, TE, 128, 128);
    k_mma_fh<<<dim3(GN, 1),  256, SMEM_BYTES_FH>>>(nr, p_wl1,             p_a0,  NN, 128, 128);
    k_mma_fh<<<dim3(GN, 1),  256, SMEM_BYTES_FH>>>(nr, p_wl1 + 16384,     p_a1,  NN, 128, 128);

    k_combine<<<2048, 128>>>();                             // stats slot 0, pre1 half

    cudaStreamWaitEvent(0, ev_csr, 0);
    k_gather_nin<<<NN, 128>>>(nr, lvl1_g, lvl1_b, eps12, eps11);  // BN+aggregate+nin fused

    k_mma_h<__half, false, true><<<dim3(2, GN), 256, SMEM_BYTES_H>>>(
        p_nin, p_wnp1, p_np1, NN, 128, 256,
        p_sum + 256, p_sq + 256, nullptr, nullptr, nullptr, nullptr, 0.f);
    k_mma_h<float, true, false><<<dim3(GN, 1), 256, SMEM_BYTES_H>>>(
        p_np1, p_wnp2, p_np2, NN, 256, 128,
        p_sum + 512, p_sq + 512,
        p_sum + 256, p_sq + 256, lvl2_g1, lvl2_b1, 1.0f / NN);
    k_bnapply4<<<2048, 256>>>((const float4*)p_np2, (float4*)out_node, NN, 31,
                              p_sum + 512, p_sq + 512, lvl2_g2, lvl2_b2, 1.0f / NN);

    // -------- join: graph end depends on both chains --------
    cudaStreamWaitEvent(0, ev_edge, 0);
}

// round 14
// speedup vs baseline: 1.4619x; 1.0568x over previous
#include <cuda_runtime.h>
#include <cuda_fp16.h>
#include <cstring>

#define NN 20000      // nodes
#define NE 160000     // edges
#define TE 320000     // 2E edge-rows
#define HH 128

// ---------------- scratch (static __device__, no allocs) ----------------
__device__ __align__(128) __half s_ew2 [(size_t)TE * 128];   // er @ W2
__device__ __align__(128) __half s_a0  [(size_t)NN * 128];   // nr @ W0
__device__ __align__(128) __half s_a1  [(size_t)NN * 128];   // nr @ W1
__device__ __align__(128) __half s_pre1[(size_t)TE * 128];   // lvl1 pre-act
__device__ __align__(128) __half s_nin [(size_t)NN * 128];
__device__ __align__(128) __half s_np1 [(size_t)NN * 256];
__device__ __align__(128) __half s_np2 [(size_t)NN * 128];   // final pre-act (half)
__device__ __align__(128) __half s_ein [(size_t)TE * 256];
__device__ __align__(128) __half s_ep1 [(size_t)TE * 256];
__device__ __align__(128) __half s_ep2 [(size_t)TE * 128];   // final pre-act (half)
// fp16 weights, pre-transposed to n-major [N][K]
__device__ __align__(128) __half w_np1h[256 * 128];
__device__ __align__(128) __half w_np2h[128 * 256];
__device__ __align__(128) __half w_ep1h[256 * 256];
__device__ __align__(128) __half w_ep2h[128 * 256];
__device__ __align__(128) __half w_l1h [3 * 128 * 128];   // lvl1 W blocks 0,1,2 n-major
// CSR: node -> incident edge-rows
__device__ int s_deg[NN];
__device__ int s_rowptr[NN + 1];
__device__ int s_cursor[NN];
__device__ int s_csr[TE];
__device__ float s_sum[5 * 256];
__device__ float s_sq [5 * 256];
__device__ int   s_u[NE];
__device__ int   s_v[NE];
__device__ int   g_is64;

// ---------------- helpers ----------------
__device__ __forceinline__ unsigned h2u(__half2 h) {
    unsigned u;
    memcpy(&u, &h, 4);
    return u;
}

__global__ void k_zero() {
    int i0 = blockIdx.x * blockDim.x + threadIdx.x;
    if (i0 < NN) s_deg[i0] = 0;
    if (i0 < 5 * 256) { s_sum[i0] = 0.0f; s_sq[i0] = 0.0f; }
}

__global__ void k_detect(const int* __restrict__ ei32) {
    if (threadIdx.x == 0 && blockIdx.x == 0) {
        int nz = 0;
        for (int i = 0; i < 256; i++) nz |= ei32[2 * i + 1];
        g_is64 = (nz == 0) ? 1 : 0;
    }
}

__global__ void k_decode(const void* __restrict__ ei) {
    int e = blockIdx.x * blockDim.x + threadIdx.x;
    if (e >= NE) return;
    if (g_is64) {
        const long long* p = (const long long*)ei;
        s_u[e] = (int)p[e];
        s_v[e] = (int)p[NE + e];
    } else {
        const int* p = (const int*)ei;
        s_u[e] = p[e];
        s_v[e] = p[NE + e];
    }
}

// ---- CSR build ----
__global__ void k_hist() {
    int e = blockIdx.x * blockDim.x + threadIdx.x;
    if (e >= NE) return;
    atomicAdd(&s_deg[s_u[e]], 1);
    atomicAdd(&s_deg[s_v[e]], 1);
}

__global__ void k_scan() {   // single block, 1024 threads; 20 nodes/thread
    __shared__ int ts[1024];
    int t = threadIdx.x;
    int base = t * 20;
    int lv[20];
    int loc = 0;
#pragma unroll
    for (int i = 0; i < 20; i++) {
        int n = base + i;
        lv[i] = (n < NN) ? s_deg[n] : 0;
        loc += lv[i];
    }
    ts[t] = loc;
    __syncthreads();
    for (int off = 1; off < 1024; off <<= 1) {
        int v = (t >= off) ? ts[t - off] : 0;
        __syncthreads();
        ts[t] += v;
        __syncthreads();
    }
    int run = ts[t] - loc;   // exclusive prefix
#pragma unroll
    for (int i = 0; i < 20; i++) {
        int n = base + i;
        if (n < NN) {
            s_rowptr[n] = run;
            s_cursor[n] = run;
            run += lv[i];
        }
    }
    if (t == 1023) s_rowptr[NN] = ts[1023];
}

__global__ void k_place() {
    int e = blockIdx.x * blockDim.x + threadIdx.x;
    if (e >= NE) return;
    int p0 = atomicAdd(&s_cursor[s_u[e]], 1);
    s_csr[p0] = 2 * e;
    int p1 = atomicAdd(&s_cursor[s_v[e]], 1);
    s_csr[p1] = 2 * e + 1;
}

// convert + transpose weights to fp16 n-major
__global__ void k_wprep(const float* __restrict__ w_np1, const float* __restrict__ w_np2,
                        const float* __restrict__ w_ep1, const float* __restrict__ w_ep2,
                        const float* __restrict__ w_l1) {
    int i = blockIdx.x * blockDim.x + threadIdx.x;   // 65536 threads
    if (i < 256 * 128) {            // np1: [128][256] -> [256][128]
        int n = i >> 7, k = i & 127;
        w_np1h[i] = __float2half_rn(w_np1[k * 256 + n]);
    }
    if (i < 128 * 256) {            // np2: [256][128] -> [128][256]
        int n = i >> 8, k = i & 255;
        w_np2h[i] = __float2half_rn(w_np2[k * 128 + n]);
    }
    if (i < 256 * 256) {            // ep1: [256][256] -> transposed
        int n = i >> 8, k = i & 255;
        w_ep1h[i] = __float2half_rn(w_ep1[k * 256 + n]);
    }
    if (i < 128 * 256) {            // ep2: [256][128] -> [128][256]
        int n = i >> 8, k = i & 255;
        w_ep2h[i] = __float2half_rn(w_ep2[k * 128 + n]);
    }
    if (i < 3 * 128 * 128) {        // lvl1 blocks: [384][128] -> 3x [128][128] n-major
        int blk = i >> 14, rem = i & 16383;
        int n = rem >> 7, k = rem & 127;
        w_l1h[i] = __float2half_rn(w_l1[(blk * 128 + k) * 128 + n]);
    }
}

__device__ __forceinline__ void cpasync16(void* smem_ptr, const void* gptr, int src_bytes) {
    unsigned saddr = (unsigned)__cvta_generic_to_shared(smem_ptr);
    asm volatile("cp.async.cg.shared.global [%0], [%1], 16, %2;"
                 :: "r"(saddr), "l"(gptr), "r"(src_bytes));
}
__device__ __forceinline__ void cpasync_commit() {
    asm volatile("cp.async.commit_group;");
}
template <int N>
__device__ __forceinline__ void cpasync_wait() {
    asm volatile("cp.async.wait_group %0;" :: "n"(N));
}

#define MMA_F16(d, Af, Bf)                                                      \
    asm volatile(                                                               \
        "mma.sync.aligned.m16n8k16.row.col.f32.f16.f16.f32 "                    \
        "{%0,%1,%2,%3},{%4,%5,%6,%7},{%8,%9},{%0,%1,%2,%3};"                    \
        : "+f"(d[0]), "+f"(d[1]), "+f"(d[2]), "+f"(d[3])                        \
        : "r"(Af[0]), "r"(Af[1]), "r"(Af[2]), "r"(Af[3]),                       \
          "r"(Bf[0]), "r"(Bf[1]))

// typed stores (stats on stored/rounded values)
__device__ __forceinline__ void st2(float* C, size_t off, float c0, float c1,
                                    float& r0, float& r1) {
    *(float2*)(C + off) = make_float2(c0, c1);
    r0 = c0; r1 = c1;
}
__device__ __forceinline__ void st2(__half* C, size_t off, float c0, float c1,
                                    float& r0, float& r1) {
    __half2 h = __floats2half2_rn(c0, c1);
    *(__half2*)(C + off) = h;
    r0 = __low2float(h); r1 = __high2float(h);
}

#define HSTR 40
#define HA_TILE (128 * HSTR)

// ======== HMMA GEMM, fp32 A (cvt at smem->reg), fp16 n-major B, half C ========
#define AF_STRIDE 36
#define SMEM_BYTES_FH (2 * 128 * AF_STRIDE * 4 + 2 * HA_TILE * 2 + 1024)  // 58368

__global__ __launch_bounds__(256, 2) void k_mma_fh(
    const float* __restrict__ A, const __half* __restrict__ Bt,
    __half* __restrict__ C, int M, int K, int NC)
{
    extern __shared__ char dsmRaw[];
    float* AsB = (float*)dsmRaw;
    __half* BsB = (__half*)(dsmRaw + 2 * 128 * AF_STRIDE * 4);

    const int tid = threadIdx.x;
    const int lane = tid & 31, warp = tid >> 5;
    const int group = lane >> 2, qt = lane & 3;
    const int warpM = warp & 1, warpN = warp >> 1;
    const int mBase = blockIdx.x * 128, nBase = blockIdx.y * 128;
    const int nk = K >> 5;

    const int arow = tid >> 3, akq = (tid & 7) << 2;     // fp32: 8 thr/row
    const int brow = tid >> 2, bkq = (tid & 3) << 3;     // fp16: 4 thr/row

    auto issue = [&](int i, int b) {
        const int k0 = i << 5;
        float* As = AsB + b * 128 * AF_STRIDE;
        __half* Bs = BsB + b * HA_TILE;
#pragma unroll
        for (int it = 0; it < 4; it++) {
            int row = arow + it * 32;
            int gm = mBase + row;
            const float* src = A + (size_t)(gm < M ? gm : 0) * K + k0 + akq;
            cpasync16(As + row * AF_STRIDE + akq, src, gm < M ? 16 : 0);
        }
#pragma unroll
        for (int it = 0; it < 2; it++) {
            int row = brow + it * 64;
            const __half* src = Bt + (size_t)(nBase + row) * K + k0 + bkq;
            cpasync16(Bs + row * HSTR + bkq, src, 16);
        }
        cpasync_commit();
    };

    float acc[4][4][4];
#pragma unroll
    for (int mt = 0; mt < 4; mt++)
#pragma unroll
        for (int nt = 0; nt < 4; nt++)
#pragma unroll
            for (int i = 0; i < 4; i++) acc[mt][nt][i] = 0.0f;

    issue(0, 0);
    for (int i = 0; i < nk; i++) {
        if (i + 1 < nk) { issue(i + 1, (i + 1) & 1); cpasync_wait<1>(); }
        else            { cpasync_wait<0>(); }
        __syncthreads();
        const float* As = AsB + (i & 1) * 128 * AF_STRIDE;
        const __half* Bs = BsB + (i & 1) * HA_TILE;
#pragma unroll
        for (int ks = 0; ks < 2; ks++) {
            const int kb = ks * 16 + 2 * qt;
            unsigned af[4][4], bf[4][2];
#pragma unroll
            for (int mt = 0; mt < 4; mt++) {
                int r = warpM * 64 + mt * 16 + group;
                float2 v0 = *(const float2*)(As + r * AF_STRIDE + kb);
                float2 v1 = *(const float2*)(As + (r + 8) * AF_STRIDE + kb);
                float2 v2 = *(const float2*)(As + r * AF_STRIDE + kb + 8);
                float2 v3 = *(const float2*)(As + (r + 8) * AF_STRIDE + kb + 8);
                af[mt][0] = h2u(__floats2half2_rn(v0.x, v0.y));
                af[mt][1] = h2u(__floats2half2_rn(v1.x, v1.y));
                af[mt][2] = h2u(__floats2half2_rn(v2.x, v2.y));
                af[mt][3] = h2u(__floats2half2_rn(v3.x, v3.y));
            }
#pragma unroll
            for (int nt = 0; nt < 4; nt++) {
                int cb = warpN * 32 + nt * 8 + group;
                const __half* q = Bs + cb * HSTR + kb;
                bf[nt][0] = *(const unsigned*)q;
                bf[nt][1] = *(const unsigned*)(q + 8);
            }
#pragma unroll
            for (int mt = 0; mt < 4; mt++)
#pragma unroll
                for (int nt = 0; nt < 4; nt++)
                    MMA_F16(acc[mt][nt], af[mt], bf[nt]);
        }
        __syncthreads();
    }

#pragma unroll
    for (int mt = 0; mt < 4; mt++) {
        int r0 = mBase + warpM * 64 + mt * 16 + group;
        int r1 = r0 + 8;
#pragma unroll
        for (int nt = 0; nt < 4; nt++) {
            int cc = nBase + warpN * 32 + nt * 8 + 2 * qt;
            float x0, x1;
            if (r0 < M) st2(C, (size_t)r0 * NC + cc, acc[mt][nt][0], acc[mt][nt][1], x0, x1);
            if (r1 < M) st2(C, (size_t)r1 * NC + cc, acc[mt][nt][2], acc[mt][nt][3], x0, x1);
        }
    }
}

// ================= FP16 HMMA GEMM (half A [M][K], half B n-major [NC][K]) ==========
#define SMEM_BYTES_H (4 * HA_TILE * 2 + 2048)   // 2 A-bufs + 2 B-bufs + BN = 43008

template <typename TC, bool FUSE_BN, bool SWAP>
__global__ __launch_bounds__(256, 2) void k_mma_h(
    const __half* __restrict__ A, const __half* __restrict__ Bt,
    TC* __restrict__ C, int M, int K, int NC,
    float* __restrict__ sumO, float* __restrict__ sqO,
    const float* __restrict__ aSum, const float* __restrict__ aSq,
    const float* __restrict__ aG, const float* __restrict__ aBt, float aInv)
{
    extern __shared__ char dsmRaw[];
    __half* AsB = (__half*)dsmRaw;
    __half* BsB = (__half*)(dsmRaw + 2 * HA_TILE * 2);
    float* scS = (float*)(dsmRaw + 4 * HA_TILE * 2);
    float* shS = scS + 256;

    const int tid = threadIdx.x;
    const int lane = tid & 31, warp = tid >> 5;
    const int group = lane >> 2, qt = lane & 3;
    const int warpM = warp & 1, warpN = warp >> 1;
    const int mBase = (SWAP ? blockIdx.y : blockIdx.x) * 128;
    const int nBase = (SWAP ? blockIdx.x : blockIdx.y) * 128;
    const int nk = K >> 5;

    if (FUSE_BN) {
        if (tid < K) {
            float mean = aSum[tid] * aInv;
            float var  = aSq[tid] * aInv - mean * mean;
            float s = aG[tid] * rsqrtf(var + 1e-5f);
            scS[tid] = s; shS[tid] = aBt[tid] - mean * s;
        }
        __syncthreads();
    }

    const int arow = tid >> 2, akq = (tid & 3) << 3;  // halfs: TPR=4, RPI=64

    auto issue = [&](int i, int b) {
        const int k0 = i << 5;
        __half* As = AsB + b * HA_TILE;
        __half* Bs = BsB + b * HA_TILE;
#pragma unroll
        for (int it = 0; it < 2; it++) {
            int row = arow + it * 64;
            int gm = mBase + row;
            const __half* src = A + (size_t)(gm < M ? gm : 0) * K + k0 + akq;
            cpasync16(As + row * HSTR + akq, src, gm < M ? 16 : 0);
        }
#pragma unroll
        for (int it = 0; it < 2; it++) {
            int row = arow + it * 64;
            const __half* src = Bt + (size_t)(nBase + row) * K + k0 + akq;
            cpasync16(Bs + row * HSTR + akq, src, 16);
        }
        cpasync_commit();
    };

    float acc[4][4][4];
#pragma unroll
    for (int mt = 0; mt < 4; mt++)
#pragma unroll
        for (int nt = 0; nt < 4; nt++)
#pragma unroll
            for (int i = 0; i < 4; i++) acc[mt][nt][i] = 0.0f;

    issue(0, 0);
    for (int i = 0; i < nk; i++) {
        if (i + 1 < nk) { issue(i + 1, (i + 1) & 1); cpasync_wait<1>(); }
        else            { cpasync_wait<0>(); }
        __syncthreads();
        const __half* As = AsB + (i & 1) * HA_TILE;
        const __half* Bs = BsB + (i & 1) * HA_TILE;
        const int k0 = i << 5;
#pragma unroll
        for (int ks = 0; ks < 2; ks++) {
            const int kb = ks * 16 + 2 * qt;
            unsigned af[4][4], bf[4][2];
            float sc0, sh0, sc1, sh1, sc8, sh8, sc9, sh9;
            if (FUSE_BN) {
                int g = k0 + kb;
                sc0 = scS[g];     sh0 = shS[g];
                sc1 = scS[g + 1]; sh1 = shS[g + 1];
                sc8 = scS[g + 8]; sh8 = shS[g + 8];
                sc9 = scS[g + 9]; sh9 = shS[g + 9];
            }
#pragma unroll
            for (int mt = 0; mt < 4; mt++) {
                int r = warpM * 64 + mt * 16 + group;
                const __half* p0 = As + r * HSTR + kb;
                const __half* p1 = As + (r + 8) * HSTR + kb;
                if (FUSE_BN) {
                    float2 v0 = __half22float2(*(const __half2*)p0);
                    float2 v1 = __half22float2(*(const __half2*)p1);
                    float2 v2 = __half22float2(*(const __half2*)(p0 + 8));
                    float2 v3 = __half22float2(*(const __half2*)(p1 + 8));
                    af[mt][0] = h2u(__floats2half2_rn(
                        fmaxf(fmaf(v0.x, sc0, sh0), 0.f), fmaxf(fmaf(v0.y, sc1, sh1), 0.f)));
                    af[mt][1] = h2u(__floats2half2_rn(
                        fmaxf(fmaf(v1.x, sc0, sh0), 0.f), fmaxf(fmaf(v1.y, sc1, sh1), 0.f)));
                    af[mt][2] = h2u(__floats2half2_rn(
                        fmaxf(fmaf(v2.x, sc8, sh8), 0.f), fmaxf(fmaf(v2.y, sc9, sh9), 0.f)));
                    af[mt][3] = h2u(__floats2half2_rn(
                        fmaxf(fmaf(v3.x, sc8, sh8), 0.f), fmaxf(fmaf(v3.y, sc9, sh9), 0.f)));
                } else {
                    af[mt][0] = *(const unsigned*)p0;
                    af[mt][1] = *(const unsigned*)p1;
                    af[mt][2] = *(const unsigned*)(p0 + 8);
                    af[mt][3] = *(const unsigned*)(p1 + 8);
                }
            }
#pragma unroll
            for (int nt = 0; nt < 4; nt++) {
                int cb = warpN * 32 + nt * 8 + group;
                const __half* q = Bs + cb * HSTR + kb;
                bf[nt][0] = *(const unsigned*)q;
                bf[nt][1] = *(const unsigned*)(q + 8);
            }
#pragma unroll
            for (int mt = 0; mt < 4; mt++)
#pragma unroll
                for (int nt = 0; nt < 4; nt++)
                    MMA_F16(acc[mt][nt], af[mt], bf[nt]);
        }
        __syncthreads();
    }

    // epilogue: store + BN stats (on stored values)
    float cs[4][2], cq[4][2];
#pragma unroll
    for (int nt = 0; nt < 4; nt++) { cs[nt][0] = cs[nt][1] = 0.f; cq[nt][0] = cq[nt][1] = 0.f; }
#pragma unroll
    for (int mt = 0; mt < 4; mt++) {
        int r0 = mBase + warpM * 64 + mt * 16 + group;
        int r1 = r0 + 8;
#pragma unroll
        for (int nt = 0; nt < 4; nt++) {
            int cc = nBase + warpN * 32 + nt * 8 + 2 * qt;
            float x0, x1;
            if (r0 < M) {
                st2(C, (size_t)r0 * NC + cc, acc[mt][nt][0], acc[mt][nt][1], x0, x1);
                cs[nt][0] += x0; cs[nt][1] += x1;
                cq[nt][0] += x0 * x0; cq[nt][1] += x1 * x1;
            }
            if (r1 < M) {
                st2(C, (size_t)r1 * NC + cc, acc[mt][nt][2], acc[mt][nt][3], x0, x1);
                cs[nt][0] += x0; cs[nt][1] += x1;
                cq[nt][0] += x0 * x0; cq[nt][1] += x1 * x1;
            }
        }
    }
    if (sumO) {
#pragma unroll
        for (int off = 4; off < 32; off <<= 1) {
#pragma unroll
            for (int nt = 0; nt < 4; nt++) {
#pragma unroll
                for (int p = 0; p < 2; p++) {
                    cs[nt][p] += __shfl_xor_sync(0xffffffffu, cs[nt][p], off);
                    cq[nt][p] += __shfl_xor_sync(0xffffffffu, cq[nt][p], off);
                }
            }
        }
        if (group == 0) {
#pragma unroll
            for (int nt = 0; nt < 4; nt++) {
                int cc = nBase + warpN * 32 + nt * 8 + 2 * qt;
                atomicAdd(sumO + cc,     cs[nt][0]);
                atomicAdd(sumO + cc + 1, cs[nt][1]);
                atomicAdd(sqO  + cc,     cq[nt][0]);
                atomicAdd(sqO  + cc + 1, cq[nt][1]);
            }
        }
    }
}

// ---------------- combine (half2 vectorized) ----------------
__global__ void k_combine() {
    int c = threadIdx.x & 63;
    int eo = threadIdx.x >> 6;
    float ls0 = 0.f, ls1 = 0.f, lq0 = 0.f, lq1 = 0.f;
    const __half2* a0 = (const __half2*)s_a0;
    const __half2* a1 = (const __half2*)s_a1;
    const __half2* ew = (const __half2*)s_ew2;
    __half2* pre = (__half2*)s_pre1;
    for (int e = blockIdx.x * 2 + eo; e < NE; e += gridDim.x * 2) {
        int u = s_u[e], v = s_v[e];
        float2 a0u = __half22float2(a0[(size_t)u * 64 + c]);
        float2 a0v = __half22float2(a0[(size_t)v * 64 + c]);
        float2 a1u = __half22float2(a1[(size_t)u * 64 + c]);
        float2 a1v = __half22float2(a1[(size_t)v * 64 + c]);
        float bx = a0u.x + a0v.x, by = a0u.y + a0v.y;
        size_t r0 = (size_t)(2 * e) * 64 + c, r1 = (size_t)(2 * e + 1) * 64 + c;
        float2 e0 = __half22float2(ew[r0]);
        float2 e1 = __half22float2(ew[r1]);
        __half2 h0 = __floats2half2_rn(bx + a1u.x + e0.x, by + a1u.y + e0.y);
        __half2 h1 = __floats2half2_rn(bx + a1v.x + e1.x, by + a1v.y + e1.y);
        pre[r0] = h0; pre[r1] = h1;
        float2 q0 = __half22float2(h0), q1 = __half22float2(h1);
        ls0 += q0.x + q1.x; ls1 += q0.y + q1.y;
        lq0 += q0.x * q0.x + q1.x * q1.x; lq1 += q0.y * q0.y + q1.y * q1.y;
    }
    atomicAdd(&s_sum[2 * c],     ls0);
    atomicAdd(&s_sum[2 * c + 1], ls1);
    atomicAdd(&s_sq[2 * c],      lq0);
    atomicAdd(&s_sq[2 * c + 1],  lq1);
}

// CSR gather: nin[n] = e11*nr[n] + sum_entries[(2+eps12)*h_r + h_sib]
__global__ void k_gather_nin(const float* __restrict__ nr,
                             const float* __restrict__ g, const float* __restrict__ b,
                             const float* __restrict__ eps12p,
                             const float* __restrict__ eps11p) {
    int n = blockIdx.x;
    int c = threadIdx.x;
    float mean = s_sum[c] * (1.0f / TE);
    float var  = s_sq[c]  * (1.0f / TE) - mean * mean;
    float sc = g[c] * rsqrtf(var + 1e-5f);
    float sh = b[c] - mean * sc;
    float cf = 2.0f + *eps12p;
    float e11 = 1.0f + *eps11p;
    int beg = s_rowptr[n], end = s_rowptr[n + 1];
    float acc = 0.f;
    for (int j = beg; j < end; j++) {
        int r = s_csr[j];
        int sIb = r ^ 1;
        float hr = fmaxf(__half2float(s_pre1[(size_t)r  * 128 + c]) * sc + sh, 0.f);
        float hs = fmaxf(__half2float(s_pre1[(size_t)sIb * 128 + c]) * sc + sh, 0.f);
        acc += cf * hr + hs;
    }
    s_nin[(size_t)n * 128 + c] = __float2half_rn(e11 * nr[(size_t)n * 128 + c] + acc);
}

__global__ void k_ein(const float* __restrict__ er, const float* __restrict__ nr,
                      const float* __restrict__ eps2p) {
    int c = threadIdx.x & 63;
    int eo = threadIdx.x >> 6;
    float e2 = 1.0f + *eps2p;
    float e2h = 0.5f * e2;
    const float2* er2 = (const float2*)er;
    const float2* nr2 = (const float2*)nr;
    __half2* ein = (__half2*)s_ein;
    for (int e = blockIdx.x * 2 + eo; e < NE; e += gridDim.x * 2) {
        int u = s_u[e], v = s_v[e];
        float2 a = er2[(size_t)(2 * e) * 64 + c];
        float2 bq = er2[(size_t)(2 * e + 1) * 64 + c];
        float2 p = nr2[(size_t)u * 64 + c];
        float2 q = nr2[(size_t)v * 64 + c];
        __half2 fh = __floats2half2_rn(e2h * (a.x + bq.x) + p.x + q.x,
                                       e2h * (a.y + bq.y) + p.y + q.y);
        size_t r0 = (size_t)(2 * e) * 128 + c, r1 = (size_t)(2 * e + 1) * 128 + c;
        ein[r0] = fh;
        ein[r1] = fh;
        ein[r0 + 64] = __floats2half2_rn(e2 * a.x + p.x,  e2 * a.y + p.y);
        ein[r1 + 64] = __floats2half2_rn(e2 * bq.x + q.x, e2 * bq.y + q.y);
    }
}

// dst(fp32) = relu(src(half)*scale + shift); half2 vectorized; cols = 128 (64 half2)
__global__ void k_bnapplyh(const __half2* __restrict__ src, float2* __restrict__ dst,
                           int rows,
                           const float* __restrict__ sum, const float* __restrict__ sq,
                           const float* __restrict__ g, const float* __restrict__ b,
                           float inv) {
    size_t n = (size_t)rows * 64;
    size_t stride = (size_t)gridDim.x * blockDim.x;
    for (size_t i = (size_t)blockIdx.x * blockDim.x + threadIdx.x; i < n; i += stride) {
        int c = (int)(i & 63) << 1;
        float2 v = __half22float2(src[i]);
        float m0 = sum[c] * inv, m1 = sum[c + 1] * inv;
        float v0 = sq[c] * inv - m0 * m0, v1 = sq[c + 1] * inv - m1 * m1;
        float s0 = g[c] * rsqrtf(v0 + 1e-5f), s1 = g[c + 1] * rsqrtf(v1 + 1e-5f);
        float o0 = fmaxf(v.x * s0 + (b[c] - m0 * s0), 0.f);
        float o1 = fmaxf(v.y * s1 + (b[c + 1] - m1 * s1), 0.f);
        dst[i] = make_float2(o0, o1);
    }
}

// ---------------- launch ----------------
extern "C" void kernel_launch(void* const* d_in, const int* in_sizes, int n_in,
                              void* d_out, int out_size) {
    const float* nr      = (const float*)d_in[0];
    const float* er      = (const float*)d_in[1];
    const void*  ei      = d_in[2];
    const float* lift_w1 = (const float*)d_in[3];
    const float* lift_g1 = (const float*)d_in[4];
    const float* lift_b1 = (const float*)d_in[5];
    const float* lift_w2 = (const float*)d_in[6];
    const float* lift_g2 = (const float*)d_in[7];
    const float* lift_b2 = (const float*)d_in[8];
    const float* lvl1_w  = (const float*)d_in[9];
    const float* lvl1_g  = (const float*)d_in[10];
    const float* lvl1_b  = (const float*)d_in[11];
    const float* lvl2_w1 = (const float*)d_in[12];
    const float* lvl2_g1 = (const float*)d_in[13];
    const float* lvl2_b1 = (const float*)d_in[14];
    const float* lvl2_w2 = (const float*)d_in[15];
    const float* lvl2_g2 = (const float*)d_in[16];
    const float* lvl2_b2 = (const float*)d_in[17];
    const float* eps11   = (const float*)d_in[18];
    const float* eps12   = (const float*)d_in[19];
    const float* eps2    = (const float*)d_in[20];

    float* out_node = (float*)d_out;
    float* out_edge = out_node + (size_t)NN * HH;

    __half *p_ew2, *p_a0, *p_a1, *p_nin, *p_np1, *p_np2, *p_ein, *p_ep1, *p_ep2;
    __half *p_wnp1, *p_wnp2, *p_wep1, *p_wep2, *p_wl1;
    float *p_sum, *p_sq;
    cudaGetSymbolAddress((void**)&p_ew2, s_ew2);
    cudaGetSymbolAddress((void**)&p_a0,  s_a0);
    cudaGetSymbolAddress((void**)&p_a1,  s_a1);
    cudaGetSymbolAddress((void**)&p_nin, s_nin);
    cudaGetSymbolAddress((void**)&p_np1, s_np1);
    cudaGetSymbolAddress((void**)&p_np2, s_np2);
    cudaGetSymbolAddress((void**)&p_ein, s_ein);
    cudaGetSymbolAddress((void**)&p_ep1, s_ep1);
    cudaGetSymbolAddress((void**)&p_ep2, s_ep2);
    cudaGetSymbolAddress((void**)&p_sum, s_sum);
    cudaGetSymbolAddress((void**)&p_sq,  s_sq);
    cudaGetSymbolAddress((void**)&p_wnp1, w_np1h);
    cudaGetSymbolAddress((void**)&p_wnp2, w_np2h);
    cudaGetSymbolAddress((void**)&p_wep1, w_ep1h);
    cudaGetSymbolAddress((void**)&p_wep2, w_ep2h);
    cudaGetSymbolAddress((void**)&p_wl1,  w_l1h);

    static cudaStream_t s_edge = nullptr, s_csrS = nullptr;
    static cudaEvent_t ev_root = nullptr, ev_dec = nullptr, ev_wp = nullptr,
                       ev_edge = nullptr, ev_csr = nullptr;
    static int smem_set = 0;
    if (!smem_set) {
        cudaFuncSetAttribute((const void*)k_mma_fh,
                             cudaFuncAttributeMaxDynamicSharedMemorySize, SMEM_BYTES_FH);
        cudaFuncSetAttribute((const void*)k_mma_h<__half, false, true>,
                             cudaFuncAttributeMaxDynamicSharedMemorySize, SMEM_BYTES_H);
        cudaFuncSetAttribute((const void*)k_mma_h<__half, true, false>,
                             cudaFuncAttributeMaxDynamicSharedMemorySize, SMEM_BYTES_H);
        cudaStreamCreateWithFlags(&s_edge, cudaStreamNonBlocking);
        cudaStreamCreateWithFlags(&s_csrS, cudaStreamNonBlocking);
        cudaEventCreateWithFlags(&ev_root, cudaEventDisableTiming);
        cudaEventCreateWithFlags(&ev_dec,  cudaEventDisableTiming);
        cudaEventCreateWithFlags(&ev_wp,   cudaEventDisableTiming);
        cudaEventCreateWithFlags(&ev_edge, cudaEventDisableTiming);
        cudaEventCreateWithFlags(&ev_csr,  cudaEventDisableTiming);
        smem_set = 1;
    }

    const int GN  = (NN + 127) / 128;  // 157
    const int GTE = TE / 128;          // 2500

    // -------- root fork: side streams must join capture via event-wait --------
    cudaEventRecord(ev_root, 0);
    cudaStreamWaitEvent(s_csrS, ev_root, 0);

    // stream 0: index decode          s_csrS: zero + weight prep (parallel)
    k_detect<<<1, 32>>>((const int*)ei);
    k_decode<<<(NE + 255) / 256, 256>>>(ei);
    cudaEventRecord(ev_dec, 0);

    k_zero<<<(NN + 255) / 256, 256, 0, s_csrS>>>();
    k_wprep<<<256, 256, 0, s_csrS>>>(lvl2_w1, lvl2_w2, lift_w1, lift_w2, lvl1_w);
    cudaEventRecord(ev_wp, s_csrS);

    // CSR build on s_csrS (needs decode)
    cudaStreamWaitEvent(s_csrS, ev_dec, 0);
    k_hist<<<(NE + 255) / 256, 256, 0, s_csrS>>>();
    k_scan<<<1, 1024, 0, s_csrS>>>();
    k_place<<<(NE + 255) / 256, 256, 0, s_csrS>>>();
    cudaEventRecord(ev_csr, s_csrS);

    // -------- edge chain (s_edge) --------
    cudaStreamWaitEvent(s_edge, ev_dec, 0);
    k_ein<<<2048, 128, 0, s_edge>>>(er, nr, eps2);
    cudaStreamWaitEvent(s_edge, ev_wp, 0);
    k_mma_h<__half, false, true><<<dim3(2, GTE), 256, SMEM_BYTES_H, s_edge>>>(
        p_ein, p_wep1, p_ep1, TE, 256, 256,
        p_sum + 768, p_sq + 768, nullptr, nullptr, nullptr, nullptr, 0.f);
    k_mma_h<__half, true, false><<<dim3(GTE, 1), 256, SMEM_BYTES_H, s_edge>>>(
        p_ep1, p_wep2, p_ep2, TE, 256, 128,
        p_sum + 1024, p_sq + 1024,
        p_sum + 768, p_sq + 768, lift_g1, lift_b1, 1.0f / TE);
    k_bnapplyh<<<4096, 256, 0, s_edge>>>((const __half2*)p_ep2, (float2*)out_edge, TE,
                              p_sum + 1024, p_sq + 1024, lift_g2, lift_b2, 1.0f / TE);
    cudaEventRecord(ev_edge, s_edge);

    // -------- node chain (stream 0) --------
    cudaStreamWaitEvent(0, ev_wp, 0);
    k_mma_fh<<<dim3(GTE, 1), 256, SMEM_BYTES_FH>>>(er, p_wl1 + 2 * 16384, p_ew2, TE, 128, 128);
    k_mma_fh<<<dim3(GN, 1),  256, SMEM_BYTES_FH>>>(nr, p_wl1,             p_a0,  NN, 128, 128);
    k_mma_fh<<<dim3(GN, 1),  256, SMEM_BYTES_FH>>>(nr, p_wl1 + 16384,     p_a1,  NN, 128, 128);

    k_combine<<<2048, 128>>>();                             // stats slot 0, pre1 half

    cudaStreamWaitEvent(0, ev_csr, 0);
    k_gather_nin<<<NN, 128>>>(nr, lvl1_g, lvl1_b, eps12, eps11);  // BN+aggregate+nin fused

    k_mma_h<__half, false, true><<<dim3(2, GN), 256, SMEM_BYTES_H>>>(
        p_nin, p_wnp1, p_np1, NN, 128, 256,
        p_sum + 256, p_sq + 256, nullptr, nullptr, nullptr, nullptr, 0.f);
    k_mma_h<__half, true, false><<<dim3(GN, 1), 256, SMEM_BYTES_H>>>(
        p_np1, p_wnp2, p_np2, NN, 256, 128,
        p_sum + 512, p_sq + 512,
        p_sum + 256, p_sq + 256, lvl2_g1, lvl2_b1, 1.0f / NN);
    k_bnapplyh<<<2048, 256>>>((const __half2*)p_np2, (float2*)out_node, NN,
                              p_sum + 512, p_sq + 512, lvl2_g2, lvl2_b2, 1.0f / NN);

    // -------- join --------
    cudaStreamWaitEvent(0, ev_edge, 0);
}

// round 15
// speedup vs baseline: 1.4954x; 1.0229x over previous
#include <cuda_runtime.h>
#include <cuda_fp16.h>
#include <cstring>

#define NN 20000      // nodes
#define NE 160000     // edges
#define TE 320000     // 2E edge-rows
#define HH 128

// ---------------- scratch (static __device__, no allocs) ----------------
__device__ __align__(128) __half s_a0  [(size_t)NN * 128];   // nr @ W0
__device__ __align__(128) __half s_a1  [(size_t)NN * 128];   // nr @ W1
__device__ __align__(128) __half s_pre1[(size_t)TE * 128];   // lvl1 pre-act
__device__ __align__(128) __half s_nin [(size_t)NN * 128];
__device__ __align__(128) __half s_np1 [(size_t)NN * 256];
__device__ __align__(128) __half s_np2 [(size_t)NN * 128];   // final pre-act (half)
__device__ __align__(128) __half s_ein [(size_t)TE * 256];
__device__ __align__(128) __half s_ep1 [(size_t)TE * 256];
__device__ __align__(128) __half s_ep2 [(size_t)TE * 128];   // final pre-act (half)
// fp16 weights, pre-transposed to n-major [N][K]
__device__ __align__(128) __half w_np1h[256 * 128];
__device__ __align__(128) __half w_np2h[128 * 256];
__device__ __align__(128) __half w_ep1h[256 * 256];
__device__ __align__(128) __half w_ep2h[128 * 256];
__device__ __align__(128) __half w_l1h [3 * 128 * 128];   // lvl1 W blocks 0,1,2 n-major
// CSR: node -> incident edge-rows
__device__ int s_deg[NN];
__device__ int s_rowptr[NN + 1];
__device__ int s_cursor[NN];
__device__ int s_csr[TE];
__device__ float s_sum[5 * 256];
__device__ float s_sq [5 * 256];
__device__ int   s_u[NE];
__device__ int   s_v[NE];
__device__ int   g_is64;

// ---------------- helpers ----------------
__device__ __forceinline__ unsigned h2u(__half2 h) {
    unsigned u;
    memcpy(&u, &h, 4);
    return u;
}

__global__ void k_zero() {
    int i0 = blockIdx.x * blockDim.x + threadIdx.x;
    if (i0 < NN) s_deg[i0] = 0;
    if (i0 < 5 * 256) { s_sum[i0] = 0.0f; s_sq[i0] = 0.0f; }
}

__global__ void k_detect(const int* __restrict__ ei32) {
    if (threadIdx.x == 0 && blockIdx.x == 0) {
        int nz = 0;
        for (int i = 0; i < 256; i++) nz |= ei32[2 * i + 1];
        g_is64 = (nz == 0) ? 1 : 0;
    }
}

__global__ void k_decode(const void* __restrict__ ei) {
    int e = blockIdx.x * blockDim.x + threadIdx.x;
    if (e >= NE) return;
    if (g_is64) {
        const long long* p = (const long long*)ei;
        s_u[e] = (int)p[e];
        s_v[e] = (int)p[NE + e];
    } else {
        const int* p = (const int*)ei;
        s_u[e] = p[e];
        s_v[e] = p[NE + e];
    }
}

// ---- CSR build ----
__global__ void k_hist() {
    int e = blockIdx.x * blockDim.x + threadIdx.x;
    if (e >= NE) return;
    atomicAdd(&s_deg[s_u[e]], 1);
    atomicAdd(&s_deg[s_v[e]], 1);
}

__global__ void k_scan() {   // single block, 1024 threads; 20 nodes/thread
    __shared__ int ts[1024];
    int t = threadIdx.x;
    int base = t * 20;
    int lv[20];
    int loc = 0;
#pragma unroll
    for (int i = 0; i < 20; i++) {
        int n = base + i;
        lv[i] = (n < NN) ? s_deg[n] : 0;
        loc += lv[i];
    }
    ts[t] = loc;
    __syncthreads();
    for (int off = 1; off < 1024; off <<= 1) {
        int v = (t >= off) ? ts[t - off] : 0;
        __syncthreads();
        ts[t] += v;
        __syncthreads();
    }
    int run = ts[t] - loc;   // exclusive prefix
#pragma unroll
    for (int i = 0; i < 20; i++) {
        int n = base + i;
        if (n < NN) {
            s_rowptr[n] = run;
            s_cursor[n] = run;
            run += lv[i];
        }
    }
    if (t == 1023) s_rowptr[NN] = ts[1023];
}

__global__ void k_place() {
    int e = blockIdx.x * blockDim.x + threadIdx.x;
    if (e >= NE) return;
    int p0 = atomicAdd(&s_cursor[s_u[e]], 1);
    s_csr[p0] = 2 * e;
    int p1 = atomicAdd(&s_cursor[s_v[e]], 1);
    s_csr[p1] = 2 * e + 1;
}

// convert + transpose weights to fp16 n-major
__global__ void k_wprep(const float* __restrict__ w_np1, const float* __restrict__ w_np2,
                        const float* __restrict__ w_ep1, const float* __restrict__ w_ep2,
                        const float* __restrict__ w_l1) {
    int i = blockIdx.x * blockDim.x + threadIdx.x;   // 65536 threads
    if (i < 256 * 128) {            // np1: [128][256] -> [256][128]
        int n = i >> 7, k = i & 127;
        w_np1h[i] = __float2half_rn(w_np1[k * 256 + n]);
    }
    if (i < 128 * 256) {            // np2: [256][128] -> [128][256]
        int n = i >> 8, k = i & 255;
        w_np2h[i] = __float2half_rn(w_np2[k * 128 + n]);
    }
    if (i < 256 * 256) {            // ep1: [256][256] -> transposed
        int n = i >> 8, k = i & 255;
        w_ep1h[i] = __float2half_rn(w_ep1[k * 256 + n]);
    }
    if (i < 128 * 256) {            // ep2: [256][128] -> [128][256]
        int n = i >> 8, k = i & 255;
        w_ep2h[i] = __float2half_rn(w_ep2[k * 128 + n]);
    }
    if (i < 3 * 128 * 128) {        // lvl1 blocks: [384][128] -> 3x [128][128] n-major
        int blk = i >> 14, rem = i & 16383;
        int n = rem >> 7, k = rem & 127;
        w_l1h[i] = __float2half_rn(w_l1[(blk * 128 + k) * 128 + n]);
    }
}

__device__ __forceinline__ void cpasync16(void* smem_ptr, const void* gptr, int src_bytes) {
    unsigned saddr = (unsigned)__cvta_generic_to_shared(smem_ptr);
    asm volatile("cp.async.cg.shared.global [%0], [%1], 16, %2;"
                 :: "r"(saddr), "l"(gptr), "r"(src_bytes));
}
__device__ __forceinline__ void cpasync_commit() {
    asm volatile("cp.async.commit_group;");
}
template <int N>
__device__ __forceinline__ void cpasync_wait() {
    asm volatile("cp.async.wait_group %0;" :: "n"(N));
}

#define MMA_F16(d, Af, Bf)                                                      \
    asm volatile(                                                               \
        "mma.sync.aligned.m16n8k16.row.col.f32.f16.f16.f32 "                    \
        "{%0,%1,%2,%3},{%4,%5,%6,%7},{%8,%9},{%0,%1,%2,%3};"                    \
        : "+f"(d[0]), "+f"(d[1]), "+f"(d[2]), "+f"(d[3])                        \
        : "r"(Af[0]), "r"(Af[1]), "r"(Af[2]), "r"(Af[3]),                       \
          "r"(Bf[0]), "r"(Bf[1]))

// typed stores (stats on stored/rounded values)
__device__ __forceinline__ void st2(float* C, size_t off, float c0, float c1,
                                    float& r0, float& r1) {
    *(float2*)(C + off) = make_float2(c0, c1);
    r0 = c0; r1 = c1;
}
__device__ __forceinline__ void st2(__half* C, size_t off, float c0, float c1,
                                    float& r0, float& r1) {
    __half2 h = __floats2half2_rn(c0, c1);
    *(__half2*)(C + off) = h;
    r0 = __low2float(h); r1 = __high2float(h);
}

#define HSTR 40
#define HA_TILE (128 * HSTR)

// ======== HMMA GEMM, fp32 A (cvt at smem->reg), fp16 n-major B, half C ========
#define AF_STRIDE 36
#define SMEM_BYTES_FH (2 * 128 * AF_STRIDE * 4 + 2 * HA_TILE * 2 + 1024)  // 58368

__global__ __launch_bounds__(256, 2) void k_mma_fh(
    const float* __restrict__ A, const __half* __restrict__ Bt,
    __half* __restrict__ C, int M, int K, int NC)
{
    extern __shared__ char dsmRaw[];
    float* AsB = (float*)dsmRaw;
    __half* BsB = (__half*)(dsmRaw + 2 * 128 * AF_STRIDE * 4);

    const int tid = threadIdx.x;
    const int lane = tid & 31, warp = tid >> 5;
    const int group = lane >> 2, qt = lane & 3;
    const int warpM = warp & 1, warpN = warp >> 1;
    const int mBase = blockIdx.x * 128, nBase = blockIdx.y * 128;
    const int nk = K >> 5;

    const int arow = tid >> 3, akq = (tid & 7) << 2;     // fp32: 8 thr/row
    const int brow = tid >> 2, bkq = (tid & 3) << 3;     // fp16: 4 thr/row

    auto issue = [&](int i, int b) {
        const int k0 = i << 5;
        float* As = AsB + b * 128 * AF_STRIDE;
        __half* Bs = BsB + b * HA_TILE;
#pragma unroll
        for (int it = 0; it < 4; it++) {
            int row = arow + it * 32;
            int gm = mBase + row;
            const float* src = A + (size_t)(gm < M ? gm : 0) * K + k0 + akq;
            cpasync16(As + row * AF_STRIDE + akq, src, gm < M ? 16 : 0);
        }
#pragma unroll
        for (int it = 0; it < 2; it++) {
            int row = brow + it * 64;
            const __half* src = Bt + (size_t)(nBase + row) * K + k0 + bkq;
            cpasync16(Bs + row * HSTR + bkq, src, 16);
        }
        cpasync_commit();
    };

    float acc[4][4][4];
#pragma unroll
    for (int mt = 0; mt < 4; mt++)
#pragma unroll
        for (int nt = 0; nt < 4; nt++)
#pragma unroll
            for (int i = 0; i < 4; i++) acc[mt][nt][i] = 0.0f;

    issue(0, 0);
    for (int i = 0; i < nk; i++) {
        if (i + 1 < nk) { issue(i + 1, (i + 1) & 1); cpasync_wait<1>(); }
        else            { cpasync_wait<0>(); }
        __syncthreads();
        const float* As = AsB + (i & 1) * 128 * AF_STRIDE;
        const __half* Bs = BsB + (i & 1) * HA_TILE;
#pragma unroll
        for (int ks = 0; ks < 2; ks++) {
            const int kb = ks * 16 + 2 * qt;
            unsigned af[4][4], bf[4][2];
#pragma unroll
            for (int mt = 0; mt < 4; mt++) {
                int r = warpM * 64 + mt * 16 + group;
                float2 v0 = *(const float2*)(As + r * AF_STRIDE + kb);
                float2 v1 = *(const float2*)(As + (r + 8) * AF_STRIDE + kb);
                float2 v2 = *(const float2*)(As + r * AF_STRIDE + kb + 8);
                float2 v3 = *(const float2*)(As + (r + 8) * AF_STRIDE + kb + 8);
                af[mt][0] = h2u(__floats2half2_rn(v0.x, v0.y));
                af[mt][1] = h2u(__floats2half2_rn(v1.x, v1.y));
                af[mt][2] = h2u(__floats2half2_rn(v2.x, v2.y));
                af[mt][3] = h2u(__floats2half2_rn(v3.x, v3.y));
            }
#pragma unroll
            for (int nt = 0; nt < 4; nt++) {
                int cb = warpN * 32 + nt * 8 + group;
                const __half* q = Bs + cb * HSTR + kb;
                bf[nt][0] = *(const unsigned*)q;
                bf[nt][1] = *(const unsigned*)(q + 8);
            }
#pragma unroll
            for (int mt = 0; mt < 4; mt++)
#pragma unroll
                for (int nt = 0; nt < 4; nt++)
                    MMA_F16(acc[mt][nt], af[mt], bf[nt]);
        }
        __syncthreads();
    }

#pragma unroll
    for (int mt = 0; mt < 4; mt++) {
        int r0 = mBase + warpM * 64 + mt * 16 + group;
        int r1 = r0 + 8;
#pragma unroll
        for (int nt = 0; nt < 4; nt++) {
            int cc = nBase + warpN * 32 + nt * 8 + 2 * qt;
            float x0, x1;
            if (r0 < M) st2(C, (size_t)r0 * NC + cc, acc[mt][nt][0], acc[mt][nt][1], x0, x1);
            if (r1 < M) st2(C, (size_t)r1 * NC + cc, acc[mt][nt][2], acc[mt][nt][3], x0, x1);
        }
    }
}

// ======== pre1 GEMM: er @ W2c, epilogue adds a0[u]+a0[v]+a1[atom], writes pre1 + stats slot0 ========
// M=TE (divisible by 128), K=128, NC=128, grid (TE/128, 1).
__global__ __launch_bounds__(256, 2) void k_mma_pre1(
    const float* __restrict__ A, const __half* __restrict__ Bt,
    __half* __restrict__ C, float* __restrict__ sumO, float* __restrict__ sqO)
{
    extern __shared__ char dsmRaw[];
    float* AsB = (float*)dsmRaw;
    __half* BsB = (__half*)(dsmRaw + 2 * 128 * AF_STRIDE * 4);

    const int tid = threadIdx.x;
    const int lane = tid & 31, warp = tid >> 5;
    const int group = lane >> 2, qt = lane & 3;
    const int warpM = warp & 1, warpN = warp >> 1;
    const int mBase = blockIdx.x * 128;
    const int K = 128, NC = 128, nk = 4;

    const int arow = tid >> 3, akq = (tid & 7) << 2;
    const int brow = tid >> 2, bkq = (tid & 3) << 3;

    auto issue = [&](int i, int b) {
        const int k0 = i << 5;
        float* As = AsB + b * 128 * AF_STRIDE;
        __half* Bs = BsB + b * HA_TILE;
#pragma unroll
        for (int it = 0; it < 4; it++) {
            int row = arow + it * 32;
            const float* src = A + (size_t)(mBase + row) * K + k0 + akq;
            cpasync16(As + row * AF_STRIDE + akq, src, 16);
        }
#pragma unroll
        for (int it = 0; it < 2; it++) {
            int row = brow + it * 64;
            const __half* src = Bt + (size_t)row * K + k0 + bkq;
            cpasync16(Bs + row * HSTR + bkq, src, 16);
        }
        cpasync_commit();
    };

    float acc[4][4][4];
#pragma unroll
    for (int mt = 0; mt < 4; mt++)
#pragma unroll
        for (int nt = 0; nt < 4; nt++)
#pragma unroll
            for (int i = 0; i < 4; i++) acc[mt][nt][i] = 0.0f;

    issue(0, 0);
    for (int i = 0; i < nk; i++) {
        if (i + 1 < nk) { issue(i + 1, (i + 1) & 1); cpasync_wait<1>(); }
        else            { cpasync_wait<0>(); }
        __syncthreads();
        const float* As = AsB + (i & 1) * 128 * AF_STRIDE;
        const __half* Bs = BsB + (i & 1) * HA_TILE;
#pragma unroll
        for (int ks = 0; ks < 2; ks++) {
            const int kb = ks * 16 + 2 * qt;
            unsigned af[4][4], bf[4][2];
#pragma unroll
            for (int mt = 0; mt < 4; mt++) {
                int r = warpM * 64 + mt * 16 + group;
                float2 v0 = *(const float2*)(As + r * AF_STRIDE + kb);
                float2 v1 = *(const float2*)(As + (r + 8) * AF_STRIDE + kb);
                float2 v2 = *(const float2*)(As + r * AF_STRIDE + kb + 8);
                float2 v3 = *(const float2*)(As + (r + 8) * AF_STRIDE + kb + 8);
                af[mt][0] = h2u(__floats2half2_rn(v0.x, v0.y));
                af[mt][1] = h2u(__floats2half2_rn(v1.x, v1.y));
                af[mt][2] = h2u(__floats2half2_rn(v2.x, v2.y));
                af[mt][3] = h2u(__floats2half2_rn(v3.x, v3.y));
            }
#pragma unroll
            for (int nt = 0; nt < 4; nt++) {
                int cb = warpN * 32 + nt * 8 + group;
                const __half* q = Bs + cb * HSTR + kb;
                bf[nt][0] = *(const unsigned*)q;
                bf[nt][1] = *(const unsigned*)(q + 8);
            }
#pragma unroll
            for (int mt = 0; mt < 4; mt++)
#pragma unroll
                for (int nt = 0; nt < 4; nt++)
                    MMA_F16(acc[mt][nt], af[mt], bf[nt]);
        }
        __syncthreads();
    }

    // epilogue: add gathered node terms (a0/a1 fp16, L2-resident), store half, stats
    float cs[4][2], cq[4][2];
#pragma unroll
    for (int nt = 0; nt < 4; nt++) { cs[nt][0] = cs[nt][1] = 0.f; cq[nt][0] = cq[nt][1] = 0.f; }
#pragma unroll
    for (int mt = 0; mt < 4; mt++) {
        int r0 = mBase + warpM * 64 + mt * 16 + group;
        int r1 = r0 + 8;
        int e0 = r0 >> 1, e1 = r1 >> 1;
        int u0 = s_u[e0], v0 = s_v[e0];
        int u1 = s_u[e1], v1 = s_v[e1];
        const __half* b0u = s_a0 + (size_t)u0 * 128;
        const __half* b0v = s_a0 + (size_t)v0 * 128;
        const __half* b0x = s_a1 + (size_t)((r0 & 1) ? v0 : u0) * 128;
        const __half* b1u = s_a0 + (size_t)u1 * 128;
        const __half* b1v = s_a0 + (size_t)v1 * 128;
        const __half* b1x = s_a1 + (size_t)((r1 & 1) ? v1 : u1) * 128;
#pragma unroll
        for (int nt = 0; nt < 4; nt++) {
            int cc = warpN * 32 + nt * 8 + 2 * qt;
            float2 ga = __half22float2(*(const __half2*)(b0u + cc));
            float2 gb = __half22float2(*(const __half2*)(b0v + cc));
            float2 gc = __half22float2(*(const __half2*)(b0x + cc));
            float x0, x1;
            st2(C, (size_t)r0 * NC + cc,
                acc[mt][nt][0] + ga.x + gb.x + gc.x,
                acc[mt][nt][1] + ga.y + gb.y + gc.y, x0, x1);
            cs[nt][0] += x0; cs[nt][1] += x1;
            cq[nt][0] += x0 * x0; cq[nt][1] += x1 * x1;

            float2 ha = __half22float2(*(const __half2*)(b1u + cc));
            float2 hb = __half22float2(*(const __half2*)(b1v + cc));
            float2 hc = __half22float2(*(const __half2*)(b1x + cc));
            st2(C, (size_t)r1 * NC + cc,
                acc[mt][nt][2] + ha.x + hb.x + hc.x,
                acc[mt][nt][3] + ha.y + hb.y + hc.y, x0, x1);
            cs[nt][0] += x0; cs[nt][1] += x1;
            cq[nt][0] += x0 * x0; cq[nt][1] += x1 * x1;
        }
    }
#pragma unroll
    for (int off = 4; off < 32; off <<= 1) {
#pragma unroll
        for (int nt = 0; nt < 4; nt++) {
#pragma unroll
            for (int p = 0; p < 2; p++) {
                cs[nt][p] += __shfl_xor_sync(0xffffffffu, cs[nt][p], off);
                cq[nt][p] += __shfl_xor_sync(0xffffffffu, cq[nt][p], off);
            }
        }
    }
    if (group == 0) {
#pragma unroll
        for (int nt = 0; nt < 4; nt++) {
            int cc = warpN * 32 + nt * 8 + 2 * qt;
            atomicAdd(sumO + cc,     cs[nt][0]);
            atomicAdd(sumO + cc + 1, cs[nt][1]);
            atomicAdd(sqO  + cc,     cq[nt][0]);
            atomicAdd(sqO  + cc + 1, cq[nt][1]);
        }
    }
}

// ================= FP16 HMMA GEMM (half A [M][K], half B n-major [NC][K]) ==========
#define SMEM_BYTES_H (4 * HA_TILE * 2 + 2048)   // 2 A-bufs + 2 B-bufs + BN = 43008

template <typename TC, bool FUSE_BN, bool SWAP>
__global__ __launch_bounds__(256, 2) void k_mma_h(
    const __half* __restrict__ A, const __half* __restrict__ Bt,
    TC* __restrict__ C, int M, int K, int NC,
    float* __restrict__ sumO, float* __restrict__ sqO,
    const float* __restrict__ aSum, const float* __restrict__ aSq,
    const float* __restrict__ aG, const float* __restrict__ aBt, float aInv)
{
    extern __shared__ char dsmRaw[];
    __half* AsB = (__half*)dsmRaw;
    __half* BsB = (__half*)(dsmRaw + 2 * HA_TILE * 2);
    float* scS = (float*)(dsmRaw + 4 * HA_TILE * 2);
    float* shS = scS + 256;

    const int tid = threadIdx.x;
    const int lane = tid & 31, warp = tid >> 5;
    const int group = lane >> 2, qt = lane & 3;
    const int warpM = warp & 1, warpN = warp >> 1;
    const int mBase = (SWAP ? blockIdx.y : blockIdx.x) * 128;
    const int nBase = (SWAP ? blockIdx.x : blockIdx.y) * 128;
    const int nk = K >> 5;

    if (FUSE_BN) {
        if (tid < K) {
            float mean = aSum[tid] * aInv;
            float var  = aSq[tid] * aInv - mean * mean;
            float s = aG[tid] * rsqrtf(var + 1e-5f);
            scS[tid] = s; shS[tid] = aBt[tid] - mean * s;
        }
        __syncthreads();
    }

    const int arow = tid >> 2, akq = (tid & 3) << 3;  // halfs: TPR=4, RPI=64

    auto issue = [&](int i, int b) {
        const int k0 = i << 5;
        __half* As = AsB + b * HA_TILE;
        __half* Bs = BsB + b * HA_TILE;
#pragma unroll
        for (int it = 0; it < 2; it++) {
            int row = arow + it * 64;
            int gm = mBase + row;
            const __half* src = A + (size_t)(gm < M ? gm : 0) * K + k0 + akq;
            cpasync16(As + row * HSTR + akq, src, gm < M ? 16 : 0);
        }
#pragma unroll
        for (int it = 0; it < 2; it++) {
            int row = arow + it * 64;
            const __half* src = Bt + (size_t)(nBase + row) * K + k0 + akq;
            cpasync16(Bs + row * HSTR + akq, src, 16);
        }
        cpasync_commit();
    };

    float acc[4][4][4];
#pragma unroll
    for (int mt = 0; mt < 4; mt++)
#pragma unroll
        for (int nt = 0; nt < 4; nt++)
#pragma unroll
            for (int i = 0; i < 4; i++) acc[mt][nt][i] = 0.0f;

    issue(0, 0);
    for (int i = 0; i < nk; i++) {
        if (i + 1 < nk) { issue(i + 1, (i + 1) & 1); cpasync_wait<1>(); }
        else            { cpasync_wait<0>(); }
        __syncthreads();
        const __half* As = AsB + (i & 1) * HA_TILE;
        const __half* Bs = BsB + (i & 1) * HA_TILE;
        const int k0 = i << 5;
#pragma unroll
        for (int ks = 0; ks < 2; ks++) {
            const int kb = ks * 16 + 2 * qt;
            unsigned af[4][4], bf[4][2];
            float sc0, sh0, sc1, sh1, sc8, sh8, sc9, sh9;
            if (FUSE_BN) {
                int g = k0 + kb;
                sc0 = scS[g];     sh0 = shS[g];
                sc1 = scS[g + 1]; sh1 = shS[g + 1];
                sc8 = scS[g + 8]; sh8 = shS[g + 8];
                sc9 = scS[g + 9]; sh9 = shS[g + 9];
            }
#pragma unroll
            for (int mt = 0; mt < 4; mt++) {
                int r = warpM * 64 + mt * 16 + group;
                const __half* p0 = As + r * HSTR + kb;
                const __half* p1 = As + (r + 8) * HSTR + kb;
                if (FUSE_BN) {
                    float2 v0 = __half22float2(*(const __half2*)p0);
                    float2 v1 = __half22float2(*(const __half2*)p1);
                    float2 v2 = __half22float2(*(const __half2*)(p0 + 8));
                    float2 v3 = __half22float2(*(const __half2*)(p1 + 8));
                    af[mt][0] = h2u(__floats2half2_rn(
                        fmaxf(fmaf(v0.x, sc0, sh0), 0.f), fmaxf(fmaf(v0.y, sc1, sh1), 0.f)));
                    af[mt][1] = h2u(__floats2half2_rn(
                        fmaxf(fmaf(v1.x, sc0, sh0), 0.f), fmaxf(fmaf(v1.y, sc1, sh1), 0.f)));
                    af[mt][2] = h2u(__floats2half2_rn(
                        fmaxf(fmaf(v2.x, sc8, sh8), 0.f), fmaxf(fmaf(v2.y, sc9, sh9), 0.f)));
                    af[mt][3] = h2u(__floats2half2_rn(
                        fmaxf(fmaf(v3.x, sc8, sh8), 0.f), fmaxf(fmaf(v3.y, sc9, sh9), 0.f)));
                } else {
                    af[mt][0] = *(const unsigned*)p0;
                    af[mt][1] = *(const unsigned*)p1;
                    af[mt][2] = *(const unsigned*)(p0 + 8);
                    af[mt][3] = *(const unsigned*)(p1 + 8);
                }
            }
#pragma unroll
            for (int nt = 0; nt < 4; nt++) {
                int cb = warpN * 32 + nt * 8 + group;
                const __half* q = Bs + cb * HSTR + kb;
                bf[nt][0] = *(const unsigned*)q;
                bf[nt][1] = *(const unsigned*)(q + 8);
            }
#pragma unroll
            for (int mt = 0; mt < 4; mt++)
#pragma unroll
                for (int nt = 0; nt < 4; nt++)
                    MMA_F16(acc[mt][nt], af[mt], bf[nt]);
        }
        __syncthreads();
    }

    // epilogue: store + BN stats (on stored values)
    float cs[4][2], cq[4][2];
#pragma unroll
    for (int nt = 0; nt < 4; nt++) { cs[nt][0] = cs[nt][1] = 0.f; cq[nt][0] = cq[nt][1] = 0.f; }
#pragma unroll
    for (int mt = 0; mt < 4; mt++) {
        int r0 = mBase + warpM * 64 + mt * 16 + group;
        int r1 = r0 + 8;
#pragma unroll
        for (int nt = 0; nt < 4; nt++) {
            int cc = nBase + warpN * 32 + nt * 8 + 2 * qt;
            float x0, x1;
            if (r0 < M) {
                st2(C, (size_t)r0 * NC + cc, acc[mt][nt][0], acc[mt][nt][1], x0, x1);
                cs[nt][0] += x0; cs[nt][1] += x1;
                cq[nt][0] += x0 * x0; cq[nt][1] += x1 * x1;
            }
            if (r1 < M) {
                st2(C, (size_t)r1 * NC + cc, acc[mt][nt][2], acc[mt][nt][3], x0, x1);
                cs[nt][0] += x0; cs[nt][1] += x1;
                cq[nt][0] += x0 * x0; cq[nt][1] += x1 * x1;
            }
        }
    }
    if (sumO) {
#pragma unroll
        for (int off = 4; off < 32; off <<= 1) {
#pragma unroll
            for (int nt = 0; nt < 4; nt++) {
#pragma unroll
                for (int p = 0; p < 2; p++) {
                    cs[nt][p] += __shfl_xor_sync(0xffffffffu, cs[nt][p], off);
                    cq[nt][p] += __shfl_xor_sync(0xffffffffu, cq[nt][p], off);
                }
            }
        }
        if (group == 0) {
#pragma unroll
            for (int nt = 0; nt < 4; nt++) {
                int cc = nBase + warpN * 32 + nt * 8 + 2 * qt;
                atomicAdd(sumO + cc,     cs[nt][0]);
                atomicAdd(sumO + cc + 1, cs[nt][1]);
                atomicAdd(sqO  + cc,     cq[nt][0]);
                atomicAdd(sqO  + cc + 1, cq[nt][1]);
            }
        }
    }
}

// CSR gather: nin[n] = e11*nr[n] + sum_entries[(2+eps12)*h_r + h_sib]
__global__ void k_gather_nin(const float* __restrict__ nr,
                             const float* __restrict__ g, const float* __restrict__ b,
                             const float* __restrict__ eps12p,
                             const float* __restrict__ eps11p) {
    int n = blockIdx.x;
    int c = threadIdx.x;
    float mean = s_sum[c] * (1.0f / TE);
    float var  = s_sq[c]  * (1.0f / TE) - mean * mean;
    float sc = g[c] * rsqrtf(var + 1e-5f);
    float sh = b[c] - mean * sc;
    float cf = 2.0f + *eps12p;
    float e11 = 1.0f + *eps11p;
    int beg = s_rowptr[n], end = s_rowptr[n + 1];
    float acc = 0.f;
    for (int j = beg; j < end; j++) {
        int r = s_csr[j];
        int sIb = r ^ 1;
        float hr = fmaxf(__half2float(s_pre1[(size_t)r  * 128 + c]) * sc + sh, 0.f);
        float hs = fmaxf(__half2float(s_pre1[(size_t)sIb * 128 + c]) * sc + sh, 0.f);
        acc += cf * hr + hs;
    }
    s_nin[(size_t)n * 128 + c] = __float2half_rn(e11 * nr[(size_t)n * 128 + c] + acc);
}

__global__ void k_ein(const float* __restrict__ er, const float* __restrict__ nr,
                      const float* __restrict__ eps2p) {
    int c = threadIdx.x & 63;
    int eo = threadIdx.x >> 6;
    float e2 = 1.0f + *eps2p;
    float e2h = 0.5f * e2;
    const float2* er2 = (const float2*)er;
    const float2* nr2 = (const float2*)nr;
    __half2* ein = (__half2*)s_ein;
    for (int e = blockIdx.x * 2 + eo; e < NE; e += gridDim.x * 2) {
        int u = s_u[e], v = s_v[e];
        float2 a = er2[(size_t)(2 * e) * 64 + c];
        float2 bq = er2[(size_t)(2 * e + 1) * 64 + c];
        float2 p = nr2[(size_t)u * 64 + c];
        float2 q = nr2[(size_t)v * 64 + c];
        __half2 fh = __floats2half2_rn(e2h * (a.x + bq.x) + p.x + q.x,
                                       e2h * (a.y + bq.y) + p.y + q.y);
        size_t r0 = (size_t)(2 * e) * 128 + c, r1 = (size_t)(2 * e + 1) * 128 + c;
        ein[r0] = fh;
        ein[r1] = fh;
        ein[r0 + 64] = __floats2half2_rn(e2 * a.x + p.x,  e2 * a.y + p.y);
        ein[r1 + 64] = __floats2half2_rn(e2 * bq.x + q.x, e2 * bq.y + q.y);
    }
}

// dst(fp32) = relu(src(half)*scale + shift); half2 vectorized; cols = 128 (64 half2)
__global__ void k_bnapplyh(const __half2* __restrict__ src, float2* __restrict__ dst,
                           int rows,
                           const float* __restrict__ sum, const float* __restrict__ sq,
                           const float* __restrict__ g, const float* __restrict__ b,
                           float inv) {
    size_t n = (size_t)rows * 64;
    size_t stride = (size_t)gridDim.x * blockDim.x;
    for (size_t i = (size_t)blockIdx.x * blockDim.x + threadIdx.x; i < n; i += stride) {
        int c = (int)(i & 63) << 1;
        float2 v = __half22float2(src[i]);
        float m0 = sum[c] * inv, m1 = sum[c + 1] * inv;
        float v0 = sq[c] * inv - m0 * m0, v1 = sq[c + 1] * inv - m1 * m1;
        float s0 = g[c] * rsqrtf(v0 + 1e-5f), s1 = g[c + 1] * rsqrtf(v1 + 1e-5f);
        float o0 = fmaxf(v.x * s0 + (b[c] - m0 * s0), 0.f);
        float o1 = fmaxf(v.y * s1 + (b[c + 1] - m1 * s1), 0.f);
        dst[i] = make_float2(o0, o1);
    }
}

// ---------------- launch ----------------
extern "C" void kernel_launch(void* const* d_in, const int* in_sizes, int n_in,
                              void* d_out, int out_size) {
    const float* nr      = (const float*)d_in[0];
    const float* er      = (const float*)d_in[1];
    const void*  ei      = d_in[2];
    const float* lift_w1 = (const float*)d_in[3];
    const float* lift_g1 = (const float*)d_in[4];
    const float* lift_b1 = (const float*)d_in[5];
    const float* lift_w2 = (const float*)d_in[6];
    const float* lift_g2 = (const float*)d_in[7];
    const float* lift_b2 = (const float*)d_in[8];
    const float* lvl1_w  = (const float*)d_in[9];
    const float* lvl1_g  = (const float*)d_in[10];
    const float* lvl1_b  = (const float*)d_in[11];
    const float* lvl2_w1 = (const float*)d_in[12];
    const float* lvl2_g1 = (const float*)d_in[13];
    const float* lvl2_b1 = (const float*)d_in[14];
    const float* lvl2_w2 = (const float*)d_in[15];
    const float* lvl2_g2 = (const float*)d_in[16];
    const float* lvl2_b2 = (const float*)d_in[17];
    const float* eps11   = (const float*)d_in[18];
    const float* eps12   = (const float*)d_in[19];
    const float* eps2    = (const float*)d_in[20];

    float* out_node = (float*)d_out;
    float* out_edge = out_node + (size_t)NN * HH;

    __half *p_a0, *p_a1, *p_nin, *p_np1, *p_np2, *p_ein, *p_ep1, *p_ep2, *p_pre1;
    __half *p_wnp1, *p_wnp2, *p_wep1, *p_wep2, *p_wl1;
    float *p_sum, *p_sq;
    cudaGetSymbolAddress((void**)&p_a0,  s_a0);
    cudaGetSymbolAddress((void**)&p_a1,  s_a1);
    cudaGetSymbolAddress((void**)&p_pre1, s_pre1);
    cudaGetSymbolAddress((void**)&p_nin, s_nin);
    cudaGetSymbolAddress((void**)&p_np1, s_np1);
    cudaGetSymbolAddress((void**)&p_np2, s_np2);
    cudaGetSymbolAddress((void**)&p_ein, s_ein);
    cudaGetSymbolAddress((void**)&p_ep1, s_ep1);
    cudaGetSymbolAddress((void**)&p_ep2, s_ep2);
    cudaGetSymbolAddress((void**)&p_sum, s_sum);
    cudaGetSymbolAddress((void**)&p_sq,  s_sq);
    cudaGetSymbolAddress((void**)&p_wnp1, w_np1h);
    cudaGetSymbolAddress((void**)&p_wnp2, w_np2h);
    cudaGetSymbolAddress((void**)&p_wep1, w_ep1h);
    cudaGetSymbolAddress((void**)&p_wep2, w_ep2h);
    cudaGetSymbolAddress((void**)&p_wl1,  w_l1h);

    static cudaStream_t s_edge = nullptr, s_csrS = nullptr;
    static cudaEvent_t ev_root = nullptr, ev_dec = nullptr, ev_wp = nullptr,
                       ev_edge = nullptr, ev_csr = nullptr;
    static int smem_set = 0;
    if (!smem_set) {
        cudaFuncSetAttribute((const void*)k_mma_fh,
                             cudaFuncAttributeMaxDynamicSharedMemorySize, SMEM_BYTES_FH);
        cudaFuncSetAttribute((const void*)k_mma_pre1,
                             cudaFuncAttributeMaxDynamicSharedMemorySize, SMEM_BYTES_FH);
        cudaFuncSetAttribute((const void*)k_mma_h<__half, false, true>,
                             cudaFuncAttributeMaxDynamicSharedMemorySize, SMEM_BYTES_H);
        cudaFuncSetAttribute((const void*)k_mma_h<__half, true, false>,
                             cudaFuncAttributeMaxDynamicSharedMemorySize, SMEM_BYTES_H);
        cudaStreamCreateWithFlags(&s_edge, cudaStreamNonBlocking);
        cudaStreamCreateWithFlags(&s_csrS, cudaStreamNonBlocking);
        cudaEventCreateWithFlags(&ev_root, cudaEventDisableTiming);
        cudaEventCreateWithFlags(&ev_dec,  cudaEventDisableTiming);
        cudaEventCreateWithFlags(&ev_wp,   cudaEventDisableTiming);
        cudaEventCreateWithFlags(&ev_edge, cudaEventDisableTiming);
        cudaEventCreateWithFlags(&ev_csr,  cudaEventDisableTiming);
        smem_set = 1;
    }

    const int GN  = (NN + 127) / 128;  // 157
    const int GTE = TE / 128;          // 2500

    // -------- root fork: side streams must join capture via event-wait --------
    cudaEventRecord(ev_root, 0);
    cudaStreamWaitEvent(s_csrS, ev_root, 0);

    // stream 0: index decode          s_csrS: zero + weight prep (parallel)
    k_detect<<<1, 32>>>((const int*)ei);
    k_decode<<<(NE + 255) / 256, 256>>>(ei);
    cudaEventRecord(ev_dec, 0);

    k_zero<<<(NN + 255) / 256, 256, 0, s_csrS>>>();
    k_wprep<<<256, 256, 0, s_csrS>>>(lvl2_w1, lvl2_w2, lift_w1, lift_w2, lvl1_w);
    cudaEventRecord(ev_wp, s_csrS);

    // CSR build on s_csrS (needs decode)
    cudaStreamWaitEvent(s_csrS, ev_dec, 0);
    k_hist<<<(NE + 255) / 256, 256, 0, s_csrS>>>();
    k_scan<<<1, 1024, 0, s_csrS>>>();
    k_place<<<(NE + 255) / 256, 256, 0, s_csrS>>>();
    cudaEventRecord(ev_csr, s_csrS);

    // -------- edge chain (s_edge) --------
    cudaStreamWaitEvent(s_edge, ev_dec, 0);
    k_ein<<<2048, 128, 0, s_edge>>>(er, nr, eps2);
    cudaStreamWaitEvent(s_edge, ev_wp, 0);
    k_mma_h<__half, false, true><<<dim3(2, GTE), 256, SMEM_BYTES_H, s_edge>>>(
        p_ein, p_wep1, p_ep1, TE, 256, 256,
        p_sum + 768, p_sq + 768, nullptr, nullptr, nullptr, nullptr, 0.f);
    k_mma_h<__half, true, false><<<dim3(GTE, 1), 256, SMEM_BYTES_H, s_edge>>>(
        p_ep1, p_wep2, p_ep2, TE, 256, 128,
        p_sum + 1024, p_sq + 1024,
        p_sum + 768, p_sq + 768, lift_g1, lift_b1, 1.0f / TE);
    k_bnapplyh<<<4096, 256, 0, s_edge>>>((const __half2*)p_ep2, (float2*)out_edge, TE,
                              p_sum + 1024, p_sq + 1024, lift_g2, lift_b2, 1.0f / TE);
    cudaEventRecord(ev_edge, s_edge);

    // -------- node chain (stream 0) --------
    cudaStreamWaitEvent(0, ev_wp, 0);
    k_mma_fh<<<dim3(GN, 1), 256, SMEM_BYTES_FH>>>(nr, p_wl1,         p_a0, NN, 128, 128);
    k_mma_fh<<<dim3(GN, 1), 256, SMEM_BYTES_FH>>>(nr, p_wl1 + 16384, p_a1, NN, 128, 128);
    // pre1 = er@W2c + a0[u]+a0[v]+a1[atom], fused epilogue; stats slot 0
    k_mma_pre1<<<dim3(GTE, 1), 256, SMEM_BYTES_FH>>>(er, p_wl1 + 2 * 16384, p_pre1,
                                                     p_sum, p_sq);

    cudaStreamWaitEvent(0, ev_csr, 0);
    k_gather_nin<<<NN, 128>>>(nr, lvl1_g, lvl1_b, eps12, eps11);  // BN+aggregate+nin fused

    k_mma_h<__half, false, true><<<dim3(2, GN), 256, SMEM_BYTES_H>>>(
        p_nin, p_wnp1, p_np1, NN, 128, 256,
        p_sum + 256, p_sq + 256, nullptr, nullptr, nullptr, nullptr, 0.f);
    k_mma_h<__half, true, false><<<dim3(GN, 1), 256, SMEM_BYTES_H>>>(
        p_np1, p_wnp2, p_np2, NN, 256, 128,
        p_sum + 512, p_sq + 512,
        p_sum + 256, p_sq + 256, lvl2_g1, lvl2_b1, 1.0f / NN);
    k_bnapplyh<<<2048, 256>>>((const __half2*)p_np2, (float2*)out_node, NN,
                              p_sum + 512, p_sq + 512, lvl2_g2, lvl2_b2, 1.0f / NN);

    // -------- join --------
    cudaStreamWaitEvent(0, ev_edge, 0);
}